// round 4
// baseline (speedup 1.0000x reference)
#include <cuda_runtime.h>
#include <math.h>

// ---------------- problem constants ----------------
#define N_EMBD   2048
#define N_HEAD   16
#define HEAD_DIM 128
#define N_INNER  8192
#define SEQ      2048
#define BATCH    2
#define ROWS     (BATCH*SEQ)     /* 4096 */
#define QKV_W    (3*N_EMBD)      /* 6144 */

// ---------------- scratch (device globals; no allocs allowed) ----------------
__device__ float g_ln   [(size_t)ROWS * N_EMBD];
__device__ float g_qkv  [(size_t)ROWS * QKV_W];
__device__ float g_attn [(size_t)ROWS * N_EMBD];
__device__ float g_hid  [(size_t)ROWS * N_EMBD];
__device__ float g_fc   [(size_t)ROWS * N_INNER];
__device__ float g_sA   [N_EMBD];
__device__ float g_sM   [N_INNER];

// ======================= LayerNorm: one block per row =======================
__global__ __launch_bounds__(256) void ln_kernel(const float* __restrict__ x,
                                                 const float* __restrict__ g,
                                                 const float* __restrict__ b,
                                                 float* __restrict__ y) {
    __shared__ float red[8];
    __shared__ float s_mean, s_rstd;
    const int row = blockIdx.x, tid = threadIdx.x;
    const float* xr = x + (size_t)row * N_EMBD;
    float v[8];
    float s = 0.f;
#pragma unroll
    for (int k = 0; k < 8; k++) { v[k] = xr[tid + k * 256]; s += v[k]; }
#pragma unroll
    for (int o = 16; o > 0; o >>= 1) s += __shfl_xor_sync(0xffffffffu, s, o);
    if ((tid & 31) == 0) red[tid >> 5] = s;
    __syncthreads();
    if (tid == 0) {
        float t = 0.f;
#pragma unroll
        for (int i = 0; i < 8; i++) t += red[i];
        s_mean = t * (1.f / N_EMBD);
    }
    __syncthreads();
    const float mu = s_mean;
    float vs = 0.f;
#pragma unroll
    for (int k = 0; k < 8; k++) { float d = v[k] - mu; vs += d * d; }
#pragma unroll
    for (int o = 16; o > 0; o >>= 1) vs += __shfl_xor_sync(0xffffffffu, vs, o);
    if ((tid & 31) == 0) red[tid >> 5] = vs;
    __syncthreads();
    if (tid == 0) {
        float t = 0.f;
#pragma unroll
        for (int i = 0; i < 8; i++) t += red[i];
        s_rstd = rsqrtf(t * (1.f / N_EMBD) + 1e-5f);
    }
    __syncthreads();
    const float rstd = s_rstd;
    float* yr = y + (size_t)row * N_EMBD;
#pragma unroll
    for (int k = 0; k < 8; k++) {
        const int c = tid + k * 256;
        yr[c] = (v[k] - mu) * rstd * g[c] + b[c];
    }
}

// ========== weight-norm column scales: s[j] = g[j] / ||v[:,j]||_2 ==========
// v is [rows, cols] row-major; norm over axis 0. Block handles 32 columns.
__global__ __launch_bounds__(256) void colnorm_kernel(const float* __restrict__ v,
                                                      const float* __restrict__ g,
                                                      float* __restrict__ scale,
                                                      int rows, int cols) {
    __shared__ float red[8][32];
    const int lane = threadIdx.x & 31;
    const int r0   = threadIdx.x >> 5;           // 0..7
    const int j    = blockIdx.x * 32 + lane;
    float acc = 0.f;
    for (int r = r0; r < rows; r += 8) {
        float t = v[(size_t)r * cols + j];
        acc += t * t;
    }
    red[r0][lane] = acc;
    __syncthreads();
    if (r0 == 0) {
        float s = red[0][lane];
#pragma unroll
        for (int q = 1; q < 8; q++) s += red[q][lane];
        scale[j] = g[j] / sqrtf(s);
    }
}

// ======================= SGEMM: C[M,N] = A[M,K] @ B[N,K]^T + epilogue =======
// A row-major [M,K]; B row-major [N,K] (K contiguous for both).
// Epilogue: +bias[col]; optional exact GELU; optional +res[row,col].
// Optional per-K column scale on A (weight-norm fold).
template<bool COLSCALE, bool DOGELU, bool RES>
__global__ __launch_bounds__(256) void sgemm_nt(const float* __restrict__ A,
                                                const float* __restrict__ B,
                                                const float* __restrict__ bias,
                                                const float* __restrict__ cs,
                                                const float* __restrict__ res,
                                                float* __restrict__ C,
                                                int M, int N, int K) {
    __shared__ float As[16][132];
    __shared__ float Bs[16][132];
    const int tid = threadIdx.x;
    const int m0 = blockIdx.y * 128;
    const int n0 = blockIdx.x * 128;
    const int tr = tid >> 4;       // 0..15 -> rows tr*8..tr*8+7
    const int tc = tid & 15;       // 0..15 -> cols tc*8..tc*8+7

    float acc[8][8];
#pragma unroll
    for (int i = 0; i < 8; i++)
#pragma unroll
        for (int j = 0; j < 8; j++) acc[i][j] = 0.f;

    for (int k0 = 0; k0 < K; k0 += 16) {
#pragma unroll
        for (int q = 0; q < 2; q++) {
            const int idx = tid + q * 256;          // 0..511
            const int r  = idx >> 2;                // 0..127
            const int kk = (idx & 3) * 4;           // 0,4,8,12
            float4 av = *(const float4*)&A[(size_t)(m0 + r) * K + k0 + kk];
            if (COLSCALE) {
                av.x *= cs[k0 + kk + 0];
                av.y *= cs[k0 + kk + 1];
                av.z *= cs[k0 + kk + 2];
                av.w *= cs[k0 + kk + 3];
            }
            As[kk + 0][r] = av.x; As[kk + 1][r] = av.y;
            As[kk + 2][r] = av.z; As[kk + 3][r] = av.w;
            float4 bv = *(const float4*)&B[(size_t)(n0 + r) * K + k0 + kk];
            Bs[kk + 0][r] = bv.x; Bs[kk + 1][r] = bv.y;
            Bs[kk + 2][r] = bv.z; Bs[kk + 3][r] = bv.w;
        }
        __syncthreads();
#pragma unroll
        for (int kk = 0; kk < 16; kk++) {
            float a[8], bb[8];
            *(float4*)&a[0]  = *(const float4*)&As[kk][tr * 8];
            *(float4*)&a[4]  = *(const float4*)&As[kk][tr * 8 + 4];
            *(float4*)&bb[0] = *(const float4*)&Bs[kk][tc * 8];
            *(float4*)&bb[4] = *(const float4*)&Bs[kk][tc * 8 + 4];
#pragma unroll
            for (int i = 0; i < 8; i++)
#pragma unroll
                for (int j = 0; j < 8; j++) acc[i][j] += a[i] * bb[j];
        }
        __syncthreads();
    }

#pragma unroll
    for (int i = 0; i < 8; i++) {
        const int row = m0 + tr * 8 + i;
#pragma unroll
        for (int j0 = 0; j0 < 8; j0 += 4) {
            const int col = n0 + tc * 8 + j0;
            float4 cv;
            cv.x = acc[i][j0 + 0]; cv.y = acc[i][j0 + 1];
            cv.z = acc[i][j0 + 2]; cv.w = acc[i][j0 + 3];
            const float4 bi = *(const float4*)&bias[col];
            cv.x += bi.x; cv.y += bi.y; cv.z += bi.z; cv.w += bi.w;
            if (DOGELU) {
                cv.x = 0.5f * cv.x * (1.f + erff(cv.x * 0.70710678118654752f));
                cv.y = 0.5f * cv.y * (1.f + erff(cv.y * 0.70710678118654752f));
                cv.z = 0.5f * cv.z * (1.f + erff(cv.z * 0.70710678118654752f));
                cv.w = 0.5f * cv.w * (1.f + erff(cv.w * 0.70710678118654752f));
            }
            if (RES) {
                const float4 rv = *(const float4*)&res[(size_t)row * N + col];
                cv.x += rv.x; cv.y += rv.y; cv.z += rv.z; cv.w += rv.w;
            }
            *(float4*)&C[(size_t)row * N + col] = cv;
        }
    }
}

// ======================= Flash attention (fp32, online softmax) ============
// Grid: (SEQ/64, H, B). Block: 256 threads. 64 queries x full D=128 per CTA.
// q/k/v live interleaved in qkv buffer: row stride 6144; k at +2048, v at +4096.
// emotion_bias is constant over the softmax axis -> dropped (softmax invariant).
#define ATT_SMEM_FLOATS (128*72*2 + 64*128 + 64*68 + 3*64)

__global__ __launch_bounds__(256) void attn_kernel(const float* __restrict__ qkv,
                                                   float* __restrict__ out) {
    extern __shared__ float sm[];
    float* Qt   = sm;                   // [128][72]  (d-major, row index last)
    float* Kt   = Qt + 128 * 72;        // [128][72]
    float* Vs   = Kt + 128 * 72;        // [64][128]
    float* Ss   = Vs + 64 * 128;        // [64][68]
    float* mrow = Ss + 64 * 68;
    float* lrow = mrow + 64;
    float* crow = lrow + 64;

    const int tid = threadIdx.x;
    const int qb  = blockIdx.x * 64;
    const int h   = blockIdx.y;
    const int b   = blockIdx.z;
    const size_t rs = QKV_W;
    const float* qbase = qkv + (size_t)b * SEQ * rs + (size_t)h * HEAD_DIM;
    const float* kbase = qbase + N_EMBD;
    const float* vbase = qbase + 2 * N_EMBD;

    // load Q transposed: Qt[d][r]
#pragma unroll
    for (int q = 0; q < 8; q++) {
        const int idx = tid + q * 256;         // 0..2047
        const int r  = idx >> 5;               // 0..63
        const int d4 = (idx & 31) * 4;         // 0..124
        const float4 v = *(const float4*)&qbase[(size_t)(qb + r) * rs + d4];
        Qt[(d4 + 0) * 72 + r] = v.x; Qt[(d4 + 1) * 72 + r] = v.y;
        Qt[(d4 + 2) * 72 + r] = v.z; Qt[(d4 + 3) * 72 + r] = v.w;
    }
    if (tid < 64) { mrow[tid] = -INFINITY; lrow[tid] = 0.f; }

    const int tr = tid >> 4;   // 0..15
    const int tc = tid & 15;   // 0..15
    float o[4][8];
#pragma unroll
    for (int i = 0; i < 4; i++)
#pragma unroll
        for (int j = 0; j < 8; j++) o[i][j] = 0.f;

    __syncthreads();

    for (int kt = 0; kt < SEQ; kt += 64) {
        // load K transposed + V
#pragma unroll
        for (int q = 0; q < 8; q++) {
            const int idx = tid + q * 256;
            const int r  = idx >> 5;
            const int d4 = (idx & 31) * 4;
            const float4 kv = *(const float4*)&kbase[(size_t)(kt + r) * rs + d4];
            Kt[(d4 + 0) * 72 + r] = kv.x; Kt[(d4 + 1) * 72 + r] = kv.y;
            Kt[(d4 + 2) * 72 + r] = kv.z; Kt[(d4 + 3) * 72 + r] = kv.w;
            const float4 vv = *(const float4*)&vbase[(size_t)(kt + r) * rs + d4];
            *(float4*)&Vs[r * 128 + d4] = vv;
        }
        __syncthreads();

        // S = Q K^T / sqrt(D)
        float s[4][4];
#pragma unroll
        for (int i = 0; i < 4; i++)
#pragma unroll
            for (int j = 0; j < 4; j++) s[i][j] = 0.f;
#pragma unroll 8
        for (int kk = 0; kk < 128; kk++) {
            float a[4], bv[4];
            *(float4*)a  = *(const float4*)&Qt[kk * 72 + tr * 4];
            *(float4*)bv = *(const float4*)&Kt[kk * 72 + tc * 4];
#pragma unroll
            for (int i = 0; i < 4; i++)
#pragma unroll
                for (int j = 0; j < 4; j++) s[i][j] += a[i] * bv[j];
        }
        const float sc = 0.08838834764831845f;  // 1/sqrt(128)
#pragma unroll
        for (int i = 0; i < 4; i++)
#pragma unroll
            for (int j = 0; j < 4; j++)
                Ss[(tr * 4 + i) * 68 + tc * 4 + j] = s[i][j] * sc;
        __syncthreads();

        // online softmax stats, one thread per row
        if (tid < 64) {
            float* srow = &Ss[tid * 68];
            const float mold = mrow[tid];
            float mn = mold;
#pragma unroll 8
            for (int c = 0; c < 64; c++) mn = fmaxf(mn, srow[c]);
            const float corr = expf(mold - mn);   // 0 on first tile
            float sum = 0.f;
#pragma unroll 8
            for (int c = 0; c < 64; c++) {
                const float p = expf(srow[c] - mn);
                srow[c] = p;
                sum += p;
            }
            lrow[tid] = lrow[tid] * corr + sum;
            mrow[tid] = mn;
            crow[tid] = corr;
        }
        __syncthreads();

        // O = O*corr + P @ V
#pragma unroll
        for (int i = 0; i < 4; i++) {
            const float cf = crow[tr * 4 + i];
#pragma unroll
            for (int j = 0; j < 8; j++) o[i][j] *= cf;
        }
#pragma unroll 4
        for (int k = 0; k < 64; k++) {
            float p[4];
#pragma unroll
            for (int i = 0; i < 4; i++) p[i] = Ss[(tr * 4 + i) * 68 + k];
            float v0[4], v1[4];
            *(float4*)v0 = *(const float4*)&Vs[k * 128 + tc * 4];
            *(float4*)v1 = *(const float4*)&Vs[k * 128 + 64 + tc * 4];
#pragma unroll
            for (int i = 0; i < 4; i++) {
#pragma unroll
                for (int j = 0; j < 4; j++) {
                    o[i][j]     += p[i] * v0[j];
                    o[i][4 + j] += p[i] * v1[j];
                }
            }
        }
        __syncthreads();
    }

    // normalize + write attn output in [B,S,E] layout (e = h*128 + d)
#pragma unroll
    for (int i = 0; i < 4; i++) {
        const int r = qb + tr * 4 + i;
        const float inv = 1.f / lrow[tr * 4 + i];
        const size_t base = ((size_t)b * SEQ + r) * N_EMBD + (size_t)h * HEAD_DIM;
        float4 r0, r1;
        r0.x = o[i][0] * inv; r0.y = o[i][1] * inv; r0.z = o[i][2] * inv; r0.w = o[i][3] * inv;
        r1.x = o[i][4] * inv; r1.y = o[i][5] * inv; r1.z = o[i][6] * inv; r1.w = o[i][7] * inv;
        *(float4*)&out[base + tc * 4]      = r0;
        *(float4*)&out[base + 64 + tc * 4] = r1;
    }
}

// =========================== launch sequence ===============================
extern "C" void kernel_launch(void* const* d_in, const int* in_sizes, int n_in,
                              void* d_out, int out_size) {
    const float* hs      = (const float*)d_in[0];
    const float* ln1_g   = (const float*)d_in[1];
    const float* ln1_b   = (const float*)d_in[2];
    const float* w_qkv   = (const float*)d_in[3];
    const float* b_qkv   = (const float*)d_in[4];
    const float* attn_v  = (const float*)d_in[5];
    const float* attn_g  = (const float*)d_in[6];
    const float* attn_b  = (const float*)d_in[7];
    /* d_in[8] = emotion_bias: softmax-invariant, unused */
    const float* ln2_g   = (const float*)d_in[9];
    const float* ln2_b   = (const float*)d_in[10];
    const float* w_fc    = (const float*)d_in[11];
    const float* b_fc    = (const float*)d_in[12];
    const float* mlp_v   = (const float*)d_in[13];
    const float* mlp_g   = (const float*)d_in[14];
    const float* mlp_b   = (const float*)d_in[15];
    float* out = (float*)d_out;

    float *ln, *qkv, *attn, *hid, *fc, *sA, *sM;
    cudaGetSymbolAddress((void**)&ln,   g_ln);
    cudaGetSymbolAddress((void**)&qkv,  g_qkv);
    cudaGetSymbolAddress((void**)&attn, g_attn);
    cudaGetSymbolAddress((void**)&hid,  g_hid);
    cudaGetSymbolAddress((void**)&fc,   g_fc);
    cudaGetSymbolAddress((void**)&sA,   g_sA);
    cudaGetSymbolAddress((void**)&sM,   g_sM);

    const size_t att_smem = (size_t)ATT_SMEM_FLOATS * sizeof(float);
    cudaFuncSetAttribute(attn_kernel,
                         cudaFuncAttributeMaxDynamicSharedMemorySize,
                         (int)att_smem);

    // weight-norm column scales
    colnorm_kernel<<<N_EMBD / 32, 256>>>(attn_v, attn_g, sA, N_EMBD, N_EMBD);
    colnorm_kernel<<<N_INNER / 32, 256>>>(mlp_v, mlp_g, sM, N_EMBD, N_INNER);

    // LN1
    ln_kernel<<<ROWS, 256>>>(hs, ln1_g, ln1_b, ln);

    // QKV: [4096,6144] = ln @ w_qkv^T + b_qkv
    sgemm_nt<false, false, false><<<dim3(QKV_W / 128, ROWS / 128), 256>>>(
        ln, w_qkv, b_qkv, nullptr, nullptr, qkv, ROWS, QKV_W, N_EMBD);

    // attention
    attn_kernel<<<dim3(SEQ / 64, N_HEAD, BATCH), 256, att_smem>>>(qkv, attn);

    // attn proj (weight-norm folded) + residual -> hidden
    sgemm_nt<true, false, true><<<dim3(N_EMBD / 128, ROWS / 128), 256>>>(
        attn, attn_v, attn_b, sA, hs, hid, ROWS, N_EMBD, N_EMBD);

    // LN2
    ln_kernel<<<ROWS, 256>>>(hid, ln2_g, ln2_b, ln);

    // FC + exact GELU: [4096,8192]
    sgemm_nt<false, true, false><<<dim3(N_INNER / 128, ROWS / 128), 256>>>(
        ln, w_fc, b_fc, nullptr, nullptr, fc, ROWS, N_INNER, N_EMBD);

    // MLP proj (weight-norm folded) + residual -> output
    sgemm_nt<true, false, true><<<dim3(N_EMBD / 128, ROWS / 128), 256>>>(
        fc, mlp_v, mlp_b, sM, hid, out, ROWS, N_EMBD, N_INNER);
}

// round 6
// speedup vs baseline: 1.8249x; 1.8249x over previous
#include <cuda_runtime.h>
#include <cuda_bf16.h>
#include <math.h>
#include <stdint.h>

// ---------------- problem constants ----------------
#define N_EMBD   2048
#define N_HEAD   16
#define HEAD_DIM 128
#define N_INNER  8192
#define SEQ      2048
#define BATCH    2
#define ROWS     (BATCH*SEQ)     /* 4096 */
#define QKV_W    (3*N_EMBD)      /* 6144 */

typedef __nv_bfloat16 bf16;
typedef __nv_bfloat162 bf162;

// ---------------- scratch (device globals; no allocs allowed) ----------------
__device__ float g_qkv [(size_t)ROWS * QKV_W];     // fp32 qkv (attention input)
__device__ float g_hid [(size_t)ROWS * N_EMBD];    // post-attn hidden (fp32)
__device__ bf16  g_xh  [(size_t)ROWS * N_EMBD];    // LN output hi
__device__ bf16  g_xl  [(size_t)ROWS * N_EMBD];    // LN output lo
__device__ bf16  g_ah  [(size_t)ROWS * N_EMBD];    // attention output hi
__device__ bf16  g_al  [(size_t)ROWS * N_EMBD];    // attention output lo
__device__ bf16  g_fh  [(size_t)ROWS * N_INNER];   // gelu(fc) hi
__device__ bf16  g_fl  [(size_t)ROWS * N_INNER];   // gelu(fc) lo
__device__ bf16  g_wqkvh[(size_t)QKV_W * N_EMBD];
__device__ bf16  g_wqkvl[(size_t)QKV_W * N_EMBD];
__device__ bf16  g_wph [(size_t)N_EMBD * N_EMBD];  // attn proj (wn-folded) hi
__device__ bf16  g_wpl [(size_t)N_EMBD * N_EMBD];
__device__ bf16  g_wfh [(size_t)N_INNER * N_EMBD];
__device__ bf16  g_wfl [(size_t)N_INNER * N_EMBD];
__device__ bf16  g_wmh [(size_t)N_EMBD * N_INNER]; // mlp proj (wn-folded) hi
__device__ bf16  g_wml [(size_t)N_EMBD * N_INNER];
__device__ float g_sA  [N_EMBD];
__device__ float g_sM  [N_INNER];

// ========================= helpers (plain sm_100 only) =====================
__device__ __forceinline__ uint32_t smem_u32(const void* p) {
    uint32_t a;
    asm("{ .reg .u64 t; cvta.to.shared.u64 t, %1; cvt.u32.u64 %0, t; }"
        : "=r"(a) : "l"(p));
    return a;
}
#define CP16(d, s) \
    asm volatile("cp.async.cg.shared.global [%0], [%1], 16;" :: "r"(d), "l"(s))
__device__ __forceinline__ void cp_commit() {
    asm volatile("cp.async.commit_group;" ::: "memory");
}
template<int N> __device__ __forceinline__ void cp_wait() {
    asm volatile("cp.async.wait_group %0;" :: "n"(N) : "memory");
}
__device__ __forceinline__ void ldsm4(uint32_t& r0, uint32_t& r1,
                                      uint32_t& r2, uint32_t& r3, uint32_t addr) {
    asm volatile("ldmatrix.sync.aligned.m8n8.x4.shared.b16 {%0,%1,%2,%3}, [%4];"
                 : "=r"(r0), "=r"(r1), "=r"(r2), "=r"(r3) : "r"(addr));
}
__device__ __forceinline__ void mma_bf16(float* c, const uint32_t* a,
                                         const uint32_t* b) {
    asm volatile(
        "mma.sync.aligned.m16n8k16.row.col.f32.bf16.bf16.f32 "
        "{%0,%1,%2,%3}, {%4,%5,%6,%7}, {%8,%9}, {%0,%1,%2,%3};"
        : "+f"(c[0]), "+f"(c[1]), "+f"(c[2]), "+f"(c[3])
        : "r"(a[0]), "r"(a[1]), "r"(a[2]), "r"(a[3]), "r"(b[0]), "r"(b[1]));
}
__device__ __forceinline__ void split2(float x, bf16& h, bf16& l) {
    h = __float2bfloat16(x);
    l = __float2bfloat16(x - __bfloat162float(h));
}

// ======================= LayerNorm -> bf16 hi/lo ============================
__global__ __launch_bounds__(256) void ln_kernel(const float* __restrict__ x,
                                                 const float* __restrict__ g,
                                                 const float* __restrict__ b,
                                                 bf16* __restrict__ yh,
                                                 bf16* __restrict__ yl) {
    __shared__ float red[8];
    __shared__ float s_mean, s_rstd;
    const int row = blockIdx.x, tid = threadIdx.x;
    const float* xr = x + (size_t)row * N_EMBD;
    float v[8];
    float s = 0.f;
#pragma unroll
    for (int k = 0; k < 8; k++) { v[k] = xr[tid + k * 256]; s += v[k]; }
#pragma unroll
    for (int o = 16; o > 0; o >>= 1) s += __shfl_xor_sync(0xffffffffu, s, o);
    if ((tid & 31) == 0) red[tid >> 5] = s;
    __syncthreads();
    if (tid == 0) {
        float t = 0.f;
#pragma unroll
        for (int i = 0; i < 8; i++) t += red[i];
        s_mean = t * (1.f / N_EMBD);
    }
    __syncthreads();
    const float mu = s_mean;
    float vs = 0.f;
#pragma unroll
    for (int k = 0; k < 8; k++) { float d = v[k] - mu; vs += d * d; }
#pragma unroll
    for (int o = 16; o > 0; o >>= 1) vs += __shfl_xor_sync(0xffffffffu, vs, o);
    if ((tid & 31) == 0) red[tid >> 5] = vs;
    __syncthreads();
    if (tid == 0) {
        float t = 0.f;
#pragma unroll
        for (int i = 0; i < 8; i++) t += red[i];
        s_rstd = rsqrtf(t * (1.f / N_EMBD) + 1e-5f);
    }
    __syncthreads();
    const float rstd = s_rstd;
    bf16* yhr = yh + (size_t)row * N_EMBD;
    bf16* ylr = yl + (size_t)row * N_EMBD;
#pragma unroll
    for (int k = 0; k < 8; k++) {
        const int c = tid + k * 256;
        const float val = (v[k] - mu) * rstd * g[c] + b[c];
        bf16 h, l; split2(val, h, l);
        yhr[c] = h; ylr[c] = l;
    }
}

// ========== weight-norm column scales: s[j] = g[j] / ||v[:,j]||_2 ==========
__global__ __launch_bounds__(256) void colnorm_kernel(const float* __restrict__ v,
                                                      const float* __restrict__ g,
                                                      float* __restrict__ scale,
                                                      int rows, int cols) {
    __shared__ float red[8][32];
    const int lane = threadIdx.x & 31;
    const int r0   = threadIdx.x >> 5;
    const int j    = blockIdx.x * 32 + lane;
    float acc = 0.f;
    for (int r = r0; r < rows; r += 8) {
        float t = v[(size_t)r * cols + j];
        acc += t * t;
    }
    red[r0][lane] = acc;
    __syncthreads();
    if (r0 == 0) {
        float s = red[0][lane];
#pragma unroll
        for (int q = 1; q < 8; q++) s += red[q][lane];
        scale[j] = g[j] / sqrtf(s);
    }
}

// ========== weight conversion: fp32 (optionally * s[k]) -> bf16 hi/lo =======
__global__ __launch_bounds__(256) void convw_kernel(const float* __restrict__ w,
                                                    const float* __restrict__ s,
                                                    bf16* __restrict__ hi,
                                                    bf16* __restrict__ lo,
                                                    int K, size_t n4) {
    const size_t i = (size_t)blockIdx.x * 256 + threadIdx.x;
    if (i >= n4) return;
    float4 v = ((const float4*)w)[i];
    if (s) {
        const int k = (int)((i * 4) % (size_t)K);
        v.x *= s[k]; v.y *= s[k + 1]; v.z *= s[k + 2]; v.w *= s[k + 3];
    }
    bf16 h0, h1, h2, h3, l0, l1, l2, l3;
    split2(v.x, h0, l0); split2(v.y, h1, l1);
    split2(v.z, h2, l2); split2(v.w, h3, l3);
    bf162 ph0; ph0.x = h0; ph0.y = h1;
    bf162 ph1; ph1.x = h2; ph1.y = h3;
    bf162 pl0; pl0.x = l0; pl0.y = l1;
    bf162 pl1; pl1.x = l2; pl1.y = l3;
    bf162* H = (bf162*)(hi + i * 4);
    bf162* L = (bf162*)(lo + i * 4);
    H[0] = ph0; H[1] = ph1;
    L[0] = pl0; L[1] = pl1;
}

// ================= HMMA split-bf16 GEMM: C = A @ B^T + epilogue ============
// A = Ah+Al [M,K] bf16 row-major; B = Bh+Bl [N,K] bf16 row-major.
// fp32 accumulate of Ah*Bh + Ah*Bl + Al*Bh via mma.sync.m16n8k16 (plain sm_100).
// CTA tile 128x128, 8 warps (warp tile 64x32), K-chunk 32, cp.async double buffer.
// SMEM rows padded to 40 bf16 (80B) -> conflict-free ldmatrix.
#define CH_A_H 0
#define CH_A_L 10240
#define CH_B_H 20480
#define CH_B_L 30720
#define CHUNK_BYTES 40960
#define GEMM_SMEM (2 * CHUNK_BYTES)

__device__ __forceinline__ void load_chunk(const bf16* __restrict__ Ah,
                                           const bf16* __restrict__ Al,
                                           const bf16* __restrict__ Bh,
                                           const bf16* __restrict__ Bl,
                                           int m0, int n0, int k0, int K,
                                           uint32_t sbuf, int tid) {
#pragma unroll
    for (int q = 0; q < 2; q++) {
        const int c   = tid + q * 256;       // 0..511
        const int row = c >> 2;              // 0..127
        const int kp  = c & 3;               // 16B chunk within 64B row
        const uint32_t doff = (uint32_t)(row * 80 + kp * 16);
        const size_t ga = (size_t)(m0 + row) * K + k0 + kp * 8;
        const size_t gb = (size_t)(n0 + row) * K + k0 + kp * 8;
        CP16(sbuf + CH_A_H + doff, Ah + ga);
        CP16(sbuf + CH_A_L + doff, Al + ga);
        CP16(sbuf + CH_B_H + doff, Bh + gb);
        CP16(sbuf + CH_B_L + doff, Bl + gb);
    }
}

template<bool DOGELU, bool RES, bool WF32, bool WPAIR>
__global__ __launch_bounds__(256) void tgemm(const bf16* __restrict__ Ah,
                                             const bf16* __restrict__ Al,
                                             const bf16* __restrict__ Bh,
                                             const bf16* __restrict__ Bl,
                                             const float* __restrict__ bias,
                                             const float* __restrict__ res,
                                             float* __restrict__ C,
                                             bf16* __restrict__ Ch,
                                             bf16* __restrict__ Cl,
                                             int M, int N, int K) {
    extern __shared__ char sm[];
    const uint32_t sb = smem_u32(sm);
    const int tid  = threadIdx.x;
    const int lane = tid & 31;
    const int wid  = tid >> 5;
    const int warp_m = wid & 1;     // 0..1 -> 64-row half
    const int warp_n = wid >> 1;    // 0..3 -> 32-col slice
    const int m0 = blockIdx.y * 128;
    const int n0 = blockIdx.x * 128;

    float acc[4][4][4];
#pragma unroll
    for (int i = 0; i < 4; i++)
#pragma unroll
        for (int j = 0; j < 4; j++)
#pragma unroll
            for (int t = 0; t < 4; t++) acc[i][j][t] = 0.f;

    // ldmatrix lane address components
    const uint32_t a_row  = (uint32_t)(warp_m * 64 + (lane & 15));
    const uint32_t a_koff = (uint32_t)((lane >> 4) * 8);
    const uint32_t b_row  = (uint32_t)(warp_n * 32 + ((lane >> 4) & 1) * 8 + (lane & 7));
    const uint32_t b_koff = (uint32_t)(((lane >> 3) & 1) * 8);

    const int nc = K / 32;
    load_chunk(Ah, Al, Bh, Bl, m0, n0, 0, K, sb, tid);
    cp_commit();

    for (int c = 0; c < nc; c++) {
        if (c + 1 < nc) {
            load_chunk(Ah, Al, Bh, Bl, m0, n0, (c + 1) * 32, K,
                       sb + (uint32_t)(((c + 1) & 1) * CHUNK_BYTES), tid);
            cp_commit();
            cp_wait<1>();
        } else {
            cp_wait<0>();
        }
        __syncthreads();

        const uint32_t st = sb + (uint32_t)((c & 1) * CHUNK_BYTES);
#pragma unroll
        for (int s = 0; s < 2; s++) {
            uint32_t ah[4][4], al[4][4], bh[4][2], bl[4][2];
#pragma unroll
            for (int i = 0; i < 4; i++) {
                const uint32_t off = (a_row + i * 16) * 80 + (s * 16 + a_koff) * 2;
                ldsm4(ah[i][0], ah[i][1], ah[i][2], ah[i][3], st + CH_A_H + off);
                ldsm4(al[i][0], al[i][1], al[i][2], al[i][3], st + CH_A_L + off);
            }
#pragma unroll
            for (int j2 = 0; j2 < 2; j2++) {
                const uint32_t off = (b_row + j2 * 16) * 80 + (s * 16 + b_koff) * 2;
                uint32_t t0, t1, t2, t3;
                ldsm4(t0, t1, t2, t3, st + CH_B_H + off);
                bh[2 * j2][0] = t0; bh[2 * j2][1] = t1;
                bh[2 * j2 + 1][0] = t2; bh[2 * j2 + 1][1] = t3;
                ldsm4(t0, t1, t2, t3, st + CH_B_L + off);
                bl[2 * j2][0] = t0; bl[2 * j2][1] = t1;
                bl[2 * j2 + 1][0] = t2; bl[2 * j2 + 1][1] = t3;
            }
#pragma unroll
            for (int i = 0; i < 4; i++)
#pragma unroll
                for (int j = 0; j < 4; j++) {
                    mma_bf16(acc[i][j], ah[i], bh[j]);
                    mma_bf16(acc[i][j], ah[i], bl[j]);
                    mma_bf16(acc[i][j], al[i], bh[j]);
                }
        }
        __syncthreads();
    }

    // ---------------- epilogue: direct register stores ----------------
    const int r_base = m0 + warp_m * 64 + (lane >> 2);
    const int c_base = n0 + warp_n * 32 + 2 * (lane & 3);
#pragma unroll
    for (int i = 0; i < 4; i++) {
#pragma unroll
        for (int j = 0; j < 4; j++) {
            const int col = c_base + j * 8;
            const float2 bi = *(const float2*)&bias[col];
#pragma unroll
            for (int half = 0; half < 2; half++) {
                const int row = r_base + i * 16 + half * 8;
                float2 v;
                v.x = acc[i][j][half * 2 + 0] + bi.x;
                v.y = acc[i][j][half * 2 + 1] + bi.y;
                if (DOGELU) {
                    v.x = 0.5f * v.x * (1.f + erff(v.x * 0.70710678118654752f));
                    v.y = 0.5f * v.y * (1.f + erff(v.y * 0.70710678118654752f));
                }
                if (RES) {
                    const float2 rv = *(const float2*)&res[(size_t)row * N + col];
                    v.x += rv.x; v.y += rv.y;
                }
                if (WF32) *(float2*)&C[(size_t)row * N + col] = v;
                if (WPAIR) {
                    bf16 h0, h1, l0, l1;
                    split2(v.x, h0, l0); split2(v.y, h1, l1);
                    bf162 ph; ph.x = h0; ph.y = h1;
                    bf162 pl; pl.x = l0; pl.y = l1;
                    *(bf162*)&Ch[(size_t)row * N + col] = ph;
                    *(bf162*)&Cl[(size_t)row * N + col] = pl;
                }
            }
        }
    }
}

// ======================= Flash attention (fp32, online softmax) ============
// emotion_bias is constant over the softmax axis -> dropped (softmax invariant).
// Output written directly as bf16 hi/lo pairs for the proj GEMM.
#define ATT_SMEM_FLOATS (128*72*2 + 64*128 + 64*68 + 3*64)

__global__ __launch_bounds__(256) void attn_kernel(const float* __restrict__ qkv,
                                                   bf16* __restrict__ oh,
                                                   bf16* __restrict__ ol) {
    extern __shared__ float smf[];
    float* Qt   = smf;
    float* Kt   = Qt + 128 * 72;
    float* Vs   = Kt + 128 * 72;
    float* Ss   = Vs + 64 * 128;
    float* mrow = Ss + 64 * 68;
    float* lrow = mrow + 64;
    float* crow = lrow + 64;

    const int tid = threadIdx.x;
    const int qb  = blockIdx.x * 64;
    const int hh  = blockIdx.y;
    const int b   = blockIdx.z;
    const size_t rs = QKV_W;
    const float* qbase = qkv + (size_t)b * SEQ * rs + (size_t)hh * HEAD_DIM;
    const float* kbase = qbase + N_EMBD;
    const float* vbase = qbase + 2 * N_EMBD;

#pragma unroll
    for (int q = 0; q < 8; q++) {
        const int idx = tid + q * 256;
        const int r  = idx >> 5;
        const int d4 = (idx & 31) * 4;
        const float4 v = *(const float4*)&qbase[(size_t)(qb + r) * rs + d4];
        Qt[(d4 + 0) * 72 + r] = v.x; Qt[(d4 + 1) * 72 + r] = v.y;
        Qt[(d4 + 2) * 72 + r] = v.z; Qt[(d4 + 3) * 72 + r] = v.w;
    }
    if (tid < 64) { mrow[tid] = -INFINITY; lrow[tid] = 0.f; }

    const int tr = tid >> 4;
    const int tc = tid & 15;
    float o[4][8];
#pragma unroll
    for (int i = 0; i < 4; i++)
#pragma unroll
        for (int j = 0; j < 8; j++) o[i][j] = 0.f;

    __syncthreads();

    for (int kt = 0; kt < SEQ; kt += 64) {
#pragma unroll
        for (int q = 0; q < 8; q++) {
            const int idx = tid + q * 256;
            const int r  = idx >> 5;
            const int d4 = (idx & 31) * 4;
            const float4 kv = *(const float4*)&kbase[(size_t)(kt + r) * rs + d4];
            Kt[(d4 + 0) * 72 + r] = kv.x; Kt[(d4 + 1) * 72 + r] = kv.y;
            Kt[(d4 + 2) * 72 + r] = kv.z; Kt[(d4 + 3) * 72 + r] = kv.w;
            const float4 vv = *(const float4*)&vbase[(size_t)(kt + r) * rs + d4];
            *(float4*)&Vs[r * 128 + d4] = vv;
        }
        __syncthreads();

        float s[4][4];
#pragma unroll
        for (int i = 0; i < 4; i++)
#pragma unroll
            for (int j = 0; j < 4; j++) s[i][j] = 0.f;
#pragma unroll 8
        for (int kk = 0; kk < 128; kk++) {
            float a[4], bv[4];
            *(float4*)a  = *(const float4*)&Qt[kk * 72 + tr * 4];
            *(float4*)bv = *(const float4*)&Kt[kk * 72 + tc * 4];
#pragma unroll
            for (int i = 0; i < 4; i++)
#pragma unroll
                for (int j = 0; j < 4; j++) s[i][j] += a[i] * bv[j];
        }
        const float sc = 0.08838834764831845f;
#pragma unroll
        for (int i = 0; i < 4; i++)
#pragma unroll
            for (int j = 0; j < 4; j++)
                Ss[(tr * 4 + i) * 68 + tc * 4 + j] = s[i][j] * sc;
        __syncthreads();

        if (tid < 64) {
            float* srow = &Ss[tid * 68];
            const float mold = mrow[tid];
            float mn = mold;
#pragma unroll 8
            for (int c = 0; c < 64; c++) mn = fmaxf(mn, srow[c]);
            const float corr = expf(mold - mn);
            float sum = 0.f;
#pragma unroll 8
            for (int c = 0; c < 64; c++) {
                const float p = expf(srow[c] - mn);
                srow[c] = p;
                sum += p;
            }
            lrow[tid] = lrow[tid] * corr + sum;
            mrow[tid] = mn;
            crow[tid] = corr;
        }
        __syncthreads();

#pragma unroll
        for (int i = 0; i < 4; i++) {
            const float cf = crow[tr * 4 + i];
#pragma unroll
            for (int j = 0; j < 8; j++) o[i][j] *= cf;
        }
#pragma unroll 4
        for (int k = 0; k < 64; k++) {
            float p[4];
#pragma unroll
            for (int i = 0; i < 4; i++) p[i] = Ss[(tr * 4 + i) * 68 + k];
            float v0[4], v1[4];
            *(float4*)v0 = *(const float4*)&Vs[k * 128 + tc * 4];
            *(float4*)v1 = *(const float4*)&Vs[k * 128 + 64 + tc * 4];
#pragma unroll
            for (int i = 0; i < 4; i++) {
#pragma unroll
                for (int j = 0; j < 4; j++) {
                    o[i][j]     += p[i] * v0[j];
                    o[i][4 + j] += p[i] * v1[j];
                }
            }
        }
        __syncthreads();
    }

#pragma unroll
    for (int i = 0; i < 4; i++) {
        const int r = qb + tr * 4 + i;
        const float inv = 1.f / lrow[tr * 4 + i];
        const size_t base = ((size_t)b * SEQ + r) * N_EMBD + (size_t)hh * HEAD_DIM;
#pragma unroll
        for (int half = 0; half < 2; half++) {
            float vv[4];
#pragma unroll
            for (int j = 0; j < 4; j++) vv[j] = o[i][half * 4 + j] * inv;
            bf16 hb[4], lb[4];
#pragma unroll
            for (int j = 0; j < 4; j++) split2(vv[j], hb[j], lb[j]);
            bf162 p0; p0.x = hb[0]; p0.y = hb[1];
            bf162 p1; p1.x = hb[2]; p1.y = hb[3];
            bf162 q0; q0.x = lb[0]; q0.y = lb[1];
            bf162 q1; q1.x = lb[2]; q1.y = lb[3];
            const size_t off = base + half * 64 + tc * 4;
            bf162* H = (bf162*)(oh + off);
            bf162* L = (bf162*)(ol + off);
            H[0] = p0; H[1] = p1;
            L[0] = q0; L[1] = q1;
        }
    }
}

// =========================== launch sequence ===============================
extern "C" void kernel_launch(void* const* d_in, const int* in_sizes, int n_in,
                              void* d_out, int out_size) {
    const float* hs      = (const float*)d_in[0];
    const float* ln1_g   = (const float*)d_in[1];
    const float* ln1_b   = (const float*)d_in[2];
    const float* w_qkv   = (const float*)d_in[3];
    const float* b_qkv   = (const float*)d_in[4];
    const float* attn_v  = (const float*)d_in[5];
    const float* attn_g  = (const float*)d_in[6];
    const float* attn_b  = (const float*)d_in[7];
    /* d_in[8] = emotion_bias: softmax-invariant, unused */
    const float* ln2_g   = (const float*)d_in[9];
    const float* ln2_b   = (const float*)d_in[10];
    const float* w_fc    = (const float*)d_in[11];
    const float* b_fc    = (const float*)d_in[12];
    const float* mlp_v   = (const float*)d_in[13];
    const float* mlp_g   = (const float*)d_in[14];
    const float* mlp_b   = (const float*)d_in[15];
    float* out = (float*)d_out;

    float *qkv, *hid, *sA, *sM;
    bf16 *xh, *xl, *ah, *al, *fh, *fl;
    bf16 *wqkvh, *wqkvl, *wph, *wpl, *wfh, *wfl, *wmh, *wml;
    cudaGetSymbolAddress((void**)&qkv,   g_qkv);
    cudaGetSymbolAddress((void**)&hid,   g_hid);
    cudaGetSymbolAddress((void**)&sA,    g_sA);
    cudaGetSymbolAddress((void**)&sM,    g_sM);
    cudaGetSymbolAddress((void**)&xh,    g_xh);
    cudaGetSymbolAddress((void**)&xl,    g_xl);
    cudaGetSymbolAddress((void**)&ah,    g_ah);
    cudaGetSymbolAddress((void**)&al,    g_al);
    cudaGetSymbolAddress((void**)&fh,    g_fh);
    cudaGetSymbolAddress((void**)&fl,    g_fl);
    cudaGetSymbolAddress((void**)&wqkvh, g_wqkvh);
    cudaGetSymbolAddress((void**)&wqkvl, g_wqkvl);
    cudaGetSymbolAddress((void**)&wph,   g_wph);
    cudaGetSymbolAddress((void**)&wpl,   g_wpl);
    cudaGetSymbolAddress((void**)&wfh,   g_wfh);
    cudaGetSymbolAddress((void**)&wfl,   g_wfl);
    cudaGetSymbolAddress((void**)&wmh,   g_wmh);
    cudaGetSymbolAddress((void**)&wml,   g_wml);

    const size_t att_smem = (size_t)ATT_SMEM_FLOATS * sizeof(float);
    cudaFuncSetAttribute(attn_kernel,
                         cudaFuncAttributeMaxDynamicSharedMemorySize, (int)att_smem);
    cudaFuncSetAttribute(tgemm<false, false, true, false>,
                         cudaFuncAttributeMaxDynamicSharedMemorySize, GEMM_SMEM);
    cudaFuncSetAttribute(tgemm<false, true, true, false>,
                         cudaFuncAttributeMaxDynamicSharedMemorySize, GEMM_SMEM);
    cudaFuncSetAttribute(tgemm<true, false, false, true>,
                         cudaFuncAttributeMaxDynamicSharedMemorySize, GEMM_SMEM);

    // weight-norm column scales
    colnorm_kernel<<<N_EMBD / 32, 256>>>(attn_v, attn_g, sA, N_EMBD, N_EMBD);
    colnorm_kernel<<<N_INNER / 32, 256>>>(mlp_v, mlp_g, sM, N_EMBD, N_INNER);

    // weight conversion to bf16 hi/lo (wn scales folded into proj weights)
    {
        size_t n4;
        n4 = (size_t)QKV_W * N_EMBD / 4;
        convw_kernel<<<(unsigned)((n4 + 255) / 256), 256>>>(w_qkv, nullptr, wqkvh, wqkvl, N_EMBD, n4);
        n4 = (size_t)N_EMBD * N_EMBD / 4;
        convw_kernel<<<(unsigned)((n4 + 255) / 256), 256>>>(attn_v, sA, wph, wpl, N_EMBD, n4);
        n4 = (size_t)N_INNER * N_EMBD / 4;
        convw_kernel<<<(unsigned)((n4 + 255) / 256), 256>>>(w_fc, nullptr, wfh, wfl, N_EMBD, n4);
        n4 = (size_t)N_EMBD * N_INNER / 4;
        convw_kernel<<<(unsigned)((n4 + 255) / 256), 256>>>(mlp_v, sM, wmh, wml, N_INNER, n4);
    }

    // LN1 -> bf16 hi/lo
    ln_kernel<<<ROWS, 256>>>(hs, ln1_g, ln1_b, xh, xl);

    // QKV GEMM: [4096,6144], K=2048, +bias, write fp32
    tgemm<false, false, true, false><<<dim3(QKV_W / 128, ROWS / 128), 256, GEMM_SMEM>>>(
        xh, xl, wqkvh, wqkvl, b_qkv, nullptr, qkv, nullptr, nullptr,
        ROWS, QKV_W, N_EMBD);

    // attention -> bf16 hi/lo
    attn_kernel<<<dim3(SEQ / 64, N_HEAD, BATCH), 256, att_smem>>>(qkv, ah, al);

    // attn proj + residual(hs) -> hid fp32
    tgemm<false, true, true, false><<<dim3(N_EMBD / 128, ROWS / 128), 256, GEMM_SMEM>>>(
        ah, al, wph, wpl, attn_b, hs, hid, nullptr, nullptr,
        ROWS, N_EMBD, N_EMBD);

    // LN2 -> bf16 hi/lo
    ln_kernel<<<ROWS, 256>>>(hid, ln2_g, ln2_b, xh, xl);

    // FC + GELU: [4096,8192], K=2048 -> bf16 hi/lo only
    tgemm<true, false, false, true><<<dim3(N_INNER / 128, ROWS / 128), 256, GEMM_SMEM>>>(
        xh, xl, wfh, wfl, b_fc, nullptr, nullptr, fh, fl,
        ROWS, N_INNER, N_EMBD);

    // MLP proj + residual(hid) -> out fp32, K=8192
    tgemm<false, true, true, false><<<dim3(N_EMBD / 128, ROWS / 128), 256, GEMM_SMEM>>>(
        fh, fl, wmh, wml, mlp_b, hid, out, nullptr, nullptr,
        ROWS, N_EMBD, N_INNER);
}

// round 9
// speedup vs baseline: 2.9572x; 1.6205x over previous
#include <cuda_runtime.h>
#include <cuda_bf16.h>
#include <math.h>
#include <stdint.h>

// ---------------- problem constants ----------------
#define N_EMBD   2048
#define N_HEAD   16
#define HEAD_DIM 128
#define N_INNER  8192
#define SEQ      2048
#define BATCH    2
#define ROWS     (BATCH*SEQ)     /* 4096 */
#define QKV_W    (3*N_EMBD)      /* 6144 */

typedef __nv_bfloat16 bf16;
typedef __nv_bfloat162 bf162;

// ---------------- scratch (device globals; no allocs allowed) ----------------
__device__ float g_hid [(size_t)ROWS * N_EMBD];    // post-attn hidden (fp32)
__device__ bf16  g_qh  [(size_t)ROWS * QKV_W];     // qkv hi
__device__ bf16  g_ql  [(size_t)ROWS * QKV_W];     // qkv lo
__device__ bf16  g_xh  [(size_t)ROWS * N_EMBD];    // LN output hi
__device__ bf16  g_xl  [(size_t)ROWS * N_EMBD];    // LN output lo
__device__ bf16  g_ah  [(size_t)ROWS * N_EMBD];    // attention output hi
__device__ bf16  g_al  [(size_t)ROWS * N_EMBD];    // attention output lo
__device__ bf16  g_fh  [(size_t)ROWS * N_INNER];   // gelu(fc) hi
__device__ bf16  g_fl  [(size_t)ROWS * N_INNER];   // gelu(fc) lo
__device__ bf16  g_wqkvh[(size_t)QKV_W * N_EMBD];
__device__ bf16  g_wqkvl[(size_t)QKV_W * N_EMBD];
__device__ bf16  g_wph [(size_t)N_EMBD * N_EMBD];  // attn proj (wn-folded) hi
__device__ bf16  g_wpl [(size_t)N_EMBD * N_EMBD];
__device__ bf16  g_wfh [(size_t)N_INNER * N_EMBD];
__device__ bf16  g_wfl [(size_t)N_INNER * N_EMBD];
__device__ bf16  g_wmh [(size_t)N_EMBD * N_INNER]; // mlp proj (wn-folded) hi
__device__ bf16  g_wml [(size_t)N_EMBD * N_INNER];
__device__ float g_sA  [N_EMBD];
__device__ float g_sM  [N_INNER];

// ========================= helpers (plain sm_100 only) =====================
__device__ __forceinline__ uint32_t smem_u32(const void* p) {
    uint32_t a;
    asm("{ .reg .u64 t; cvta.to.shared.u64 t, %1; cvt.u32.u64 %0, t; }"
        : "=r"(a) : "l"(p));
    return a;
}
#define CP16(d, s) \
    asm volatile("cp.async.cg.shared.global [%0], [%1], 16;" :: "r"(d), "l"(s))
__device__ __forceinline__ void cp_commit() {
    asm volatile("cp.async.commit_group;" ::: "memory");
}
template<int N> __device__ __forceinline__ void cp_wait() {
    asm volatile("cp.async.wait_group %0;" :: "n"(N) : "memory");
}
__device__ __forceinline__ void ldsm4(uint32_t& r0, uint32_t& r1,
                                      uint32_t& r2, uint32_t& r3, uint32_t addr) {
    asm volatile("ldmatrix.sync.aligned.m8n8.x4.shared.b16 {%0,%1,%2,%3}, [%4];"
                 : "=r"(r0), "=r"(r1), "=r"(r2), "=r"(r3) : "r"(addr));
}
__device__ __forceinline__ void ldsm4t(uint32_t& r0, uint32_t& r1,
                                       uint32_t& r2, uint32_t& r3, uint32_t addr) {
    asm volatile("ldmatrix.sync.aligned.m8n8.x4.trans.shared.b16 {%0,%1,%2,%3}, [%4];"
                 : "=r"(r0), "=r"(r1), "=r"(r2), "=r"(r3) : "r"(addr));
}
__device__ __forceinline__ void mma_bf16(float* c, const uint32_t* a,
                                         const uint32_t* b) {
    asm volatile(
        "mma.sync.aligned.m16n8k16.row.col.f32.bf16.bf16.f32 "
        "{%0,%1,%2,%3}, {%4,%5,%6,%7}, {%8,%9}, {%0,%1,%2,%3};"
        : "+f"(c[0]), "+f"(c[1]), "+f"(c[2]), "+f"(c[3])
        : "r"(a[0]), "r"(a[1]), "r"(a[2]), "r"(a[3]), "r"(b[0]), "r"(b[1]));
}
__device__ __forceinline__ float ex2f(float x) {
    float y;
    asm("ex2.approx.f32 %0, %1;" : "=f"(y) : "f"(x));
    return y;
}
__device__ __forceinline__ void split2(float x, bf16& h, bf16& l) {
    h = __float2bfloat16(x);
    l = __float2bfloat16(x - __bfloat162float(h));
}
__device__ __forceinline__ uint32_t packbf(float a, float b) {
    bf162 t = __floats2bfloat162_rn(a, b);
    return *(uint32_t*)&t;
}

// ======================= LayerNorm -> bf16 hi/lo ============================
__global__ __launch_bounds__(256) void ln_kernel(const float* __restrict__ x,
                                                 const float* __restrict__ g,
                                                 const float* __restrict__ b,
                                                 bf16* __restrict__ yh,
                                                 bf16* __restrict__ yl) {
    __shared__ float red[8];
    __shared__ float s_mean, s_rstd;
    const int row = blockIdx.x, tid = threadIdx.x;
    const float* xr = x + (size_t)row * N_EMBD;
    float v[8];
    float s = 0.f;
#pragma unroll
    for (int k = 0; k < 8; k++) { v[k] = xr[tid + k * 256]; s += v[k]; }
#pragma unroll
    for (int o = 16; o > 0; o >>= 1) s += __shfl_xor_sync(0xffffffffu, s, o);
    if ((tid & 31) == 0) red[tid >> 5] = s;
    __syncthreads();
    if (tid == 0) {
        float t = 0.f;
#pragma unroll
        for (int i = 0; i < 8; i++) t += red[i];
        s_mean = t * (1.f / N_EMBD);
    }
    __syncthreads();
    const float mu = s_mean;
    float vs = 0.f;
#pragma unroll
    for (int k = 0; k < 8; k++) { float d = v[k] - mu; vs += d * d; }
#pragma unroll
    for (int o = 16; o > 0; o >>= 1) vs += __shfl_xor_sync(0xffffffffu, vs, o);
    if ((tid & 31) == 0) red[tid >> 5] = vs;
    __syncthreads();
    if (tid == 0) {
        float t = 0.f;
#pragma unroll
        for (int i = 0; i < 8; i++) t += red[i];
        s_rstd = rsqrtf(t * (1.f / N_EMBD) + 1e-5f);
    }
    __syncthreads();
    const float rstd = s_rstd;
    bf16* yhr = yh + (size_t)row * N_EMBD;
    bf16* ylr = yl + (size_t)row * N_EMBD;
#pragma unroll
    for (int k = 0; k < 8; k++) {
        const int c = tid + k * 256;
        const float val = (v[k] - mu) * rstd * g[c] + b[c];
        bf16 h, l; split2(val, h, l);
        yhr[c] = h; ylr[c] = l;
    }
}

// ========== weight-norm column scales: s[j] = g[j] / ||v[:,j]||_2 ==========
__global__ __launch_bounds__(256) void colnorm_kernel(const float* __restrict__ v,
                                                      const float* __restrict__ g,
                                                      float* __restrict__ scale,
                                                      int rows, int cols) {
    __shared__ float red[8][32];
    const int lane = threadIdx.x & 31;
    const int r0   = threadIdx.x >> 5;
    const int j    = blockIdx.x * 32 + lane;
    float acc = 0.f;
    for (int r = r0; r < rows; r += 8) {
        float t = v[(size_t)r * cols + j];
        acc += t * t;
    }
    red[r0][lane] = acc;
    __syncthreads();
    if (r0 == 0) {
        float s = red[0][lane];
#pragma unroll
        for (int q = 1; q < 8; q++) s += red[q][lane];
        scale[j] = g[j] / sqrtf(s);
    }
}

// ========== weight conversion: fp32 (optionally * s[k]) -> bf16 hi/lo =======
__global__ __launch_bounds__(256) void convw_kernel(const float* __restrict__ w,
                                                    const float* __restrict__ s,
                                                    bf16* __restrict__ hi,
                                                    bf16* __restrict__ lo,
                                                    int K, size_t n4) {
    const size_t i = (size_t)blockIdx.x * 256 + threadIdx.x;
    if (i >= n4) return;
    float4 v = ((const float4*)w)[i];
    if (s) {
        const int k = (int)((i * 4) % (size_t)K);
        v.x *= s[k]; v.y *= s[k + 1]; v.z *= s[k + 2]; v.w *= s[k + 3];
    }
    bf16 h0, h1, h2, h3, l0, l1, l2, l3;
    split2(v.x, h0, l0); split2(v.y, h1, l1);
    split2(v.z, h2, l2); split2(v.w, h3, l3);
    bf162 ph0; ph0.x = h0; ph0.y = h1;
    bf162 ph1; ph1.x = h2; ph1.y = h3;
    bf162 pl0; pl0.x = l0; pl0.y = l1;
    bf162 pl1; pl1.x = l2; pl1.y = l3;
    bf162* H = (bf162*)(hi + i * 4);
    bf162* L = (bf162*)(lo + i * 4);
    H[0] = ph0; H[1] = ph1;
    L[0] = pl0; L[1] = pl1;
}

// ================= HMMA split-bf16 GEMM: C = A @ B^T + epilogue ============
#define CH_A_H 0
#define CH_A_L 10240
#define CH_B_H 20480
#define CH_B_L 30720
#define CHUNK_BYTES 40960
#define GEMM_SMEM (2 * CHUNK_BYTES)

__device__ __forceinline__ void load_chunk(const bf16* __restrict__ Ah,
                                           const bf16* __restrict__ Al,
                                           const bf16* __restrict__ Bh,
                                           const bf16* __restrict__ Bl,
                                           int m0, int n0, int k0, int K,
                                           uint32_t sbuf, int tid) {
#pragma unroll
    for (int q = 0; q < 2; q++) {
        const int c   = tid + q * 256;       // 0..511
        const int row = c >> 2;              // 0..127
        const int kp  = c & 3;               // 16B chunk within 64B row
        const uint32_t doff = (uint32_t)(row * 80 + kp * 16);
        const size_t ga = (size_t)(m0 + row) * K + k0 + kp * 8;
        const size_t gb = (size_t)(n0 + row) * K + k0 + kp * 8;
        CP16(sbuf + CH_A_H + doff, Ah + ga);
        CP16(sbuf + CH_A_L + doff, Al + ga);
        CP16(sbuf + CH_B_H + doff, Bh + gb);
        CP16(sbuf + CH_B_L + doff, Bl + gb);
    }
}

template<bool DOGELU, bool RES, bool WF32, bool WPAIR>
__global__ __launch_bounds__(256) void tgemm(const bf16* __restrict__ Ah,
                                             const bf16* __restrict__ Al,
                                             const bf16* __restrict__ Bh,
                                             const bf16* __restrict__ Bl,
                                             const float* __restrict__ bias,
                                             const float* __restrict__ res,
                                             float* __restrict__ C,
                                             bf16* __restrict__ Ch,
                                             bf16* __restrict__ Cl,
                                             int M, int N, int K) {
    extern __shared__ char sm[];
    const uint32_t sb = smem_u32(sm);
    const int tid  = threadIdx.x;
    const int lane = tid & 31;
    const int wid  = tid >> 5;
    const int warp_m = wid & 1;     // 0..1 -> 64-row half
    const int warp_n = wid >> 1;    // 0..3 -> 32-col slice
    const int m0 = blockIdx.y * 128;
    const int n0 = blockIdx.x * 128;

    float acc[4][4][4];
#pragma unroll
    for (int i = 0; i < 4; i++)
#pragma unroll
        for (int j = 0; j < 4; j++)
#pragma unroll
            for (int t = 0; t < 4; t++) acc[i][j][t] = 0.f;

    const uint32_t a_row  = (uint32_t)(warp_m * 64 + (lane & 15));
    const uint32_t a_koff = (uint32_t)((lane >> 4) * 8);
    const uint32_t b_row  = (uint32_t)(warp_n * 32 + ((lane >> 4) & 1) * 8 + (lane & 7));
    const uint32_t b_koff = (uint32_t)(((lane >> 3) & 1) * 8);

    const int nc = K / 32;
    load_chunk(Ah, Al, Bh, Bl, m0, n0, 0, K, sb, tid);
    cp_commit();

    for (int c = 0; c < nc; c++) {
        if (c + 1 < nc) {
            load_chunk(Ah, Al, Bh, Bl, m0, n0, (c + 1) * 32, K,
                       sb + (uint32_t)(((c + 1) & 1) * CHUNK_BYTES), tid);
            cp_commit();
            cp_wait<1>();
        } else {
            cp_wait<0>();
        }
        __syncthreads();

        const uint32_t st = sb + (uint32_t)((c & 1) * CHUNK_BYTES);
#pragma unroll
        for (int s = 0; s < 2; s++) {
            uint32_t ah[4][4], al[4][4], bh[4][2], bl[4][2];
#pragma unroll
            for (int i = 0; i < 4; i++) {
                const uint32_t off = (a_row + i * 16) * 80 + (s * 16 + a_koff) * 2;
                ldsm4(ah[i][0], ah[i][1], ah[i][2], ah[i][3], st + CH_A_H + off);
                ldsm4(al[i][0], al[i][1], al[i][2], al[i][3], st + CH_A_L + off);
            }
#pragma unroll
            for (int j2 = 0; j2 < 2; j2++) {
                const uint32_t off = (b_row + j2 * 16) * 80 + (s * 16 + b_koff) * 2;
                uint32_t t0, t1, t2, t3;
                ldsm4(t0, t1, t2, t3, st + CH_B_H + off);
                bh[2 * j2][0] = t0; bh[2 * j2][1] = t1;
                bh[2 * j2 + 1][0] = t2; bh[2 * j2 + 1][1] = t3;
                ldsm4(t0, t1, t2, t3, st + CH_B_L + off);
                bl[2 * j2][0] = t0; bl[2 * j2][1] = t1;
                bl[2 * j2 + 1][0] = t2; bl[2 * j2 + 1][1] = t3;
            }
#pragma unroll
            for (int i = 0; i < 4; i++)
#pragma unroll
                for (int j = 0; j < 4; j++) {
                    mma_bf16(acc[i][j], ah[i], bh[j]);
                    mma_bf16(acc[i][j], ah[i], bl[j]);
                    mma_bf16(acc[i][j], al[i], bh[j]);
                }
        }
        __syncthreads();
    }

    // ---------------- epilogue: direct register stores ----------------
    const int r_base = m0 + warp_m * 64 + (lane >> 2);
    const int c_base = n0 + warp_n * 32 + 2 * (lane & 3);
#pragma unroll
    for (int i = 0; i < 4; i++) {
#pragma unroll
        for (int j = 0; j < 4; j++) {
            const int col = c_base + j * 8;
            const float2 bi = *(const float2*)&bias[col];
#pragma unroll
            for (int half = 0; half < 2; half++) {
                const int row = r_base + i * 16 + half * 8;
                float2 v;
                v.x = acc[i][j][half * 2 + 0] + bi.x;
                v.y = acc[i][j][half * 2 + 1] + bi.y;
                if (DOGELU) {
                    v.x = 0.5f * v.x * (1.f + erff(v.x * 0.70710678118654752f));
                    v.y = 0.5f * v.y * (1.f + erff(v.y * 0.70710678118654752f));
                }
                if (RES) {
                    const float2 rv = *(const float2*)&res[(size_t)row * N + col];
                    v.x += rv.x; v.y += rv.y;
                }
                if (WF32) *(float2*)&C[(size_t)row * N + col] = v;
                if (WPAIR) {
                    bf16 h0, h1, l0, l1;
                    split2(v.x, h0, l0); split2(v.y, h1, l1);
                    bf162 ph; ph.x = h0; ph.y = h1;
                    bf162 pl; pl.x = l0; pl.y = l1;
                    *(bf162*)&Ch[(size_t)row * N + col] = ph;
                    *(bf162*)&Cl[(size_t)row * N + col] = pl;
                }
            }
        }
    }
}

// ============== HMMA split-bf16 flash attention =============================
// CTA: 64 queries x one head. 4 warps (128 thr), warp owns 16 query rows.
// Q/K/V read as bf16 hi/lo pairs from the QKV GEMM output.
// S = Q K^T via 3-term split MMA; online softmax in registers (ex2.approx);
// P reused in-register as A operand of PV; V via ldmatrix.trans (hi/lo, 3-term).
// emotion_bias dropped (softmax-invariant).
#define AT_ROWB 272          /* 136 bf16 per smem row */
#define SQH 0
#define SQL 17408
#define SKH 34816
#define SKL 52224
#define SVH 69632
#define SVL 87040
#define ATT_SMEM 104448
#define SOFTSC 0.1275174048f /* (1/sqrt(128)) * log2(e) */

__global__ __launch_bounds__(128) void attn_mma(const bf16* __restrict__ qh,
                                                const bf16* __restrict__ ql,
                                                bf16* __restrict__ oh,
                                                bf16* __restrict__ ol) {
    extern __shared__ char sm[];
    const uint32_t sb = smem_u32(sm);
    const int tid  = threadIdx.x;
    const int lane = tid & 31;
    const int wid  = tid >> 5;
    const int qb   = blockIdx.x * 64;
    const int h    = blockIdx.y;
    const int b    = blockIdx.z;
    const int q0   = wid * 16;

    // ---- load Q tile (hi+lo): 64 rows x 128 bf16 each ----
#pragma unroll
    for (int i = 0; i < 16; i++) {
        const int idx = tid + i * 128;         // 0..2047
        const int arr = idx >> 10;             // 0=hi 1=lo
        const int rem = idx & 1023;
        const int row = rem >> 4;
        const int seg = rem & 15;
        const bf16* src = (arr ? ql : qh) +
            (size_t)(b * SEQ + qb + row) * QKV_W + h * HEAD_DIM + seg * 8;
        CP16(sb + (arr ? SQL : SQH) + row * AT_ROWB + seg * 16, src);
    }
    cp_commit();

    // softmax state (per thread: 2 rows)
    float m0 = -1e30f, m1 = -1e30f, l0 = 0.f, l1 = 0.f;
    float O[16][4];
#pragma unroll
    for (int f = 0; f < 16; f++)
#pragma unroll
        for (int c = 0; c < 4; c++) O[f][c] = 0.f;

    const uint32_t a_off = (uint32_t)((q0 + (lane & 15)) * AT_ROWB + (lane >> 4) * 16);
    const uint32_t kb_row  = (uint32_t)(((lane >> 4) & 1) * 8 + (lane & 7));
    const uint32_t kb_koff = (uint32_t)(((lane >> 3) & 1) * 8);
    const uint32_t v_row   = (uint32_t)(((lane >> 3) & 1) * 8 + (lane & 7));
    const uint32_t v_doff  = (uint32_t)((lane >> 4) * 16);

    for (int kt = 0; kt < SEQ; kt += 64) {
        __syncthreads();   // protect smem K/V from overwrite
        // ---- load K,V tiles (hi+lo) ----
#pragma unroll
        for (int i = 0; i < 32; i++) {
            const int idx = tid + i * 128;     // 0..4095
            const int arr = idx >> 10;         // 0 Kh,1 Kl,2 Vh,3 Vl
            const int rem = idx & 1023;
            const int row = rem >> 4;
            const int seg = rem & 15;
            const size_t base = (size_t)(b * SEQ + kt + row) * QKV_W + h * HEAD_DIM +
                                ((arr >> 1) ? 2 * N_EMBD : N_EMBD) + seg * 8;
            const bf16* src = ((arr & 1) ? ql : qh) + base;
            CP16(sb + SKH + arr * 17408 + row * AT_ROWB + seg * 16, src);
        }
        cp_commit();
        cp_wait<0>();
        __syncthreads();

        // ---- S = Q K^T (scaled log2 domain) ----
        float s[8][4];
#pragma unroll
        for (int j = 0; j < 8; j++)
#pragma unroll
            for (int c = 0; c < 4; c++) s[j][c] = 0.f;

#pragma unroll
        for (int kd = 0; kd < 8; kd++) {       // d k-steps of 16
            uint32_t aH[4], aL[4];
            const uint32_t ao = a_off + kd * 32;
            ldsm4(aH[0], aH[1], aH[2], aH[3], sb + SQH + ao);
            ldsm4(aL[0], aL[1], aL[2], aL[3], sb + SQL + ao);
#pragma unroll
            for (int kg = 0; kg < 4; kg++) {   // key groups of 16
                const uint32_t bo = (kg * 16 + kb_row) * AT_ROWB + (kd * 16 + kb_koff) * 2;
                uint32_t t0, t1, t2, t3;
                uint32_t bh0[2], bh1[2], bl0[2], bl1[2];
                ldsm4(t0, t1, t2, t3, sb + SKH + bo);
                bh0[0] = t0; bh0[1] = t1; bh1[0] = t2; bh1[1] = t3;
                ldsm4(t0, t1, t2, t3, sb + SKL + bo);
                bl0[0] = t0; bl0[1] = t1; bl1[0] = t2; bl1[1] = t3;
                mma_bf16(s[2 * kg],     aH, bh0);
                mma_bf16(s[2 * kg],     aH, bl0);
                mma_bf16(s[2 * kg],     aL, bh0);
                mma_bf16(s[2 * kg + 1], aH, bh1);
                mma_bf16(s[2 * kg + 1], aH, bl1);
                mma_bf16(s[2 * kg + 1], aL, bh1);
            }
        }

        // ---- online softmax (registers) ----
        float mt0 = -1e30f, mt1 = -1e30f;
#pragma unroll
        for (int j = 0; j < 8; j++) {
#pragma unroll
            for (int c = 0; c < 4; c++) s[j][c] *= SOFTSC;
            mt0 = fmaxf(mt0, fmaxf(s[j][0], s[j][1]));
            mt1 = fmaxf(mt1, fmaxf(s[j][2], s[j][3]));
        }
        mt0 = fmaxf(mt0, __shfl_xor_sync(0xffffffffu, mt0, 1));
        mt0 = fmaxf(mt0, __shfl_xor_sync(0xffffffffu, mt0, 2));
        mt1 = fmaxf(mt1, __shfl_xor_sync(0xffffffffu, mt1, 1));
        mt1 = fmaxf(mt1, __shfl_xor_sync(0xffffffffu, mt1, 2));
        const float mn0 = fmaxf(m0, mt0), mn1 = fmaxf(m1, mt1);
        const float corr0 = ex2f(m0 - mn0), corr1 = ex2f(m1 - mn1);
        m0 = mn0; m1 = mn1;
        float ps0 = 0.f, ps1 = 0.f;
#pragma unroll
        for (int j = 0; j < 8; j++) {
            s[j][0] = ex2f(s[j][0] - mn0);
            s[j][1] = ex2f(s[j][1] - mn0);
            s[j][2] = ex2f(s[j][2] - mn1);
            s[j][3] = ex2f(s[j][3] - mn1);
            ps0 += s[j][0] + s[j][1];
            ps1 += s[j][2] + s[j][3];
        }
        l0 = l0 * corr0 + ps0;
        l1 = l1 * corr1 + ps1;
#pragma unroll
        for (int f = 0; f < 16; f++) {
            O[f][0] *= corr0; O[f][1] *= corr0;
            O[f][2] *= corr1; O[f][3] *= corr1;
        }

        // ---- O += P V (P from registers, V via ldmatrix.trans) ----
#pragma unroll
        for (int kk = 0; kk < 4; kk++) {       // key k-steps of 16
            const int j0 = 2 * kk, j1 = 2 * kk + 1;
            uint32_t pH[4], pL[4];
            {
                uint32_t hi;
                bf162 hv;
                float la, lb;
                hi = packbf(s[j0][0], s[j0][1]); hv = *(bf162*)&hi;
                la = s[j0][0] - __bfloat162float(hv.x);
                lb = s[j0][1] - __bfloat162float(hv.y);
                pH[0] = hi; pL[0] = packbf(la, lb);
                hi = packbf(s[j0][2], s[j0][3]); hv = *(bf162*)&hi;
                la = s[j0][2] - __bfloat162float(hv.x);
                lb = s[j0][3] - __bfloat162float(hv.y);
                pH[1] = hi; pL[1] = packbf(la, lb);
                hi = packbf(s[j1][0], s[j1][1]); hv = *(bf162*)&hi;
                la = s[j1][0] - __bfloat162float(hv.x);
                lb = s[j1][1] - __bfloat162float(hv.y);
                pH[2] = hi; pL[2] = packbf(la, lb);
                hi = packbf(s[j1][2], s[j1][3]); hv = *(bf162*)&hi;
                la = s[j1][2] - __bfloat162float(hv.x);
                lb = s[j1][3] - __bfloat162float(hv.y);
                pH[3] = hi; pL[3] = packbf(la, lb);
            }
#pragma unroll
            for (int g = 0; g < 8; g++) {      // d groups of 16
                const uint32_t vo = (kk * 16 + v_row) * AT_ROWB + (g * 16) * 2 + v_doff;
                uint32_t t0, t1, t2, t3;
                uint32_t bh0[2], bh1[2], bl0[2], bl1[2];
                ldsm4t(t0, t1, t2, t3, sb + SVH + vo);
                bh0[0] = t0; bh0[1] = t1; bh1[0] = t2; bh1[1] = t3;
                ldsm4t(t0, t1, t2, t3, sb + SVL + vo);
                bl0[0] = t0; bl0[1] = t1; bl1[0] = t2; bl1[1] = t3;
                mma_bf16(O[2 * g],     pH, bh0);
                mma_bf16(O[2 * g],     pH, bl0);
                mma_bf16(O[2 * g],     pL, bh0);
                mma_bf16(O[2 * g + 1], pH, bh1);
                mma_bf16(O[2 * g + 1], pH, bl1);
                mma_bf16(O[2 * g + 1], pL, bh1);
            }
        }
    }

    // ---- finalize: normalize, split, store ----
    l0 += __shfl_xor_sync(0xffffffffu, l0, 1);
    l0 += __shfl_xor_sync(0xffffffffu, l0, 2);
    l1 += __shfl_xor_sync(0xffffffffu, l1, 1);
    l1 += __shfl_xor_sync(0xffffffffu, l1, 2);
    const float inv0 = 1.f / l0, inv1 = 1.f / l1;
    const int r0g = qb + q0 + (lane >> 2);
    const int r1g = r0g + 8;
    const size_t base0 = ((size_t)b * SEQ + r0g) * N_EMBD + h * HEAD_DIM + 2 * (lane & 3);
    const size_t base1 = ((size_t)b * SEQ + r1g) * N_EMBD + h * HEAD_DIM + 2 * (lane & 3);
#pragma unroll
    for (int f = 0; f < 16; f++) {
        const int col = f * 8;
        float vx = O[f][0] * inv0, vy = O[f][1] * inv0;
        bf16 h0, h1, lo0, lo1;
        split2(vx, h0, lo0); split2(vy, h1, lo1);
        bf162 ph; ph.x = h0; ph.y = h1;
        bf162 pl; pl.x = lo0; pl.y = lo1;
        *(bf162*)&oh[base0 + col] = ph;
        *(bf162*)&ol[base0 + col] = pl;
        vx = O[f][2] * inv1; vy = O[f][3] * inv1;
        split2(vx, h0, lo0); split2(vy, h1, lo1);
        ph.x = h0; ph.y = h1;
        pl.x = lo0; pl.y = lo1;
        *(bf162*)&oh[base1 + col] = ph;
        *(bf162*)&ol[base1 + col] = pl;
    }
}

// =========================== launch sequence ===============================
extern "C" void kernel_launch(void* const* d_in, const int* in_sizes, int n_in,
                              void* d_out, int out_size) {
    const float* hs      = (const float*)d_in[0];
    const float* ln1_g   = (const float*)d_in[1];
    const float* ln1_b   = (const float*)d_in[2];
    const float* w_qkv   = (const float*)d_in[3];
    const float* b_qkv   = (const float*)d_in[4];
    const float* attn_v  = (const float*)d_in[5];
    const float* attn_g  = (const float*)d_in[6];
    const float* attn_b  = (const float*)d_in[7];
    /* d_in[8] = emotion_bias: softmax-invariant, unused */
    const float* ln2_g   = (const float*)d_in[9];
    const float* ln2_b   = (const float*)d_in[10];
    const float* w_fc    = (const float*)d_in[11];
    const float* b_fc    = (const float*)d_in[12];
    const float* mlp_v   = (const float*)d_in[13];
    const float* mlp_g   = (const float*)d_in[14];
    const float* mlp_b   = (const float*)d_in[15];
    float* out = (float*)d_out;

    float *hid, *sA, *sM;
    bf16 *qh, *ql, *xh, *xl, *ah, *al, *fh, *fl;
    bf16 *wqkvh, *wqkvl, *wph, *wpl, *wfh, *wfl, *wmh, *wml;
    cudaGetSymbolAddress((void**)&hid,   g_hid);
    cudaGetSymbolAddress((void**)&sA,    g_sA);
    cudaGetSymbolAddress((void**)&sM,    g_sM);
    cudaGetSymbolAddress((void**)&qh,    g_qh);
    cudaGetSymbolAddress((void**)&ql,    g_ql);
    cudaGetSymbolAddress((void**)&xh,    g_xh);
    cudaGetSymbolAddress((void**)&xl,    g_xl);
    cudaGetSymbolAddress((void**)&ah,    g_ah);
    cudaGetSymbolAddress((void**)&al,    g_al);
    cudaGetSymbolAddress((void**)&fh,    g_fh);
    cudaGetSymbolAddress((void**)&fl,    g_fl);
    cudaGetSymbolAddress((void**)&wqkvh, g_wqkvh);
    cudaGetSymbolAddress((void**)&wqkvl, g_wqkvl);
    cudaGetSymbolAddress((void**)&wph,   g_wph);
    cudaGetSymbolAddress((void**)&wpl,   g_wpl);
    cudaGetSymbolAddress((void**)&wfh,   g_wfh);
    cudaGetSymbolAddress((void**)&wfl,   g_wfl);
    cudaGetSymbolAddress((void**)&wmh,   g_wmh);
    cudaGetSymbolAddress((void**)&wml,   g_wml);

    cudaFuncSetAttribute(attn_mma,
                         cudaFuncAttributeMaxDynamicSharedMemorySize, ATT_SMEM);
    cudaFuncSetAttribute(tgemm<false, false, false, true>,
                         cudaFuncAttributeMaxDynamicSharedMemorySize, GEMM_SMEM);
    cudaFuncSetAttribute(tgemm<false, true, true, false>,
                         cudaFuncAttributeMaxDynamicSharedMemorySize, GEMM_SMEM);
    cudaFuncSetAttribute(tgemm<true, false, false, true>,
                         cudaFuncAttributeMaxDynamicSharedMemorySize, GEMM_SMEM);

    // launch order arranged so ncu (-s 5 -c 1) profiles the QKV GEMM (#5)
    // 0,1: weight-norm column scales
    colnorm_kernel<<<N_EMBD / 32, 256>>>(attn_v, attn_g, sA, N_EMBD, N_EMBD);
    colnorm_kernel<<<N_INNER / 32, 256>>>(mlp_v, mlp_g, sM, N_EMBD, N_INNER);

    // 2: LN1 -> bf16 hi/lo
    ln_kernel<<<ROWS, 256>>>(hs, ln1_g, ln1_b, xh, xl);

    // 3,4: weight conversions needed before QKV GEMM
    size_t n4;
    n4 = (size_t)QKV_W * N_EMBD / 4;
    convw_kernel<<<(unsigned)((n4 + 255) / 256), 256>>>(w_qkv, nullptr, wqkvh, wqkvl, N_EMBD, n4);
    n4 = (size_t)N_INNER * N_EMBD / 4;
    convw_kernel<<<(unsigned)((n4 + 255) / 256), 256>>>(w_fc, nullptr, wfh, wfl, N_EMBD, n4);

    // 5: QKV GEMM [4096,6144] K=2048 -> bf16 hi/lo pairs  (ncu target)
    tgemm<false, false, false, true><<<dim3(QKV_W / 128, ROWS / 128), 256, GEMM_SMEM>>>(
        xh, xl, wqkvh, wqkvl, b_qkv, nullptr, nullptr, qh, ql,
        ROWS, QKV_W, N_EMBD);

    // 6,7: remaining weight conversions (wn scales folded)
    n4 = (size_t)N_EMBD * N_EMBD / 4;
    convw_kernel<<<(unsigned)((n4 + 255) / 256), 256>>>(attn_v, sA, wph, wpl, N_EMBD, n4);
    n4 = (size_t)N_EMBD * N_INNER / 4;
    convw_kernel<<<(unsigned)((n4 + 255) / 256), 256>>>(mlp_v, sM, wmh, wml, N_INNER, n4);

    // 8: flash attention (split-bf16 HMMA) -> bf16 hi/lo
    attn_mma<<<dim3(SEQ / 64, N_HEAD, BATCH), 128, ATT_SMEM>>>(qh, ql, ah, al);

    // 9: attn proj + residual(hs) -> hid fp32
    tgemm<false, true, true, false><<<dim3(N_EMBD / 128, ROWS / 128), 256, GEMM_SMEM>>>(
        ah, al, wph, wpl, attn_b, hs, hid, nullptr, nullptr,
        ROWS, N_EMBD, N_EMBD);

    // 10: LN2 -> bf16 hi/lo
    ln_kernel<<<ROWS, 256>>>(hid, ln2_g, ln2_b, xh, xl);

    // 11: FC + GELU [4096,8192] K=2048 -> bf16 hi/lo
    tgemm<true, false, false, true><<<dim3(N_INNER / 128, ROWS / 128), 256, GEMM_SMEM>>>(
        xh, xl, wfh, wfl, b_fc, nullptr, nullptr, fh, fl,
        ROWS, N_INNER, N_EMBD);

    // 12: MLP proj + residual(hid) -> out fp32, K=8192
    tgemm<false, true, true, false><<<dim3(N_EMBD / 128, ROWS / 128), 256, GEMM_SMEM>>>(
        fh, fl, wmh, wml, mlp_b, hid, out, nullptr, nullptr,
        ROWS, N_EMBD, N_INNER);
}

// round 10
// speedup vs baseline: 3.6375x; 1.2300x over previous
#include <cuda_runtime.h>
#include <cuda_bf16.h>
#include <math.h>
#include <stdint.h>

// ---------------- problem constants ----------------
#define N_EMBD   2048
#define N_HEAD   16
#define HEAD_DIM 128
#define N_INNER  8192
#define SEQ      2048
#define BATCH    2
#define ROWS     (BATCH*SEQ)     /* 4096 */
#define QKV_W    (3*N_EMBD)      /* 6144 */

typedef __nv_bfloat16 bf16;
typedef __nv_bfloat162 bf162;

// ---------------- scratch (device globals; no allocs allowed) --------------
// TB layout: [rowblk128][kchunk32] blocks of 16KB; row=128B=[hi 64B|lo 64B],
//   unit u (16B) at phys r*128 + ((u ^ (r&7))<<4)  (u 0..3 hi, 4..7 lo)
// AB layout (attention): [type][b][h][seqblk64] blocks of 32KB; row=512B,
//   unit u at phys r*512 + ((u ^ (r&7))<<4)  (u 0..15 hi, 16..31 lo)
__device__ __align__(256) bf16  g_x  [(size_t)ROWS * N_EMBD * 2];
__device__ __align__(256) bf16  g_f  [(size_t)ROWS * N_INNER * 2];
__device__ __align__(256) bf16  g_a  [(size_t)ROWS * N_EMBD * 2];
__device__ __align__(256) bf16  g_qt [(size_t)3 * BATCH * N_HEAD * 32 * 16384];
__device__ __align__(256) bf16  g_wq [(size_t)QKV_W * N_EMBD * 2];
__device__ __align__(256) bf16  g_wp [(size_t)N_EMBD * N_EMBD * 2];
__device__ __align__(256) bf16  g_wf [(size_t)N_INNER * N_EMBD * 2];
__device__ __align__(256) bf16  g_wm [(size_t)N_EMBD * N_INNER * 2];
__device__ float g_hid[(size_t)ROWS * N_EMBD];
__device__ float g_sA [N_EMBD];
__device__ float g_sM [N_INNER];

// ========================= helpers =========================================
__device__ __forceinline__ uint32_t smem_u32(const void* p) {
    uint32_t a;
    asm("{ .reg .u64 t; cvta.to.shared.u64 t, %1; cvt.u32.u64 %0, t; }"
        : "=r"(a) : "l"(p));
    return a;
}
__device__ __forceinline__ uint32_t tb_off(int r, int u) {
    return (uint32_t)(r * 128 + ((u ^ (r & 7)) << 4));
}
__device__ __forceinline__ uint32_t ab_off(int r, int u) {
    return (uint32_t)(r * 512 + ((u ^ (r & 7)) << 4));
}
__device__ __forceinline__ void mbar_init(uint32_t m, uint32_t cnt) {
    asm volatile("mbarrier.init.shared.b64 [%0], %1;" :: "r"(m), "r"(cnt) : "memory");
}
__device__ __forceinline__ void mbar_expect(uint32_t m, uint32_t bytes) {
    asm volatile("mbarrier.arrive.expect_tx.shared.b64 _, [%0], %1;"
                 :: "r"(m), "r"(bytes) : "memory");
}
__device__ __forceinline__ void mbar_wait(uint32_t m, uint32_t parity) {
    asm volatile(
        "{\n\t.reg .pred P;\n\t"
        "W_%=:\n\t"
        "mbarrier.try_wait.parity.shared.b64 P, [%0], %1;\n\t"
        "@!P bra W_%=;\n\t}"
        :: "r"(m), "r"(parity) : "memory");
}
__device__ __forceinline__ void bulk_g2s(uint32_t dst, const void* src,
                                         uint32_t bytes, uint32_t mbar) {
    asm volatile(
        "cp.async.bulk.shared::cluster.global.mbarrier::complete_tx::bytes "
        "[%0], [%1], %2, [%3];"
        :: "r"(dst), "l"(src), "r"(bytes), "r"(mbar) : "memory");
}
__device__ __forceinline__ void ldsm4(uint32_t& r0, uint32_t& r1,
                                      uint32_t& r2, uint32_t& r3, uint32_t addr) {
    asm volatile("ldmatrix.sync.aligned.m8n8.x4.shared.b16 {%0,%1,%2,%3}, [%4];"
                 : "=r"(r0), "=r"(r1), "=r"(r2), "=r"(r3) : "r"(addr));
}
__device__ __forceinline__ void ldsm4t(uint32_t& r0, uint32_t& r1,
                                       uint32_t& r2, uint32_t& r3, uint32_t addr) {
    asm volatile("ldmatrix.sync.aligned.m8n8.x4.trans.shared.b16 {%0,%1,%2,%3}, [%4];"
                 : "=r"(r0), "=r"(r1), "=r"(r2), "=r"(r3) : "r"(addr));
}
__device__ __forceinline__ void mma_bf16(float* c, const uint32_t* a,
                                         const uint32_t* b) {
    asm volatile(
        "mma.sync.aligned.m16n8k16.row.col.f32.bf16.bf16.f32 "
        "{%0,%1,%2,%3}, {%4,%5,%6,%7}, {%8,%9}, {%0,%1,%2,%3};"
        : "+f"(c[0]), "+f"(c[1]), "+f"(c[2]), "+f"(c[3])
        : "r"(a[0]), "r"(a[1]), "r"(a[2]), "r"(a[3]), "r"(b[0]), "r"(b[1]));
}
__device__ __forceinline__ float ex2f(float x) {
    float y;
    asm("ex2.approx.f32 %0, %1;" : "=f"(y) : "f"(x));
    return y;
}
__device__ __forceinline__ void split2(float x, bf16& h, bf16& l) {
    h = __float2bfloat16(x);
    l = __float2bfloat16(x - __bfloat162float(h));
}
__device__ __forceinline__ uint32_t packbf(float a, float b) {
    bf162 t = __floats2bfloat162_rn(a, b);
    return *(uint32_t*)&t;
}
__device__ __forceinline__ uint32_t pack2(bf16 a, bf16 b) {
    bf162 t; t.x = a; t.y = b;
    return *(uint32_t*)&t;
}

// ======================= LayerNorm -> TB layout ============================
__global__ __launch_bounds__(256) void ln_kernel(const float* __restrict__ x,
                                                 const float* __restrict__ g,
                                                 const float* __restrict__ bp,
                                                 bf16* __restrict__ yt) {
    __shared__ float red[8];
    __shared__ float s_mean, s_rstd;
    const int row = blockIdx.x, t = threadIdx.x;
    const float* xr = x + (size_t)row * N_EMBD + t * 8;
    float v[8];
    *(float4*)&v[0] = *(const float4*)&xr[0];
    *(float4*)&v[4] = *(const float4*)&xr[4];
    float s = v[0] + v[1] + v[2] + v[3] + v[4] + v[5] + v[6] + v[7];
#pragma unroll
    for (int o = 16; o > 0; o >>= 1) s += __shfl_xor_sync(0xffffffffu, s, o);
    if ((t & 31) == 0) red[t >> 5] = s;
    __syncthreads();
    if (t == 0) {
        float tt = 0.f;
#pragma unroll
        for (int i = 0; i < 8; i++) tt += red[i];
        s_mean = tt * (1.f / N_EMBD);
    }
    __syncthreads();
    const float mu = s_mean;
    float vs = 0.f;
#pragma unroll
    for (int k = 0; k < 8; k++) { float d = v[k] - mu; vs += d * d; }
#pragma unroll
    for (int o = 16; o > 0; o >>= 1) vs += __shfl_xor_sync(0xffffffffu, vs, o);
    if ((t & 31) == 0) red[t >> 5] = vs;
    __syncthreads();
    if (t == 0) {
        float tt = 0.f;
#pragma unroll
        for (int i = 0; i < 8; i++) tt += red[i];
        s_rstd = rsqrtf(tt * (1.f / N_EMBD) + 1e-5f);
    }
    __syncthreads();
    const float rstd = s_rstd;
    float gg[8], bb[8];
    *(float4*)&gg[0] = *(const float4*)&g[t * 8];
    *(float4*)&gg[4] = *(const float4*)&g[t * 8 + 4];
    *(float4*)&bb[0] = *(const float4*)&bp[t * 8];
    *(float4*)&bb[4] = *(const float4*)&bp[t * 8 + 4];
    bf16 hi[8], lo[8];
#pragma unroll
    for (int k = 0; k < 8; k++) {
        const float val = (v[k] - mu) * rstd * gg[k] + bb[k];
        split2(val, hi[k], lo[k]);
    }
    uint4 H, L;
    H.x = pack2(hi[0], hi[1]); H.y = pack2(hi[2], hi[3]);
    H.z = pack2(hi[4], hi[5]); H.w = pack2(hi[6], hi[7]);
    L.x = pack2(lo[0], lo[1]); L.y = pack2(lo[2], lo[3]);
    L.z = pack2(lo[4], lo[5]); L.w = pack2(lo[6], lo[7]);
    const int mblk = row >> 7, rl = row & 127, c = t >> 2, su = t & 3;
    char* base = (char*)yt + (((size_t)(mblk * 64 + c)) << 14);
    *(uint4*)(base + tb_off(rl, su))     = H;
    *(uint4*)(base + tb_off(rl, su + 4)) = L;
}

// ========== weight-norm column scales ======================================
__global__ __launch_bounds__(256) void colnorm_kernel(const float* __restrict__ v,
                                                      const float* __restrict__ g,
                                                      float* __restrict__ scale,
                                                      int rows, int cols) {
    __shared__ float red[8][32];
    const int lane = threadIdx.x & 31;
    const int r0   = threadIdx.x >> 5;
    const int j    = blockIdx.x * 32 + lane;
    float acc = 0.f;
    for (int r = r0; r < rows; r += 8) {
        float t = v[(size_t)r * cols + j];
        acc += t * t;
    }
    red[r0][lane] = acc;
    __syncthreads();
    if (r0 == 0) {
        float s = red[0][lane];
#pragma unroll
        for (int q = 1; q < 8; q++) s += red[q][lane];
        scale[j] = g[j] / sqrtf(s);
    }
}

// ========== weight conversion: fp32 (* s[k]) -> TB layout ==================
// grid (K/2048, N): thread handles 8 consecutive k of one output row n.
__global__ __launch_bounds__(256) void convw_kernel(const float* __restrict__ w,
                                                    const float* __restrict__ s,
                                                    bf16* __restrict__ out,
                                                    int N, int K) {
    const int n  = blockIdx.y;
    const int kg = blockIdx.x * 256 + threadIdx.x;
    const int k0 = kg * 8;
    float v[8];
    *(float4*)&v[0] = *(const float4*)&w[(size_t)n * K + k0];
    *(float4*)&v[4] = *(const float4*)&w[(size_t)n * K + k0 + 4];
    if (s) {
#pragma unroll
        for (int k = 0; k < 8; k++) v[k] *= s[k0 + k];
    }
    bf16 hi[8], lo[8];
#pragma unroll
    for (int k = 0; k < 8; k++) split2(v[k], hi[k], lo[k]);
    uint4 H, L;
    H.x = pack2(hi[0], hi[1]); H.y = pack2(hi[2], hi[3]);
    H.z = pack2(hi[4], hi[5]); H.w = pack2(hi[6], hi[7]);
    L.x = pack2(lo[0], lo[1]); L.y = pack2(lo[2], lo[3]);
    L.z = pack2(lo[4], lo[5]); L.w = pack2(lo[6], lo[7]);
    const int nblk = n >> 7, r = n & 127, c = kg >> 2, su = kg & 3;
    char* base = (char*)out + (((size_t)(nblk * (K >> 5) + c)) << 14);
    *(uint4*)(base + tb_off(r, su))     = H;
    *(uint4*)(base + tb_off(r, su + 4)) = L;
}

// ================= HMMA split-bf16 GEMM, bulk-copy pipeline ================
// Tile 256x128, 8 warps (warp 64x64), 3-stage mbarrier pipeline.
// Stage: A 32KB (two 16KB TB blocks) + B 16KB = 48KB.
#define GSOFF 1024
#define GSTG  49152
#define GEMM_SMEM (GSOFF + 3 * GSTG)

template<bool DOGELU, bool RES, bool WF32, bool WTB, bool WQKV>
__global__ __launch_bounds__(256) void tgemm(const bf16* __restrict__ A,
                                             const bf16* __restrict__ B,
                                             const float* __restrict__ bias,
                                             const float* __restrict__ res,
                                             float* __restrict__ C,
                                             bf16* __restrict__ T,
                                             int M, int N, int K) {
    extern __shared__ char sm[];
    const uint32_t sb = smem_u32(sm);
    const int tid  = threadIdx.x;
    const int lane = tid & 31;
    const int wid  = tid >> 5;
    const int warp_m = wid >> 1;    // 0..3
    const int warp_n = wid & 1;     // 0..1
    const int m0 = blockIdx.y * 256;
    const int n0 = blockIdx.x * 128;
    const int nc = K >> 5;
    const int lm = lane & 15, lq = lane >> 4, l8 = (lane >> 3) & 1, l7 = lane & 7;
    const char* Ab = (const char*)A;
    const char* Bb = (const char*)B;
    const int amb = blockIdx.y * 2;

    if (tid == 0) {
#pragma unroll
        for (int s = 0; s < 3; s++) mbar_init(sb + s * 8, 1);
    }
    __syncthreads();
    if (tid == 0) {
#pragma unroll
        for (int s = 0; s < 3; s++) {
            const uint32_t mb = sb + s * 8;
            const uint32_t st = sb + GSOFF + s * GSTG;
            mbar_expect(mb, 49152);
            bulk_g2s(st,         Ab + (((size_t)((amb + 0) * nc + s)) << 14), 16384, mb);
            bulk_g2s(st + 16384, Ab + (((size_t)((amb + 1) * nc + s)) << 14), 16384, mb);
            bulk_g2s(st + 32768, Bb + (((size_t)(blockIdx.x * nc + s)) << 14), 16384, mb);
        }
    }

    float acc[4][8][4];
#pragma unroll
    for (int i = 0; i < 4; i++)
#pragma unroll
        for (int j = 0; j < 8; j++)
#pragma unroll
            for (int t = 0; t < 4; t++) acc[i][j][t] = 0.f;

    for (int c = 0; c < nc; c++) {
        const int slot = c % 3;
        mbar_wait(sb + slot * 8, (c / 3) & 1);
        const uint32_t st = sb + GSOFF + slot * GSTG;
#pragma unroll
        for (int s = 0; s < 2; s++) {
            uint32_t aH[4][4], aL[4][4], bH[8][2], bL[8][2];
#pragma unroll
            for (int i = 0; i < 4; i++) {
                const int r = warp_m * 64 + lm + i * 16;
                const uint32_t bb_ = st + ((uint32_t)(r >> 7) << 14);
                const int rl = r & 127;
                ldsm4(aH[i][0], aH[i][1], aH[i][2], aH[i][3],
                      bb_ + tb_off(rl, s * 2 + lq));
                ldsm4(aL[i][0], aL[i][1], aL[i][2], aL[i][3],
                      bb_ + tb_off(rl, s * 2 + lq + 4));
            }
#pragma unroll
            for (int j2 = 0; j2 < 4; j2++) {
                const int r = warp_n * 64 + j2 * 16 + lq * 8 + l7;
                uint32_t t0, t1, t2, t3;
                ldsm4(t0, t1, t2, t3, st + 32768 + tb_off(r, s * 2 + l8));
                bH[2 * j2][0] = t0; bH[2 * j2][1] = t1;
                bH[2 * j2 + 1][0] = t2; bH[2 * j2 + 1][1] = t3;
                ldsm4(t0, t1, t2, t3, st + 32768 + tb_off(r, s * 2 + l8 + 4));
                bL[2 * j2][0] = t0; bL[2 * j2][1] = t1;
                bL[2 * j2 + 1][0] = t2; bL[2 * j2 + 1][1] = t3;
            }
#pragma unroll
            for (int i = 0; i < 4; i++)
#pragma unroll
                for (int j = 0; j < 8; j++) {
                    mma_bf16(acc[i][j], aH[i], bH[j]);
                    mma_bf16(acc[i][j], aH[i], bL[j]);
                    mma_bf16(acc[i][j], aL[i], bH[j]);
                }
        }
        __syncthreads();
        if (c + 3 < nc && tid == 0) {
            const uint32_t mb = sb + slot * 8;
            mbar_expect(mb, 49152);
            bulk_g2s(st,         Ab + (((size_t)((amb + 0) * nc + c + 3)) << 14), 16384, mb);
            bulk_g2s(st + 16384, Ab + (((size_t)((amb + 1) * nc + c + 3)) << 14), 16384, mb);
            bulk_g2s(st + 32768, Bb + (((size_t)(blockIdx.x * nc + c + 3)) << 14), 16384, mb);
        }
    }

    // ---------------- epilogue ----------------
    const int r_base = m0 + warp_m * 64 + (lane >> 2);
    const int c_base = n0 + warp_n * 64 + 2 * (lane & 3);
#pragma unroll
    for (int i = 0; i < 4; i++) {
#pragma unroll
        for (int j = 0; j < 8; j++) {
            const int col = c_base + j * 8;
            const float2 bi = *(const float2*)&bias[col];
#pragma unroll
            for (int half = 0; half < 2; half++) {
                const int row = r_base + i * 16 + half * 8;
                float vx = acc[i][j][half * 2 + 0] + bi.x;
                float vy = acc[i][j][half * 2 + 1] + bi.y;
                if (DOGELU) {
                    vx = 0.5f * vx * (1.f + erff(vx * 0.70710678118654752f));
                    vy = 0.5f * vy * (1.f + erff(vy * 0.70710678118654752f));
                }
                if (RES) {
                    const float2 rv = *(const float2*)&res[(size_t)row * N + col];
                    vx += rv.x; vy += rv.y;
                }
                if (WF32) {
                    float2 o; o.x = vx; o.y = vy;
                    *(float2*)&C[(size_t)row * N + col] = o;
                }
                if (WTB) {
                    bf16 h0, h1, l0, l1;
                    split2(vx, h0, l0); split2(vy, h1, l1);
                    bf162 ph; ph.x = h0; ph.y = h1;
                    bf162 pl; pl.x = l0; pl.y = l1;
                    const int mblk = row >> 7, rl = row & 127;
                    const int cc = col >> 5, u = (col & 31) >> 3, bo = (col & 7) * 2;
                    char* base = (char*)T + (((size_t)(mblk * (N >> 5) + cc)) << 14);
                    *(bf162*)(base + tb_off(rl, u) + bo)     = ph;
                    *(bf162*)(base + tb_off(rl, u + 4) + bo) = pl;
                }
                if (WQKV) {
                    bf16 h0, h1, l0, l1;
                    split2(vx, h0, l0); split2(vy, h1, l1);
                    bf162 ph; ph.x = h0; ph.y = h1;
                    bf162 pl; pl.x = l0; pl.y = l1;
                    const int type = col >> 11, hh = (col >> 7) & 15;
                    const int bb2 = row >> 11, seq = row & 2047;
                    const int sblk = seq >> 6, rl = seq & 63;
                    const int d = col & 127, u = d >> 3, bo = (d & 7) * 2;
                    char* base = (char*)T +
                        (((size_t)((((type * 2 + bb2) * 16 + hh) * 32) + sblk)) << 15);
                    *(bf162*)(base + ab_off(rl, u) + bo)      = ph;
                    *(bf162*)(base + ab_off(rl, u + 16) + bo) = pl;
                }
            }
        }
    }
}

// ============== HMMA split-bf16 flash attention (bulk loads) ===============
// CTA: 64 queries x one head, 4 warps. Q/K/V in AB layout (32KB blocks).
// smem: Q 32KB @1024; KV 2 stages x 64KB. Output -> TB layout (attn-proj A).
#define ASQ   1024
#define ASKV  (1024 + 32768)
#define ASTG  65536
#define ATT_SMEM (1024 + 32768 + 2 * 65536)
#define SOFTSC 0.1275174048f /* (1/sqrt(128)) * log2(e) */

__global__ __launch_bounds__(128) void attn_mma(const bf16* __restrict__ qt,
                                                bf16* __restrict__ aout) {
    extern __shared__ char sm[];
    const uint32_t sb = smem_u32(sm);
    const int tid  = threadIdx.x;
    const int lane = tid & 31;
    const int wid  = tid >> 5;
    const int qb   = blockIdx.x * 64;
    const int h    = blockIdx.y;
    const int b    = blockIdx.z;
    const int q0   = wid * 16;
    const int lm = lane & 15, lq = lane >> 4, l8 = (lane >> 3) & 1, l7 = lane & 7;
    const char* qbase = (const char*)qt;

    auto blk = [&](int type, int sblk) -> const char* {
        return qbase + (((size_t)(((type * 2 + b) * 16 + h) * 32 + sblk)) << 15);
    };

    if (tid == 0) {
        mbar_init(sb + 0, 1);
        mbar_init(sb + 8, 1);
        mbar_init(sb + 16, 1);
    }
    __syncthreads();
    if (tid == 0) {
        mbar_expect(sb + 0, 32768);
        bulk_g2s(sb + ASQ, blk(0, qb >> 6), 32768, sb + 0);
        mbar_expect(sb + 8, 65536);
        bulk_g2s(sb + ASKV,          blk(1, 0), 32768, sb + 8);
        bulk_g2s(sb + ASKV + 32768,  blk(2, 0), 32768, sb + 8);
        mbar_expect(sb + 16, 65536);
        bulk_g2s(sb + ASKV + ASTG,          blk(1, 1), 32768, sb + 16);
        bulk_g2s(sb + ASKV + ASTG + 32768,  blk(2, 1), 32768, sb + 16);
    }

    float m0 = -1e30f, m1 = -1e30f, l0 = 0.f, l1 = 0.f;
    float O[16][4];
#pragma unroll
    for (int f = 0; f < 16; f++)
#pragma unroll
        for (int c = 0; c < 4; c++) O[f][c] = 0.f;

    mbar_wait(sb + 0, 0);   // Q ready

    for (int it = 0; it < 32; it++) {
        const int slot = it & 1;
        mbar_wait(sb + 8 + slot * 8, (it >> 1) & 1);
        const uint32_t kvb = sb + ASKV + slot * ASTG;

        // ---- S = Q K^T (3-term split, log2 domain) ----
        float s[8][4];
#pragma unroll
        for (int j = 0; j < 8; j++)
#pragma unroll
            for (int c = 0; c < 4; c++) s[j][c] = 0.f;

#pragma unroll
        for (int kd = 0; kd < 8; kd++) {
            uint32_t aH[4], aL[4];
            const int qr = q0 + lm;
            ldsm4(aH[0], aH[1], aH[2], aH[3], sb + ASQ + ab_off(qr, kd * 2 + lq));
            ldsm4(aL[0], aL[1], aL[2], aL[3], sb + ASQ + ab_off(qr, kd * 2 + lq + 16));
#pragma unroll
            for (int kg = 0; kg < 4; kg++) {
                const int kr = kg * 16 + lq * 8 + l7;
                uint32_t t0, t1, t2, t3;
                uint32_t bh0[2], bh1[2], bl0[2], bl1[2];
                ldsm4(t0, t1, t2, t3, kvb + ab_off(kr, kd * 2 + l8));
                bh0[0] = t0; bh0[1] = t1; bh1[0] = t2; bh1[1] = t3;
                ldsm4(t0, t1, t2, t3, kvb + ab_off(kr, kd * 2 + l8 + 16));
                bl0[0] = t0; bl0[1] = t1; bl1[0] = t2; bl1[1] = t3;
                mma_bf16(s[2 * kg],     aH, bh0);
                mma_bf16(s[2 * kg],     aH, bl0);
                mma_bf16(s[2 * kg],     aL, bh0);
                mma_bf16(s[2 * kg + 1], aH, bh1);
                mma_bf16(s[2 * kg + 1], aH, bl1);
                mma_bf16(s[2 * kg + 1], aL, bh1);
            }
        }

        // ---- online softmax (registers) ----
        float mt0 = -1e30f, mt1 = -1e30f;
#pragma unroll
        for (int j = 0; j < 8; j++) {
#pragma unroll
            for (int c = 0; c < 4; c++) s[j][c] *= SOFTSC;
            mt0 = fmaxf(mt0, fmaxf(s[j][0], s[j][1]));
            mt1 = fmaxf(mt1, fmaxf(s[j][2], s[j][3]));
        }
        mt0 = fmaxf(mt0, __shfl_xor_sync(0xffffffffu, mt0, 1));
        mt0 = fmaxf(mt0, __shfl_xor_sync(0xffffffffu, mt0, 2));
        mt1 = fmaxf(mt1, __shfl_xor_sync(0xffffffffu, mt1, 1));
        mt1 = fmaxf(mt1, __shfl_xor_sync(0xffffffffu, mt1, 2));
        const float mn0 = fmaxf(m0, mt0), mn1 = fmaxf(m1, mt1);
        const float corr0 = ex2f(m0 - mn0), corr1 = ex2f(m1 - mn1);
        m0 = mn0; m1 = mn1;
        float ps0 = 0.f, ps1 = 0.f;
#pragma unroll
        for (int j = 0; j < 8; j++) {
            s[j][0] = ex2f(s[j][0] - mn0);
            s[j][1] = ex2f(s[j][1] - mn0);
            s[j][2] = ex2f(s[j][2] - mn1);
            s[j][3] = ex2f(s[j][3] - mn1);
            ps0 += s[j][0] + s[j][1];
            ps1 += s[j][2] + s[j][3];
        }
        l0 = l0 * corr0 + ps0;
        l1 = l1 * corr1 + ps1;
#pragma unroll
        for (int f = 0; f < 16; f++) {
            O[f][0] *= corr0; O[f][1] *= corr0;
            O[f][2] *= corr1; O[f][3] *= corr1;
        }

        // ---- O += P V ----
#pragma unroll
        for (int kk = 0; kk < 4; kk++) {
            const int j0 = 2 * kk, j1 = 2 * kk + 1;
            uint32_t pH[4], pL[4];
            {
                uint32_t hi;
                bf162 hv;
                float la, lb;
                hi = packbf(s[j0][0], s[j0][1]); hv = *(bf162*)&hi;
                la = s[j0][0] - __bfloat162float(hv.x);
                lb = s[j0][1] - __bfloat162float(hv.y);
                pH[0] = hi; pL[0] = packbf(la, lb);
                hi = packbf(s[j0][2], s[j0][3]); hv = *(bf162*)&hi;
                la = s[j0][2] - __bfloat162float(hv.x);
                lb = s[j0][3] - __bfloat162float(hv.y);
                pH[1] = hi; pL[1] = packbf(la, lb);
                hi = packbf(s[j1][0], s[j1][1]); hv = *(bf162*)&hi;
                la = s[j1][0] - __bfloat162float(hv.x);
                lb = s[j1][1] - __bfloat162float(hv.y);
                pH[2] = hi; pL[2] = packbf(la, lb);
                hi = packbf(s[j1][2], s[j1][3]); hv = *(bf162*)&hi;
                la = s[j1][2] - __bfloat162float(hv.x);
                lb = s[j1][3] - __bfloat162float(hv.y);
                pH[3] = hi; pL[3] = packbf(la, lb);
            }
#pragma unroll
            for (int g = 0; g < 8; g++) {
                const int vr = kk * 16 + l8 * 8 + l7;
                uint32_t t0, t1, t2, t3;
                uint32_t bh0[2], bh1[2], bl0[2], bl1[2];
                ldsm4t(t0, t1, t2, t3, kvb + 32768 + ab_off(vr, g * 2 + lq));
                bh0[0] = t0; bh0[1] = t1; bh1[0] = t2; bh1[1] = t3;
                ldsm4t(t0, t1, t2, t3, kvb + 32768 + ab_off(vr, g * 2 + lq + 16));
                bl0[0] = t0; bl0[1] = t1; bl1[0] = t2; bl1[1] = t3;
                mma_bf16(O[2 * g],     pH, bh0);
                mma_bf16(O[2 * g],     pH, bl0);
                mma_bf16(O[2 * g],     pL, bh0);
                mma_bf16(O[2 * g + 1], pH, bh1);
                mma_bf16(O[2 * g + 1], pH, bl1);
                mma_bf16(O[2 * g + 1], pL, bh1);
            }
        }
        __syncthreads();
        if (it + 2 < 32 && tid == 0) {
            const uint32_t mb = sb + 8 + slot * 8;
            const uint32_t dst = sb + ASKV + slot * ASTG;
            mbar_expect(mb, 65536);
            bulk_g2s(dst,         blk(1, it + 2), 32768, mb);
            bulk_g2s(dst + 32768, blk(2, it + 2), 32768, mb);
        }
    }

    // ---- finalize: normalize, split, store to TB layout ----
    l0 += __shfl_xor_sync(0xffffffffu, l0, 1);
    l0 += __shfl_xor_sync(0xffffffffu, l0, 2);
    l1 += __shfl_xor_sync(0xffffffffu, l1, 1);
    l1 += __shfl_xor_sync(0xffffffffu, l1, 2);
    const float inv0 = 1.f / l0, inv1 = 1.f / l1;
    const int r0g = b * SEQ + qb + q0 + (lane >> 2);
    const int r1g = r0g + 8;
    const int col0 = h * HEAD_DIM + 2 * (lane & 3);
    char* ga = (char*)aout;
#pragma unroll
    for (int f = 0; f < 16; f++) {
        const int col = col0 + f * 8;
        const int c = col >> 5, u = (col & 31) >> 3, bo = (col & 7) * 2;
#pragma unroll
        for (int half = 0; half < 2; half++) {
            const int row = half ? r1g : r0g;
            const float inv = half ? inv1 : inv0;
            const float vx = O[f][half * 2 + 0] * inv;
            const float vy = O[f][half * 2 + 1] * inv;
            bf16 h0, h1, lo0, lo1;
            split2(vx, h0, lo0); split2(vy, h1, lo1);
            bf162 ph; ph.x = h0; ph.y = h1;
            bf162 pl; pl.x = lo0; pl.y = lo1;
            const int mblk = row >> 7, rl = row & 127;
            char* base = ga + (((size_t)(mblk * 64 + c)) << 14);
            *(bf162*)(base + tb_off(rl, u) + bo)     = ph;
            *(bf162*)(base + tb_off(rl, u + 4) + bo) = pl;
        }
    }
}

// =========================== launch sequence ===============================
extern "C" void kernel_launch(void* const* d_in, const int* in_sizes, int n_in,
                              void* d_out, int out_size) {
    const float* hs      = (const float*)d_in[0];
    const float* ln1_g   = (const float*)d_in[1];
    const float* ln1_b   = (const float*)d_in[2];
    const float* w_qkv   = (const float*)d_in[3];
    const float* b_qkv   = (const float*)d_in[4];
    const float* attn_v  = (const float*)d_in[5];
    const float* attn_g  = (const float*)d_in[6];
    const float* attn_b  = (const float*)d_in[7];
    /* d_in[8] = emotion_bias: softmax-invariant, unused */
    const float* ln2_g   = (const float*)d_in[9];
    const float* ln2_b   = (const float*)d_in[10];
    const float* w_fc    = (const float*)d_in[11];
    const float* b_fc    = (const float*)d_in[12];
    const float* mlp_v   = (const float*)d_in[13];
    const float* mlp_g   = (const float*)d_in[14];
    const float* mlp_b   = (const float*)d_in[15];
    float* out = (float*)d_out;

    float *hid, *sA, *sM;
    bf16 *xt, *ft, *at, *qt, *wq, *wp, *wf, *wm;
    cudaGetSymbolAddress((void**)&hid, g_hid);
    cudaGetSymbolAddress((void**)&sA,  g_sA);
    cudaGetSymbolAddress((void**)&sM,  g_sM);
    cudaGetSymbolAddress((void**)&xt,  g_x);
    cudaGetSymbolAddress((void**)&ft,  g_f);
    cudaGetSymbolAddress((void**)&at,  g_a);
    cudaGetSymbolAddress((void**)&qt,  g_qt);
    cudaGetSymbolAddress((void**)&wq,  g_wq);
    cudaGetSymbolAddress((void**)&wp,  g_wp);
    cudaGetSymbolAddress((void**)&wf,  g_wf);
    cudaGetSymbolAddress((void**)&wm,  g_wm);

    cudaFuncSetAttribute(attn_mma,
                         cudaFuncAttributeMaxDynamicSharedMemorySize, ATT_SMEM);
    cudaFuncSetAttribute(tgemm<false, false, false, false, true>,
                         cudaFuncAttributeMaxDynamicSharedMemorySize, GEMM_SMEM);
    cudaFuncSetAttribute(tgemm<false, true, true, false, false>,
                         cudaFuncAttributeMaxDynamicSharedMemorySize, GEMM_SMEM);
    cudaFuncSetAttribute(tgemm<true, false, false, true, false>,
                         cudaFuncAttributeMaxDynamicSharedMemorySize, GEMM_SMEM);

    // 0: LN1 -> TB
    ln_kernel<<<ROWS, 256>>>(hs, ln1_g, ln1_b, xt);
    // 1: convw w_qkv -> TB
    convw_kernel<<<dim3(1, QKV_W), 256>>>(w_qkv, nullptr, wq, QKV_W, N_EMBD);
    // 2: colnorm attn proj
    colnorm_kernel<<<N_EMBD / 32, 256>>>(attn_v, attn_g, sA, N_EMBD, N_EMBD);
    // 3: QKV GEMM -> AB layout   (ncu capture target)
    tgemm<false, false, false, false, true>
        <<<dim3(QKV_W / 128, ROWS / 256), 256, GEMM_SMEM>>>(
        xt, wq, b_qkv, nullptr, nullptr, qt, ROWS, QKV_W, N_EMBD);
    // 4: attention -> TB
    attn_mma<<<dim3(SEQ / 64, N_HEAD, BATCH), 128, ATT_SMEM>>>(qt, at);
    // 5: convw attn proj (wn-folded) -> TB
    convw_kernel<<<dim3(1, N_EMBD), 256>>>(attn_v, sA, wp, N_EMBD, N_EMBD);
    // 6: attn proj + residual(hs) -> hid fp32
    tgemm<false, true, true, false, false>
        <<<dim3(N_EMBD / 128, ROWS / 256), 256, GEMM_SMEM>>>(
        at, wp, attn_b, hs, hid, nullptr, ROWS, N_EMBD, N_EMBD);
    // 7: LN2 -> TB
    ln_kernel<<<ROWS, 256>>>(hid, ln2_g, ln2_b, xt);
    // 8: convw w_fc -> TB
    convw_kernel<<<dim3(1, N_INNER), 256>>>(w_fc, nullptr, wf, N_INNER, N_EMBD);
    // 9: FC + GELU -> TB
    tgemm<true, false, false, true, false>
        <<<dim3(N_INNER / 128, ROWS / 256), 256, GEMM_SMEM>>>(
        xt, wf, b_fc, nullptr, nullptr, ft, ROWS, N_INNER, N_EMBD);
    // 10: colnorm mlp proj
    colnorm_kernel<<<N_INNER / 32, 256>>>(mlp_v, mlp_g, sM, N_EMBD, N_INNER);
    // 11: convw mlp proj (wn-folded) -> TB (K = N_INNER)
    convw_kernel<<<dim3(N_INNER / 2048, N_EMBD), 256>>>(mlp_v, sM, wm, N_EMBD, N_INNER);
    // 12: MLP proj + residual(hid) -> out fp32
    tgemm<false, true, true, false, false>
        <<<dim3(N_EMBD / 128, ROWS / 256), 256, GEMM_SMEM>>>(
        ft, wm, mlp_b, hid, out, nullptr, ROWS, N_EMBD, N_INNER);
}

// round 11
// speedup vs baseline: 3.7664x; 1.0354x over previous
#include <cuda_runtime.h>
#include <cuda_bf16.h>
#include <math.h>
#include <stdint.h>

// ---------------- problem constants ----------------
#define N_EMBD   2048
#define N_HEAD   16
#define HEAD_DIM 128
#define N_INNER  8192
#define SEQ      2048
#define BATCH    2
#define ROWS     (BATCH*SEQ)     /* 4096 */
#define QKV_W    (3*N_EMBD)      /* 6144 */

typedef __nv_bfloat16 bf16;
typedef __nv_bfloat162 bf162;

// ---------------- scratch (device globals; no allocs allowed) --------------
// TB layout: [rowblk128][kchunk32] blocks of 16KB; row=128B=[hi 64B|lo 64B],
//   unit u (16B) at phys r*128 + ((u ^ (r&7))<<4)  (u 0..3 hi, 4..7 lo)
// AB layout (attention): [type][b][h][seqblk64] blocks of 32KB; row=512B,
//   unit u at phys r*512 + ((u ^ (r&7))<<4)  (u 0..15 hi, 16..31 lo)
__device__ __align__(256) bf16  g_x  [(size_t)ROWS * N_EMBD * 2];
__device__ __align__(256) bf16  g_f  [(size_t)ROWS * N_INNER * 2];
__device__ __align__(256) bf16  g_a  [(size_t)ROWS * N_EMBD * 2];
__device__ __align__(256) bf16  g_qt [(size_t)3 * BATCH * N_HEAD * 32 * 16384];
__device__ __align__(256) bf16  g_wq [(size_t)QKV_W * N_EMBD * 2];
__device__ __align__(256) bf16  g_wp [(size_t)N_EMBD * N_EMBD * 2];
__device__ __align__(256) bf16  g_wf [(size_t)N_INNER * N_EMBD * 2];
__device__ __align__(256) bf16  g_wm [(size_t)N_EMBD * N_INNER * 2];
__device__ float g_hid[(size_t)ROWS * N_EMBD];
__device__ float g_sA [N_EMBD];
__device__ float g_sM [N_INNER];

// ========================= helpers =========================================
__device__ __forceinline__ uint32_t smem_u32(const void* p) {
    uint32_t a;
    asm("{ .reg .u64 t; cvta.to.shared.u64 t, %1; cvt.u32.u64 %0, t; }"
        : "=r"(a) : "l"(p));
    return a;
}
__device__ __forceinline__ uint32_t tb_off(int r, int u) {
    return (uint32_t)(r * 128 + ((u ^ (r & 7)) << 4));
}
__device__ __forceinline__ uint32_t ab_off(int r, int u) {
    return (uint32_t)(r * 512 + ((u ^ (r & 7)) << 4));
}
__device__ __forceinline__ void mbar_init(uint32_t m, uint32_t cnt) {
    asm volatile("mbarrier.init.shared.b64 [%0], %1;" :: "r"(m), "r"(cnt) : "memory");
}
__device__ __forceinline__ void mbar_expect(uint32_t m, uint32_t bytes) {
    asm volatile("mbarrier.arrive.expect_tx.shared.b64 _, [%0], %1;"
                 :: "r"(m), "r"(bytes) : "memory");
}
__device__ __forceinline__ void mbar_arrive(uint32_t m) {
    asm volatile("mbarrier.arrive.shared.b64 _, [%0];" :: "r"(m) : "memory");
}
__device__ __forceinline__ void mbar_wait(uint32_t m, uint32_t parity) {
    asm volatile(
        "{\n\t.reg .pred P;\n\t"
        "W_%=:\n\t"
        "mbarrier.try_wait.parity.shared.b64 P, [%0], %1;\n\t"
        "@!P bra W_%=;\n\t}"
        :: "r"(m), "r"(parity) : "memory");
}
__device__ __forceinline__ void bulk_g2s(uint32_t dst, const void* src,
                                         uint32_t bytes, uint32_t mbar) {
    asm volatile(
        "cp.async.bulk.shared::cluster.global.mbarrier::complete_tx::bytes "
        "[%0], [%1], %2, [%3];"
        :: "r"(dst), "l"(src), "r"(bytes), "r"(mbar) : "memory");
}
__device__ __forceinline__ void ldsm4(uint32_t& r0, uint32_t& r1,
                                      uint32_t& r2, uint32_t& r3, uint32_t addr) {
    asm volatile("ldmatrix.sync.aligned.m8n8.x4.shared.b16 {%0,%1,%2,%3}, [%4];"
                 : "=r"(r0), "=r"(r1), "=r"(r2), "=r"(r3) : "r"(addr));
}
__device__ __forceinline__ void ldsm4t(uint32_t& r0, uint32_t& r1,
                                       uint32_t& r2, uint32_t& r3, uint32_t addr) {
    asm volatile("ldmatrix.sync.aligned.m8n8.x4.trans.shared.b16 {%0,%1,%2,%3}, [%4];"
                 : "=r"(r0), "=r"(r1), "=r"(r2), "=r"(r3) : "r"(addr));
}
__device__ __forceinline__ void mma_bf16(float* c, const uint32_t* a,
                                         const uint32_t* b) {
    asm volatile(
        "mma.sync.aligned.m16n8k16.row.col.f32.bf16.bf16.f32 "
        "{%0,%1,%2,%3}, {%4,%5,%6,%7}, {%8,%9}, {%0,%1,%2,%3};"
        : "+f"(c[0]), "+f"(c[1]), "+f"(c[2]), "+f"(c[3])
        : "r"(a[0]), "r"(a[1]), "r"(a[2]), "r"(a[3]), "r"(b[0]), "r"(b[1]));
}
__device__ __forceinline__ float ex2f(float x) {
    float y;
    asm("ex2.approx.f32 %0, %1;" : "=f"(y) : "f"(x));
    return y;
}
__device__ __forceinline__ void split2(float x, bf16& h, bf16& l) {
    h = __float2bfloat16(x);
    l = __float2bfloat16(x - __bfloat162float(h));
}
__device__ __forceinline__ uint32_t packbf(float a, float b) {
    bf162 t = __floats2bfloat162_rn(a, b);
    return *(uint32_t*)&t;
}
__device__ __forceinline__ uint32_t pack2(bf16 a, bf16 b) {
    bf162 t; t.x = a; t.y = b;
    return *(uint32_t*)&t;
}

// ======================= LayerNorm -> TB layout ============================
__global__ __launch_bounds__(256) void ln_kernel(const float* __restrict__ x,
                                                 const float* __restrict__ g,
                                                 const float* __restrict__ bp,
                                                 bf16* __restrict__ yt) {
    __shared__ float red[8];
    __shared__ float s_mean, s_rstd;
    const int row = blockIdx.x, t = threadIdx.x;
    const float* xr = x + (size_t)row * N_EMBD + t * 8;
    float v[8];
    *(float4*)&v[0] = *(const float4*)&xr[0];
    *(float4*)&v[4] = *(const float4*)&xr[4];
    float s = v[0] + v[1] + v[2] + v[3] + v[4] + v[5] + v[6] + v[7];
#pragma unroll
    for (int o = 16; o > 0; o >>= 1) s += __shfl_xor_sync(0xffffffffu, s, o);
    if ((t & 31) == 0) red[t >> 5] = s;
    __syncthreads();
    if (t == 0) {
        float tt = 0.f;
#pragma unroll
        for (int i = 0; i < 8; i++) tt += red[i];
        s_mean = tt * (1.f / N_EMBD);
    }
    __syncthreads();
    const float mu = s_mean;
    float vs = 0.f;
#pragma unroll
    for (int k = 0; k < 8; k++) { float d = v[k] - mu; vs += d * d; }
#pragma unroll
    for (int o = 16; o > 0; o >>= 1) vs += __shfl_xor_sync(0xffffffffu, vs, o);
    if ((t & 31) == 0) red[t >> 5] = vs;
    __syncthreads();
    if (t == 0) {
        float tt = 0.f;
#pragma unroll
        for (int i = 0; i < 8; i++) tt += red[i];
        s_rstd = rsqrtf(tt * (1.f / N_EMBD) + 1e-5f);
    }
    __syncthreads();
    const float rstd = s_rstd;
    float gg[8], bb[8];
    *(float4*)&gg[0] = *(const float4*)&g[t * 8];
    *(float4*)&gg[4] = *(const float4*)&g[t * 8 + 4];
    *(float4*)&bb[0] = *(const float4*)&bp[t * 8];
    *(float4*)&bb[4] = *(const float4*)&bp[t * 8 + 4];
    bf16 hi[8], lo[8];
#pragma unroll
    for (int k = 0; k < 8; k++) {
        const float val = (v[k] - mu) * rstd * gg[k] + bb[k];
        split2(val, hi[k], lo[k]);
    }
    uint4 H, L;
    H.x = pack2(hi[0], hi[1]); H.y = pack2(hi[2], hi[3]);
    H.z = pack2(hi[4], hi[5]); H.w = pack2(hi[6], hi[7]);
    L.x = pack2(lo[0], lo[1]); L.y = pack2(lo[2], lo[3]);
    L.z = pack2(lo[4], lo[5]); L.w = pack2(lo[6], lo[7]);
    const int mblk = row >> 7, rl = row & 127, c = t >> 2, su = t & 3;
    char* base = (char*)yt + (((size_t)(mblk * 64 + c)) << 14);
    *(uint4*)(base + tb_off(rl, su))     = H;
    *(uint4*)(base + tb_off(rl, su + 4)) = L;
}

// ========== weight-norm column scales ======================================
__global__ __launch_bounds__(256) void colnorm_kernel(const float* __restrict__ v,
                                                      const float* __restrict__ g,
                                                      float* __restrict__ scale,
                                                      int rows, int cols) {
    __shared__ float red[8][32];
    const int lane = threadIdx.x & 31;
    const int r0   = threadIdx.x >> 5;
    const int j    = blockIdx.x * 32 + lane;
    float acc = 0.f;
    for (int r = r0; r < rows; r += 8) {
        float t = v[(size_t)r * cols + j];
        acc += t * t;
    }
    red[r0][lane] = acc;
    __syncthreads();
    if (r0 == 0) {
        float s = red[0][lane];
#pragma unroll
        for (int q = 1; q < 8; q++) s += red[q][lane];
        scale[j] = g[j] / sqrtf(s);
    }
}

// ========== weight conversion: fp32 (* s[k]) -> TB layout ==================
__global__ __launch_bounds__(256) void convw_kernel(const float* __restrict__ w,
                                                    const float* __restrict__ s,
                                                    bf16* __restrict__ out,
                                                    int N, int K) {
    const int n  = blockIdx.y;
    const int kg = blockIdx.x * 256 + threadIdx.x;
    const int k0 = kg * 8;
    float v[8];
    *(float4*)&v[0] = *(const float4*)&w[(size_t)n * K + k0];
    *(float4*)&v[4] = *(const float4*)&w[(size_t)n * K + k0 + 4];
    if (s) {
#pragma unroll
        for (int k = 0; k < 8; k++) v[k] *= s[k0 + k];
    }
    bf16 hi[8], lo[8];
#pragma unroll
    for (int k = 0; k < 8; k++) split2(v[k], hi[k], lo[k]);
    uint4 H, L;
    H.x = pack2(hi[0], hi[1]); H.y = pack2(hi[2], hi[3]);
    H.z = pack2(hi[4], hi[5]); H.w = pack2(hi[6], hi[7]);
    L.x = pack2(lo[0], lo[1]); L.y = pack2(lo[2], lo[3]);
    L.z = pack2(lo[4], lo[5]); L.w = pack2(lo[6], lo[7]);
    const int nblk = n >> 7, r = n & 127, c = kg >> 2, su = kg & 3;
    char* base = (char*)out + (((size_t)(nblk * (K >> 5) + c)) << 14);
    *(uint4*)(base + tb_off(r, su))     = H;
    *(uint4*)(base + tb_off(r, su + 4)) = L;
}

// ================= HMMA split-bf16 GEMM, bulk pipeline (4-stage) ===========
// Tile 256x128, 8 warps (warp 64x64). full/empty mbarrier pairs, no
// mainloop __syncthreads: consumers arrive on empty AFTER their MMAs consume
// the fragments (register dependency => ldmatrix reads retired).
#define GSOFF 1024
#define GSTG  49152
#define GEMM_SMEM (GSOFF + 4 * GSTG)

template<bool DOGELU, bool RES, bool WF32, bool WTB, bool WQKV>
__global__ __launch_bounds__(256) void tgemm(const bf16* __restrict__ A,
                                             const bf16* __restrict__ B,
                                             const float* __restrict__ bias,
                                             const float* __restrict__ res,
                                             float* __restrict__ C,
                                             bf16* __restrict__ T,
                                             int M, int N, int K) {
    extern __shared__ char sm[];
    const uint32_t sb = smem_u32(sm);
    const int tid  = threadIdx.x;
    const int lane = tid & 31;
    const int wid  = tid >> 5;
    const int warp_m = wid >> 1;    // 0..3
    const int warp_n = wid & 1;     // 0..1
    const int m0 = blockIdx.y * 256;
    const int n0 = blockIdx.x * 128;
    const int nc = K >> 5;
    const int lm = lane & 15, lq = lane >> 4, l8 = (lane >> 3) & 1, l7 = lane & 7;
    const char* Ab = (const char*)A;
    const char* Bb = (const char*)B;
    const int amb = blockIdx.y * 2;

    // full[s] = sb + s*8 ; empty[s] = sb + 32 + s*8
    if (tid == 0) {
#pragma unroll
        for (int s = 0; s < 4; s++) {
            mbar_init(sb + s * 8, 1);
            mbar_init(sb + 32 + s * 8, 8);
        }
    }
    __syncthreads();
    if (tid == 0) {
#pragma unroll
        for (int s = 0; s < 4; s++) {
            const uint32_t mb = sb + s * 8;
            const uint32_t st = sb + GSOFF + s * GSTG;
            mbar_expect(mb, 49152);
            bulk_g2s(st,         Ab + (((size_t)((amb + 0) * nc + s)) << 14), 16384, mb);
            bulk_g2s(st + 16384, Ab + (((size_t)((amb + 1) * nc + s)) << 14), 16384, mb);
            bulk_g2s(st + 32768, Bb + (((size_t)(blockIdx.x * nc + s)) << 14), 16384, mb);
        }
    }

    float acc[4][8][4];
#pragma unroll
    for (int i = 0; i < 4; i++)
#pragma unroll
        for (int j = 0; j < 8; j++)
#pragma unroll
            for (int t = 0; t < 4; t++) acc[i][j][t] = 0.f;

    for (int c = 0; c < nc; c++) {
        const int slot = c & 3;
        const int rnd  = c >> 2;
        mbar_wait(sb + slot * 8, rnd & 1);
        const uint32_t st = sb + GSOFF + slot * GSTG;
#pragma unroll
        for (int s = 0; s < 2; s++) {
            uint32_t aH[4][4], aL[4][4], bH[8][2], bL[8][2];
#pragma unroll
            for (int i = 0; i < 4; i++) {
                const int r = warp_m * 64 + lm + i * 16;
                const uint32_t bb_ = st + ((uint32_t)(r >> 7) << 14);
                const int rl = r & 127;
                ldsm4(aH[i][0], aH[i][1], aH[i][2], aH[i][3],
                      bb_ + tb_off(rl, s * 2 + lq));
                ldsm4(aL[i][0], aL[i][1], aL[i][2], aL[i][3],
                      bb_ + tb_off(rl, s * 2 + lq + 4));
            }
#pragma unroll
            for (int j2 = 0; j2 < 4; j2++) {
                const int r = warp_n * 64 + j2 * 16 + lq * 8 + l7;
                uint32_t t0, t1, t2, t3;
                ldsm4(t0, t1, t2, t3, st + 32768 + tb_off(r, s * 2 + l8));
                bH[2 * j2][0] = t0; bH[2 * j2][1] = t1;
                bH[2 * j2 + 1][0] = t2; bH[2 * j2 + 1][1] = t3;
                ldsm4(t0, t1, t2, t3, st + 32768 + tb_off(r, s * 2 + l8 + 4));
                bL[2 * j2][0] = t0; bL[2 * j2][1] = t1;
                bL[2 * j2 + 1][0] = t2; bL[2 * j2 + 1][1] = t3;
            }
#pragma unroll
            for (int i = 0; i < 4; i++)
#pragma unroll
                for (int j = 0; j < 8; j++) {
                    mma_bf16(acc[i][j], aH[i], bH[j]);
                    mma_bf16(acc[i][j], aH[i], bL[j]);
                    mma_bf16(acc[i][j], aL[i], bH[j]);
                }
        }
        // fragments fully consumed by MMAs above -> safe to release slot
        if (lane == 0) mbar_arrive(sb + 32 + slot * 8);
        if (tid == 0 && c + 4 < nc) {
            mbar_wait(sb + 32 + slot * 8, rnd & 1);   // all 8 warps released
            const uint32_t mb = sb + slot * 8;
            mbar_expect(mb, 49152);
            bulk_g2s(st,         Ab + (((size_t)((amb + 0) * nc + c + 4)) << 14), 16384, mb);
            bulk_g2s(st + 16384, Ab + (((size_t)((amb + 1) * nc + c + 4)) << 14), 16384, mb);
            bulk_g2s(st + 32768, Bb + (((size_t)(blockIdx.x * nc + c + 4)) << 14), 16384, mb);
        }
    }

    // ---------------- epilogue ----------------
    const int r_base = m0 + warp_m * 64 + (lane >> 2);
    const int c_base = n0 + warp_n * 64 + 2 * (lane & 3);
#pragma unroll
    for (int i = 0; i < 4; i++) {
#pragma unroll
        for (int j = 0; j < 8; j++) {
            const int col = c_base + j * 8;
            const float2 bi = *(const float2*)&bias[col];
#pragma unroll
            for (int half = 0; half < 2; half++) {
                const int row = r_base + i * 16 + half * 8;
                float vx = acc[i][j][half * 2 + 0] + bi.x;
                float vy = acc[i][j][half * 2 + 1] + bi.y;
                if (DOGELU) {
                    vx = 0.5f * vx * (1.f + erff(vx * 0.70710678118654752f));
                    vy = 0.5f * vy * (1.f + erff(vy * 0.70710678118654752f));
                }
                if (RES) {
                    const float2 rv = *(const float2*)&res[(size_t)row * N + col];
                    vx += rv.x; vy += rv.y;
                }
                if (WF32) {
                    float2 o; o.x = vx; o.y = vy;
                    *(float2*)&C[(size_t)row * N + col] = o;
                }
                if (WTB) {
                    bf16 h0, h1, l0, l1;
                    split2(vx, h0, l0); split2(vy, h1, l1);
                    bf162 ph; ph.x = h0; ph.y = h1;
                    bf162 pl; pl.x = l0; pl.y = l1;
                    const int mblk = row >> 7, rl = row & 127;
                    const int cc = col >> 5, u = (col & 31) >> 3, bo = (col & 7) * 2;
                    char* base = (char*)T + (((size_t)(mblk * (N >> 5) + cc)) << 14);
                    *(bf162*)(base + tb_off(rl, u) + bo)     = ph;
                    *(bf162*)(base + tb_off(rl, u + 4) + bo) = pl;
                }
                if (WQKV) {
                    bf16 h0, h1, l0, l1;
                    split2(vx, h0, l0); split2(vy, h1, l1);
                    bf162 ph; ph.x = h0; ph.y = h1;
                    bf162 pl; pl.x = l0; pl.y = l1;
                    const int type = col >> 11, hh = (col >> 7) & 15;
                    const int bb2 = row >> 11, seq = row & 2047;
                    const int sblk = seq >> 6, rl = seq & 63;
                    const int d = col & 127, u = d >> 3, bo = (d & 7) * 2;
                    char* base = (char*)T +
                        (((size_t)((((type * 2 + bb2) * 16 + hh) * 32) + sblk)) << 15);
                    *(bf162*)(base + ab_off(rl, u) + bo)      = ph;
                    *(bf162*)(base + ab_off(rl, u + 16) + bo) = pl;
                }
            }
        }
    }
}

// ============== HMMA split-bf16 flash attention ============================
// CTA: 128 queries x one head, 8 warps (2/SMSP). Q/K/V in AB layout.
// smem: Q 64KB (two 32KB blocks); KV 2 stages x 64KB; full/empty barriers.
#define ASQ   1024
#define ASKV  (1024 + 65536)
#define ASTG  65536
#define ATT_SMEM (1024 + 65536 + 2 * 65536)
#define SOFTSC 0.1275174048f /* (1/sqrt(128)) * log2(e) */

__global__ __launch_bounds__(256) void attn_mma(const bf16* __restrict__ qt,
                                                bf16* __restrict__ aout) {
    extern __shared__ char sm[];
    const uint32_t sb = smem_u32(sm);
    const int tid  = threadIdx.x;
    const int lane = tid & 31;
    const int wid  = tid >> 5;
    const int qb   = blockIdx.x * 128;
    const int h    = blockIdx.y;
    const int b    = blockIdx.z;
    const int q0   = wid * 16;
    const int lm = lane & 15, lq = lane >> 4, l8 = (lane >> 3) & 1, l7 = lane & 7;
    const char* qbase = (const char*)qt;

    auto blk = [&](int type, int sblk) -> const char* {
        return qbase + (((size_t)(((type * 2 + b) * 16 + h) * 32 + sblk)) << 15);
    };

    // barriers: qfull=sb+0; kfull[s]=sb+8+s*8; kempty[s]=sb+24+s*8
    if (tid == 0) {
        mbar_init(sb + 0, 1);
        mbar_init(sb + 8, 1);
        mbar_init(sb + 16, 1);
        mbar_init(sb + 24, 8);
        mbar_init(sb + 32, 8);
    }
    __syncthreads();
    if (tid == 0) {
        mbar_expect(sb + 0, 65536);
        bulk_g2s(sb + ASQ,          blk(0, (qb >> 6) + 0), 32768, sb + 0);
        bulk_g2s(sb + ASQ + 32768,  blk(0, (qb >> 6) + 1), 32768, sb + 0);
        mbar_expect(sb + 8, 65536);
        bulk_g2s(sb + ASKV,          blk(1, 0), 32768, sb + 8);
        bulk_g2s(sb + ASKV + 32768,  blk(2, 0), 32768, sb + 8);
        mbar_expect(sb + 16, 65536);
        bulk_g2s(sb + ASKV + ASTG,          blk(1, 1), 32768, sb + 16);
        bulk_g2s(sb + ASKV + ASTG + 32768,  blk(2, 1), 32768, sb + 16);
    }

    float m0 = -1e30f, m1 = -1e30f, l0 = 0.f, l1 = 0.f;
    float O[16][4];
#pragma unroll
    for (int f = 0; f < 16; f++)
#pragma unroll
        for (int c = 0; c < 4; c++) O[f][c] = 0.f;

    mbar_wait(sb + 0, 0);   // Q ready

    const int qr = q0 + lm;
    const uint32_t qblk = sb + ASQ + ((uint32_t)(qr >> 6) << 15);
    const int qrl = qr & 63;

    for (int it = 0; it < 32; it++) {
        const int slot = it & 1;
        const int rnd  = it >> 1;
        mbar_wait(sb + 8 + slot * 8, rnd & 1);
        const uint32_t kvb = sb + ASKV + slot * ASTG;

        // ---- S = Q K^T (3-term split, log2 domain) ----
        float s[8][4];
#pragma unroll
        for (int j = 0; j < 8; j++)
#pragma unroll
            for (int c = 0; c < 4; c++) s[j][c] = 0.f;

#pragma unroll
        for (int kd = 0; kd < 8; kd++) {
            uint32_t aH[4], aL[4];
            ldsm4(aH[0], aH[1], aH[2], aH[3], qblk + ab_off(qrl, kd * 2 + lq));
            ldsm4(aL[0], aL[1], aL[2], aL[3], qblk + ab_off(qrl, kd * 2 + lq + 16));
#pragma unroll
            for (int kg = 0; kg < 4; kg++) {
                const int kr = kg * 16 + lq * 8 + l7;
                uint32_t t0, t1, t2, t3;
                uint32_t bh0[2], bh1[2], bl0[2], bl1[2];
                ldsm4(t0, t1, t2, t3, kvb + ab_off(kr, kd * 2 + l8));
                bh0[0] = t0; bh0[1] = t1; bh1[0] = t2; bh1[1] = t3;
                ldsm4(t0, t1, t2, t3, kvb + ab_off(kr, kd * 2 + l8 + 16));
                bl0[0] = t0; bl0[1] = t1; bl1[0] = t2; bl1[1] = t3;
                mma_bf16(s[2 * kg],     aH, bh0);
                mma_bf16(s[2 * kg],     aH, bl0);
                mma_bf16(s[2 * kg],     aL, bh0);
                mma_bf16(s[2 * kg + 1], aH, bh1);
                mma_bf16(s[2 * kg + 1], aH, bl1);
                mma_bf16(s[2 * kg + 1], aL, bh1);
            }
        }

        // ---- online softmax (registers) ----
        float mt0 = -1e30f, mt1 = -1e30f;
#pragma unroll
        for (int j = 0; j < 8; j++) {
#pragma unroll
            for (int c = 0; c < 4; c++) s[j][c] *= SOFTSC;
            mt0 = fmaxf(mt0, fmaxf(s[j][0], s[j][1]));
            mt1 = fmaxf(mt1, fmaxf(s[j][2], s[j][3]));
        }
        mt0 = fmaxf(mt0, __shfl_xor_sync(0xffffffffu, mt0, 1));
        mt0 = fmaxf(mt0, __shfl_xor_sync(0xffffffffu, mt0, 2));
        mt1 = fmaxf(mt1, __shfl_xor_sync(0xffffffffu, mt1, 1));
        mt1 = fmaxf(mt1, __shfl_xor_sync(0xffffffffu, mt1, 2));
        const float mn0 = fmaxf(m0, mt0), mn1 = fmaxf(m1, mt1);
        const float corr0 = ex2f(m0 - mn0), corr1 = ex2f(m1 - mn1);
        m0 = mn0; m1 = mn1;
        float ps0 = 0.f, ps1 = 0.f;
#pragma unroll
        for (int j = 0; j < 8; j++) {
            s[j][0] = ex2f(s[j][0] - mn0);
            s[j][1] = ex2f(s[j][1] - mn0);
            s[j][2] = ex2f(s[j][2] - mn1);
            s[j][3] = ex2f(s[j][3] - mn1);
            ps0 += s[j][0] + s[j][1];
            ps1 += s[j][2] + s[j][3];
        }
        l0 = l0 * corr0 + ps0;
        l1 = l1 * corr1 + ps1;
#pragma unroll
        for (int f = 0; f < 16; f++) {
            O[f][0] *= corr0; O[f][1] *= corr0;
            O[f][2] *= corr1; O[f][3] *= corr1;
        }

        // ---- O += P V ----
#pragma unroll
        for (int kk = 0; kk < 4; kk++) {
            const int j0 = 2 * kk, j1 = 2 * kk + 1;
            uint32_t pH[4], pL[4];
            {
                uint32_t hi;
                bf162 hv;
                float la, lb;
                hi = packbf(s[j0][0], s[j0][1]); hv = *(bf162*)&hi;
                la = s[j0][0] - __bfloat162float(hv.x);
                lb = s[j0][1] - __bfloat162float(hv.y);
                pH[0] = hi; pL[0] = packbf(la, lb);
                hi = packbf(s[j0][2], s[j0][3]); hv = *(bf162*)&hi;
                la = s[j0][2] - __bfloat162float(hv.x);
                lb = s[j0][3] - __bfloat162float(hv.y);
                pH[1] = hi; pL[1] = packbf(la, lb);
                hi = packbf(s[j1][0], s[j1][1]); hv = *(bf162*)&hi;
                la = s[j1][0] - __bfloat162float(hv.x);
                lb = s[j1][1] - __bfloat162float(hv.y);
                pH[2] = hi; pL[2] = packbf(la, lb);
                hi = packbf(s[j1][2], s[j1][3]); hv = *(bf162*)&hi;
                la = s[j1][2] - __bfloat162float(hv.x);
                lb = s[j1][3] - __bfloat162float(hv.y);
                pH[3] = hi; pL[3] = packbf(la, lb);
            }
#pragma unroll
            for (int g = 0; g < 8; g++) {
                const int vr = kk * 16 + l8 * 8 + l7;
                uint32_t t0, t1, t2, t3;
                uint32_t bh0[2], bh1[2], bl0[2], bl1[2];
                ldsm4t(t0, t1, t2, t3, kvb + 32768 + ab_off(vr, g * 2 + lq));
                bh0[0] = t0; bh0[1] = t1; bh1[0] = t2; bh1[1] = t3;
                ldsm4t(t0, t1, t2, t3, kvb + 32768 + ab_off(vr, g * 2 + lq + 16));
                bl0[0] = t0; bl0[1] = t1; bl1[0] = t2; bl1[1] = t3;
                mma_bf16(O[2 * g],     pH, bh0);
                mma_bf16(O[2 * g],     pH, bl0);
                mma_bf16(O[2 * g],     pL, bh0);
                mma_bf16(O[2 * g + 1], pH, bh1);
                mma_bf16(O[2 * g + 1], pH, bl1);
                mma_bf16(O[2 * g + 1], pL, bh1);
            }
        }
        // K/V fragments consumed by MMAs above -> release stage
        if (lane == 0) mbar_arrive(sb + 24 + slot * 8);
        if (tid == 0 && it + 2 < 32) {
            mbar_wait(sb + 24 + slot * 8, rnd & 1);
            const uint32_t mb = sb + 8 + slot * 8;
            const uint32_t dst = sb + ASKV + slot * ASTG;
            mbar_expect(mb, 65536);
            bulk_g2s(dst,         blk(1, it + 2), 32768, mb);
            bulk_g2s(dst + 32768, blk(2, it + 2), 32768, mb);
        }
    }

    // ---- finalize: normalize, split, store to TB layout ----
    l0 += __shfl_xor_sync(0xffffffffu, l0, 1);
    l0 += __shfl_xor_sync(0xffffffffu, l0, 2);
    l1 += __shfl_xor_sync(0xffffffffu, l1, 1);
    l1 += __shfl_xor_sync(0xffffffffu, l1, 2);
    const float inv0 = 1.f / l0, inv1 = 1.f / l1;
    const int r0g = b * SEQ + qb + q0 + (lane >> 2);
    const int r1g = r0g + 8;
    const int col0 = h * HEAD_DIM + 2 * (lane & 3);
    char* ga = (char*)aout;
#pragma unroll
    for (int f = 0; f < 16; f++) {
        const int col = col0 + f * 8;
        const int c = col >> 5, u = (col & 31) >> 3, bo = (col & 7) * 2;
#pragma unroll
        for (int half = 0; half < 2; half++) {
            const int row = half ? r1g : r0g;
            const float inv = half ? inv1 : inv0;
            const float vx = O[f][half * 2 + 0] * inv;
            const float vy = O[f][half * 2 + 1] * inv;
            bf16 h0, h1, lo0, lo1;
            split2(vx, h0, lo0); split2(vy, h1, lo1);
            bf162 ph; ph.x = h0; ph.y = h1;
            bf162 pl; pl.x = lo0; pl.y = lo1;
            const int mblk = row >> 7, rl = row & 127;
            char* base = ga + (((size_t)(mblk * 64 + c)) << 14);
            *(bf162*)(base + tb_off(rl, u) + bo)     = ph;
            *(bf162*)(base + tb_off(rl, u + 4) + bo) = pl;
        }
    }
}

// =========================== launch sequence ===============================
extern "C" void kernel_launch(void* const* d_in, const int* in_sizes, int n_in,
                              void* d_out, int out_size) {
    const float* hs      = (const float*)d_in[0];
    const float* ln1_g   = (const float*)d_in[1];
    const float* ln1_b   = (const float*)d_in[2];
    const float* w_qkv   = (const float*)d_in[3];
    const float* b_qkv   = (const float*)d_in[4];
    const float* attn_v  = (const float*)d_in[5];
    const float* attn_g  = (const float*)d_in[6];
    const float* attn_b  = (const float*)d_in[7];
    /* d_in[8] = emotion_bias: softmax-invariant, unused */
    const float* ln2_g   = (const float*)d_in[9];
    const float* ln2_b   = (const float*)d_in[10];
    const float* w_fc    = (const float*)d_in[11];
    const float* b_fc    = (const float*)d_in[12];
    const float* mlp_v   = (const float*)d_in[13];
    const float* mlp_g   = (const float*)d_in[14];
    const float* mlp_b   = (const float*)d_in[15];
    float* out = (float*)d_out;

    float *hid, *sA, *sM;
    bf16 *xt, *ft, *at, *qt, *wq, *wp, *wf, *wm;
    cudaGetSymbolAddress((void**)&hid, g_hid);
    cudaGetSymbolAddress((void**)&sA,  g_sA);
    cudaGetSymbolAddress((void**)&sM,  g_sM);
    cudaGetSymbolAddress((void**)&xt,  g_x);
    cudaGetSymbolAddress((void**)&ft,  g_f);
    cudaGetSymbolAddress((void**)&at,  g_a);
    cudaGetSymbolAddress((void**)&qt,  g_qt);
    cudaGetSymbolAddress((void**)&wq,  g_wq);
    cudaGetSymbolAddress((void**)&wp,  g_wp);
    cudaGetSymbolAddress((void**)&wf,  g_wf);
    cudaGetSymbolAddress((void**)&wm,  g_wm);

    cudaFuncSetAttribute(attn_mma,
                         cudaFuncAttributeMaxDynamicSharedMemorySize, ATT_SMEM);
    cudaFuncSetAttribute(tgemm<false, false, false, false, true>,
                         cudaFuncAttributeMaxDynamicSharedMemorySize, GEMM_SMEM);
    cudaFuncSetAttribute(tgemm<false, true, true, false, false>,
                         cudaFuncAttributeMaxDynamicSharedMemorySize, GEMM_SMEM);
    cudaFuncSetAttribute(tgemm<true, false, false, true, false>,
                         cudaFuncAttributeMaxDynamicSharedMemorySize, GEMM_SMEM);

    // 0: LN1 -> TB
    ln_kernel<<<ROWS, 256>>>(hs, ln1_g, ln1_b, xt);
    // 1: convw w_qkv -> TB
    convw_kernel<<<dim3(1, QKV_W), 256>>>(w_qkv, nullptr, wq, QKV_W, N_EMBD);
    // 2: colnorm attn proj
    colnorm_kernel<<<N_EMBD / 32, 256>>>(attn_v, attn_g, sA, N_EMBD, N_EMBD);
    // 3: QKV GEMM -> AB layout   (ncu capture target)
    tgemm<false, false, false, false, true>
        <<<dim3(QKV_W / 128, ROWS / 256), 256, GEMM_SMEM>>>(
        xt, wq, b_qkv, nullptr, nullptr, qt, ROWS, QKV_W, N_EMBD);
    // 4: attention -> TB
    attn_mma<<<dim3(SEQ / 128, N_HEAD, BATCH), 256, ATT_SMEM>>>(qt, at);
    // 5: convw attn proj (wn-folded) -> TB
    convw_kernel<<<dim3(1, N_EMBD), 256>>>(attn_v, sA, wp, N_EMBD, N_EMBD);
    // 6: attn proj + residual(hs) -> hid fp32
    tgemm<false, true, true, false, false>
        <<<dim3(N_EMBD / 128, ROWS / 256), 256, GEMM_SMEM>>>(
        at, wp, attn_b, hs, hid, nullptr, ROWS, N_EMBD, N_EMBD);
    // 7: LN2 -> TB
    ln_kernel<<<ROWS, 256>>>(hid, ln2_g, ln2_b, xt);
    // 8: convw w_fc -> TB
    convw_kernel<<<dim3(1, N_INNER), 256>>>(w_fc, nullptr, wf, N_INNER, N_EMBD);
    // 9: FC + GELU -> TB
    tgemm<true, false, false, true, false>
        <<<dim3(N_INNER / 128, ROWS / 256), 256, GEMM_SMEM>>>(
        xt, wf, b_fc, nullptr, nullptr, ft, ROWS, N_INNER, N_EMBD);
    // 10: colnorm mlp proj
    colnorm_kernel<<<N_INNER / 32, 256>>>(mlp_v, mlp_g, sM, N_EMBD, N_INNER);
    // 11: convw mlp proj (wn-folded) -> TB (K = N_INNER)
    convw_kernel<<<dim3(N_INNER / 2048, N_EMBD), 256>>>(mlp_v, sM, wm, N_EMBD, N_INNER);
    // 12: MLP proj + residual(hid) -> out fp32
    tgemm<false, true, true, false, false>
        <<<dim3(N_EMBD / 128, ROWS / 256), 256, GEMM_SMEM>>>(
        ft, wm, mlp_b, hid, out, nullptr, ROWS, N_EMBD, N_INNER);
}

// round 12
// speedup vs baseline: 4.1112x; 1.0916x over previous
#include <cuda_runtime.h>
#include <cuda_bf16.h>
#include <math.h>
#include <stdint.h>

// ---------------- problem constants ----------------
#define N_EMBD   2048
#define N_HEAD   16
#define HEAD_DIM 128
#define N_INNER  8192
#define SEQ      2048
#define BATCH    2
#define ROWS     (BATCH*SEQ)     /* 4096 */
#define QKV_W    (3*N_EMBD)      /* 6144 */

typedef __nv_bfloat16 bf16;
typedef __nv_bfloat162 bf162;

// ---------------- scratch (device globals; no allocs allowed) --------------
// TB layout: [rowblk128][kchunk32] blocks of 16KB; row=128B=[hi 64B|lo 64B],
//   unit u (16B) at phys r*128 + ((u ^ (r&7))<<4)  (u 0..3 hi, 4..7 lo)
// AB layout (attention): [type][b][h][seqblk64] blocks of 32KB; row=512B,
//   unit u at phys r*512 + ((u ^ (r&7))<<4)  (u 0..15 hi, 16..31 lo)
__device__ __align__(256) bf16  g_x  [(size_t)ROWS * N_EMBD * 2];
__device__ __align__(256) bf16  g_f  [(size_t)ROWS * N_INNER * 2];
__device__ __align__(256) bf16  g_a  [(size_t)ROWS * N_EMBD * 2];
__device__ __align__(256) bf16  g_qt [(size_t)3 * BATCH * N_HEAD * 32 * 16384];
__device__ __align__(256) bf16  g_wq [(size_t)QKV_W * N_EMBD * 2];
__device__ __align__(256) bf16  g_wp [(size_t)N_EMBD * N_EMBD * 2];
__device__ __align__(256) bf16  g_wf [(size_t)N_INNER * N_EMBD * 2];
__device__ __align__(256) bf16  g_wm [(size_t)N_EMBD * N_INNER * 2];
__device__ float g_hid[(size_t)ROWS * N_EMBD];
__device__ float g_sA [N_EMBD];
__device__ float g_sM [N_INNER];

// ========================= helpers =========================================
__device__ __forceinline__ uint32_t smem_u32(const void* p) {
    uint32_t a;
    asm("{ .reg .u64 t; cvta.to.shared.u64 t, %1; cvt.u32.u64 %0, t; }"
        : "=r"(a) : "l"(p));
    return a;
}
__device__ __forceinline__ uint32_t tb_off(int r, int u) {
    return (uint32_t)(r * 128 + ((u ^ (r & 7)) << 4));
}
__device__ __forceinline__ uint32_t ab_off(int r, int u) {
    return (uint32_t)(r * 512 + ((u ^ (r & 7)) << 4));
}
__device__ __forceinline__ void mbar_init(uint32_t m, uint32_t cnt) {
    asm volatile("mbarrier.init.shared.b64 [%0], %1;" :: "r"(m), "r"(cnt) : "memory");
}
__device__ __forceinline__ void mbar_expect(uint32_t m, uint32_t bytes) {
    asm volatile("mbarrier.arrive.expect_tx.shared.b64 _, [%0], %1;"
                 :: "r"(m), "r"(bytes) : "memory");
}
__device__ __forceinline__ void mbar_arrive(uint32_t m) {
    asm volatile("mbarrier.arrive.shared.b64 _, [%0];" :: "r"(m) : "memory");
}
__device__ __forceinline__ void mbar_wait(uint32_t m, uint32_t parity) {
    asm volatile(
        "{\n\t.reg .pred P;\n\t"
        "W_%=:\n\t"
        "mbarrier.try_wait.parity.shared.b64 P, [%0], %1;\n\t"
        "@!P bra W_%=;\n\t}"
        :: "r"(m), "r"(parity) : "memory");
}
__device__ __forceinline__ void bulk_g2s(uint32_t dst, const void* src,
                                         uint32_t bytes, uint32_t mbar) {
    asm volatile(
        "cp.async.bulk.shared::cluster.global.mbarrier::complete_tx::bytes "
        "[%0], [%1], %2, [%3];"
        :: "r"(dst), "l"(src), "r"(bytes), "r"(mbar) : "memory");
}
__device__ __forceinline__ void ldsm4(uint32_t& r0, uint32_t& r1,
                                      uint32_t& r2, uint32_t& r3, uint32_t addr) {
    asm volatile("ldmatrix.sync.aligned.m8n8.x4.shared.b16 {%0,%1,%2,%3}, [%4];"
                 : "=r"(r0), "=r"(r1), "=r"(r2), "=r"(r3) : "r"(addr));
}
__device__ __forceinline__ void ldsm4t(uint32_t& r0, uint32_t& r1,
                                       uint32_t& r2, uint32_t& r3, uint32_t addr) {
    asm volatile("ldmatrix.sync.aligned.m8n8.x4.trans.shared.b16 {%0,%1,%2,%3}, [%4];"
                 : "=r"(r0), "=r"(r1), "=r"(r2), "=r"(r3) : "r"(addr));
}
__device__ __forceinline__ void mma_bf16(float* c, const uint32_t* a,
                                         const uint32_t* b) {
    asm volatile(
        "mma.sync.aligned.m16n8k16.row.col.f32.bf16.bf16.f32 "
        "{%0,%1,%2,%3}, {%4,%5,%6,%7}, {%8,%9}, {%0,%1,%2,%3};"
        : "+f"(c[0]), "+f"(c[1]), "+f"(c[2]), "+f"(c[3])
        : "r"(a[0]), "r"(a[1]), "r"(a[2]), "r"(a[3]), "r"(b[0]), "r"(b[1]));
}
__device__ __forceinline__ float ex2f(float x) {
    float y;
    asm("ex2.approx.f32 %0, %1;" : "=f"(y) : "f"(x));
    return y;
}
__device__ __forceinline__ void split2(float x, bf16& h, bf16& l) {
    h = __float2bfloat16(x);
    l = __float2bfloat16(x - __bfloat162float(h));
}
__device__ __forceinline__ uint32_t packbf(float a, float b) {
    bf162 t = __floats2bfloat162_rn(a, b);
    return *(uint32_t*)&t;
}
__device__ __forceinline__ uint32_t pack2(bf16 a, bf16 b) {
    bf162 t; t.x = a; t.y = b;
    return *(uint32_t*)&t;
}

// ======================= LayerNorm -> TB layout ============================
__global__ __launch_bounds__(256) void ln_kernel(const float* __restrict__ x,
                                                 const float* __restrict__ g,
                                                 const float* __restrict__ bp,
                                                 bf16* __restrict__ yt) {
    __shared__ float red[8];
    __shared__ float s_mean, s_rstd;
    const int row = blockIdx.x, t = threadIdx.x;
    const float* xr = x + (size_t)row * N_EMBD + t * 8;
    float v[8];
    *(float4*)&v[0] = *(const float4*)&xr[0];
    *(float4*)&v[4] = *(const float4*)&xr[4];
    float s = v[0] + v[1] + v[2] + v[3] + v[4] + v[5] + v[6] + v[7];
#pragma unroll
    for (int o = 16; o > 0; o >>= 1) s += __shfl_xor_sync(0xffffffffu, s, o);
    if ((t & 31) == 0) red[t >> 5] = s;
    __syncthreads();
    if (t == 0) {
        float tt = 0.f;
#pragma unroll
        for (int i = 0; i < 8; i++) tt += red[i];
        s_mean = tt * (1.f / N_EMBD);
    }
    __syncthreads();
    const float mu = s_mean;
    float vs = 0.f;
#pragma unroll
    for (int k = 0; k < 8; k++) { float d = v[k] - mu; vs += d * d; }
#pragma unroll
    for (int o = 16; o > 0; o >>= 1) vs += __shfl_xor_sync(0xffffffffu, vs, o);
    if ((t & 31) == 0) red[t >> 5] = vs;
    __syncthreads();
    if (t == 0) {
        float tt = 0.f;
#pragma unroll
        for (int i = 0; i < 8; i++) tt += red[i];
        s_rstd = rsqrtf(tt * (1.f / N_EMBD) + 1e-5f);
    }
    __syncthreads();
    const float rstd = s_rstd;
    float gg[8], bb[8];
    *(float4*)&gg[0] = *(const float4*)&g[t * 8];
    *(float4*)&gg[4] = *(const float4*)&g[t * 8 + 4];
    *(float4*)&bb[0] = *(const float4*)&bp[t * 8];
    *(float4*)&bb[4] = *(const float4*)&bp[t * 8 + 4];
    bf16 hi[8], lo[8];
#pragma unroll
    for (int k = 0; k < 8; k++) {
        const float val = (v[k] - mu) * rstd * gg[k] + bb[k];
        split2(val, hi[k], lo[k]);
    }
    uint4 H, L;
    H.x = pack2(hi[0], hi[1]); H.y = pack2(hi[2], hi[3]);
    H.z = pack2(hi[4], hi[5]); H.w = pack2(hi[6], hi[7]);
    L.x = pack2(lo[0], lo[1]); L.y = pack2(lo[2], lo[3]);
    L.z = pack2(lo[4], lo[5]); L.w = pack2(lo[6], lo[7]);
    const int mblk = row >> 7, rl = row & 127, c = t >> 2, su = t & 3;
    char* base = (char*)yt + (((size_t)(mblk * 64 + c)) << 14);
    *(uint4*)(base + tb_off(rl, su))     = H;
    *(uint4*)(base + tb_off(rl, su + 4)) = L;
}

// ========== weight-norm column scales ======================================
__global__ __launch_bounds__(256) void colnorm_kernel(const float* __restrict__ v,
                                                      const float* __restrict__ g,
                                                      float* __restrict__ scale,
                                                      int rows, int cols) {
    __shared__ float red[8][32];
    const int lane = threadIdx.x & 31;
    const int r0   = threadIdx.x >> 5;
    const int j    = blockIdx.x * 32 + lane;
    float acc = 0.f;
    for (int r = r0; r < rows; r += 8) {
        float t = v[(size_t)r * cols + j];
        acc += t * t;
    }
    red[r0][lane] = acc;
    __syncthreads();
    if (r0 == 0) {
        float s = red[0][lane];
#pragma unroll
        for (int q = 1; q < 8; q++) s += red[q][lane];
        scale[j] = g[j] / sqrtf(s);
    }
}

// ========== weight conversion: fp32 (* s[k]) -> TB layout ==================
__global__ __launch_bounds__(256) void convw_kernel(const float* __restrict__ w,
                                                    const float* __restrict__ s,
                                                    bf16* __restrict__ out,
                                                    int N, int K) {
    const int n  = blockIdx.y;
    const int kg = blockIdx.x * 256 + threadIdx.x;
    const int k0 = kg * 8;
    float v[8];
    *(float4*)&v[0] = *(const float4*)&w[(size_t)n * K + k0];
    *(float4*)&v[4] = *(const float4*)&w[(size_t)n * K + k0 + 4];
    if (s) {
#pragma unroll
        for (int k = 0; k < 8; k++) v[k] *= s[k0 + k];
    }
    bf16 hi[8], lo[8];
#pragma unroll
    for (int k = 0; k < 8; k++) split2(v[k], hi[k], lo[k]);
    uint4 H, L;
    H.x = pack2(hi[0], hi[1]); H.y = pack2(hi[2], hi[3]);
    H.z = pack2(hi[4], hi[5]); H.w = pack2(hi[6], hi[7]);
    L.x = pack2(lo[0], lo[1]); L.y = pack2(lo[2], lo[3]);
    L.z = pack2(lo[4], lo[5]); L.w = pack2(lo[6], lo[7]);
    const int nblk = n >> 7, r = n & 127, c = kg >> 2, su = kg & 3;
    char* base = (char*)out + (((size_t)(nblk * (K >> 5) + c)) << 14);
    *(uint4*)(base + tb_off(r, su))     = H;
    *(uint4*)(base + tb_off(r, su + 4)) = L;
}

// ================= HMMA split-bf16 GEMM, 128x64 tile, 3 CTAs/SM ============
// 128 threads = 4 warps (2x2), warp tile 64x32. 3-stage bulk pipeline.
// Stage: A 16KB (one TB block) + B 8KB (half TB block, 64 rows) = 24KB.
#define GSOFF 1024
#define GSTG  24576
#define GEMM_SMEM (GSOFF + 3 * GSTG)

template<bool DOGELU, bool RES, bool WF32, bool WTB, bool WQKV>
__global__ __launch_bounds__(128, 3) void tgemm(const bf16* __restrict__ A,
                                                const bf16* __restrict__ B,
                                                const float* __restrict__ bias,
                                                const float* __restrict__ res,
                                                float* __restrict__ C,
                                                bf16* __restrict__ T,
                                                int M, int N, int K) {
    extern __shared__ char sm[];
    const uint32_t sb = smem_u32(sm);
    const int tid  = threadIdx.x;
    const int lane = tid & 31;
    const int wid  = tid >> 5;
    const int warp_m = wid >> 1;    // 0..1 -> 64-row half
    const int warp_n = wid & 1;     // 0..1 -> 32-col half
    const int m0 = blockIdx.y * 128;
    const int n0 = blockIdx.x * 64;
    const int nc = K >> 5;
    const int lm = lane & 15, lq = lane >> 4, l8 = (lane >> 3) & 1, l7 = lane & 7;
    const char* Ab = (const char*)A;
    const char* Bb = (const char*)B;
    const size_t bblk = (size_t)(blockIdx.x >> 1) * nc;
    const uint32_t bhalf = (uint32_t)(blockIdx.x & 1) * 8192;

    // full[s] = sb + s*8 ; empty[s] = sb + 32 + s*8
    if (tid == 0) {
#pragma unroll
        for (int s = 0; s < 3; s++) {
            mbar_init(sb + s * 8, 1);
            mbar_init(sb + 32 + s * 8, 4);
        }
    }
    __syncthreads();
    if (tid == 0) {
#pragma unroll
        for (int s = 0; s < 3; s++) {
            const uint32_t mb = sb + s * 8;
            const uint32_t st = sb + GSOFF + s * GSTG;
            mbar_expect(mb, 24576);
            bulk_g2s(st,         Ab + (((size_t)blockIdx.y * nc + s) << 14), 16384, mb);
            bulk_g2s(st + 16384, Bb + ((bblk + s) << 14) + bhalf, 8192, mb);
        }
    }

    float acc[4][4][4];
#pragma unroll
    for (int i = 0; i < 4; i++)
#pragma unroll
        for (int j = 0; j < 4; j++)
#pragma unroll
            for (int t = 0; t < 4; t++) acc[i][j][t] = 0.f;

    for (int c = 0; c < nc; c++) {
        const int slot = c % 3;
        const int rnd  = c / 3;
        mbar_wait(sb + slot * 8, rnd & 1);
        const uint32_t st = sb + GSOFF + slot * GSTG;
#pragma unroll
        for (int s = 0; s < 2; s++) {
            uint32_t aH[4][4], aL[4][4], bH[4][2], bL[4][2];
#pragma unroll
            for (int i = 0; i < 4; i++) {
                const int rl = warp_m * 64 + lm + i * 16;
                ldsm4(aH[i][0], aH[i][1], aH[i][2], aH[i][3],
                      st + tb_off(rl, s * 2 + lq));
                ldsm4(aL[i][0], aL[i][1], aL[i][2], aL[i][3],
                      st + tb_off(rl, s * 2 + lq + 4));
            }
#pragma unroll
            for (int j2 = 0; j2 < 2; j2++) {
                const int r = warp_n * 32 + j2 * 16 + lq * 8 + l7;
                uint32_t t0, t1, t2, t3;
                ldsm4(t0, t1, t2, t3, st + 16384 + tb_off(r, s * 2 + l8));
                bH[2 * j2][0] = t0; bH[2 * j2][1] = t1;
                bH[2 * j2 + 1][0] = t2; bH[2 * j2 + 1][1] = t3;
                ldsm4(t0, t1, t2, t3, st + 16384 + tb_off(r, s * 2 + l8 + 4));
                bL[2 * j2][0] = t0; bL[2 * j2][1] = t1;
                bL[2 * j2 + 1][0] = t2; bL[2 * j2 + 1][1] = t3;
            }
#pragma unroll
            for (int i = 0; i < 4; i++)
#pragma unroll
                for (int j = 0; j < 4; j++) {
                    mma_bf16(acc[i][j], aH[i], bH[j]);
                    mma_bf16(acc[i][j], aH[i], bL[j]);
                    mma_bf16(acc[i][j], aL[i], bH[j]);
                }
        }
        if (lane == 0) mbar_arrive(sb + 32 + slot * 8);
        if (tid == 0 && c + 3 < nc) {
            mbar_wait(sb + 32 + slot * 8, rnd & 1);   // all 4 warps released
            const uint32_t mb = sb + slot * 8;
            mbar_expect(mb, 24576);
            bulk_g2s(st,         Ab + (((size_t)blockIdx.y * nc + c + 3) << 14), 16384, mb);
            bulk_g2s(st + 16384, Bb + ((bblk + c + 3) << 14) + bhalf, 8192, mb);
        }
    }

    // ---------------- epilogue ----------------
    const int r_base = m0 + warp_m * 64 + (lane >> 2);
    const int c_base = n0 + warp_n * 32 + 2 * (lane & 3);
#pragma unroll
    for (int i = 0; i < 4; i++) {
#pragma unroll
        for (int j = 0; j < 4; j++) {
            const int col = c_base + j * 8;
            const float2 bi = *(const float2*)&bias[col];
#pragma unroll
            for (int half = 0; half < 2; half++) {
                const int row = r_base + i * 16 + half * 8;
                float vx = acc[i][j][half * 2 + 0] + bi.x;
                float vy = acc[i][j][half * 2 + 1] + bi.y;
                if (DOGELU) {
                    vx = 0.5f * vx * (1.f + erff(vx * 0.70710678118654752f));
                    vy = 0.5f * vy * (1.f + erff(vy * 0.70710678118654752f));
                }
                if (RES) {
                    const float2 rv = *(const float2*)&res[(size_t)row * N + col];
                    vx += rv.x; vy += rv.y;
                }
                if (WF32) {
                    float2 o; o.x = vx; o.y = vy;
                    *(float2*)&C[(size_t)row * N + col] = o;
                }
                if (WTB) {
                    bf16 h0, h1, l0, l1;
                    split2(vx, h0, l0); split2(vy, h1, l1);
                    bf162 ph; ph.x = h0; ph.y = h1;
                    bf162 pl; pl.x = l0; pl.y = l1;
                    const int mblk = row >> 7, rl = row & 127;
                    const int cc = col >> 5, u = (col & 31) >> 3, bo = (col & 7) * 2;
                    char* base = (char*)T + (((size_t)(mblk * (N >> 5) + cc)) << 14);
                    *(bf162*)(base + tb_off(rl, u) + bo)     = ph;
                    *(bf162*)(base + tb_off(rl, u + 4) + bo) = pl;
                }
                if (WQKV) {
                    bf16 h0, h1, l0, l1;
                    split2(vx, h0, l0); split2(vy, h1, l1);
                    bf162 ph; ph.x = h0; ph.y = h1;
                    bf162 pl; pl.x = l0; pl.y = l1;
                    const int type = col >> 11, hh = (col >> 7) & 15;
                    const int bb2 = row >> 11, seq = row & 2047;
                    const int sblk = seq >> 6, rl = seq & 63;
                    const int d = col & 127, u = d >> 3, bo = (d & 7) * 2;
                    char* base = (char*)T +
                        (((size_t)((((type * 2 + bb2) * 16 + hh) * 32) + sblk)) << 15);
                    *(bf162*)(base + ab_off(rl, u) + bo)      = ph;
                    *(bf162*)(base + ab_off(rl, u + 16) + bo) = pl;
                }
            }
        }
    }
}

// ============== HMMA split-bf16 flash attention ============================
// CTA: 128 queries x one head, 8 warps (2/SMSP). Q/K/V in AB layout.
// smem: Q 64KB (two 32KB blocks); KV 2 stages x 64KB; full/empty barriers.
#define ASQ   1024
#define ASKV  (1024 + 65536)
#define ASTG  65536
#define ATT_SMEM (1024 + 65536 + 2 * 65536)
#define SOFTSC 0.1275174048f /* (1/sqrt(128)) * log2(e) */

__global__ __launch_bounds__(256) void attn_mma(const bf16* __restrict__ qt,
                                                bf16* __restrict__ aout) {
    extern __shared__ char sm[];
    const uint32_t sb = smem_u32(sm);
    const int tid  = threadIdx.x;
    const int lane = tid & 31;
    const int wid  = tid >> 5;
    const int qb   = blockIdx.x * 128;
    const int h    = blockIdx.y;
    const int b    = blockIdx.z;
    const int q0   = wid * 16;
    const int lm = lane & 15, lq = lane >> 4, l8 = (lane >> 3) & 1, l7 = lane & 7;
    const char* qbase = (const char*)qt;

    auto blk = [&](int type, int sblk) -> const char* {
        return qbase + (((size_t)(((type * 2 + b) * 16 + h) * 32 + sblk)) << 15);
    };

    // barriers: qfull=sb+0; kfull[s]=sb+8+s*8; kempty[s]=sb+24+s*8
    if (tid == 0) {
        mbar_init(sb + 0, 1);
        mbar_init(sb + 8, 1);
        mbar_init(sb + 16, 1);
        mbar_init(sb + 24, 8);
        mbar_init(sb + 32, 8);
    }
    __syncthreads();
    if (tid == 0) {
        mbar_expect(sb + 0, 65536);
        bulk_g2s(sb + ASQ,          blk(0, (qb >> 6) + 0), 32768, sb + 0);
        bulk_g2s(sb + ASQ + 32768,  blk(0, (qb >> 6) + 1), 32768, sb + 0);
        mbar_expect(sb + 8, 65536);
        bulk_g2s(sb + ASKV,          blk(1, 0), 32768, sb + 8);
        bulk_g2s(sb + ASKV + 32768,  blk(2, 0), 32768, sb + 8);
        mbar_expect(sb + 16, 65536);
        bulk_g2s(sb + ASKV + ASTG,          blk(1, 1), 32768, sb + 16);
        bulk_g2s(sb + ASKV + ASTG + 32768,  blk(2, 1), 32768, sb + 16);
    }

    float m0 = -1e30f, m1 = -1e30f, l0 = 0.f, l1 = 0.f;
    float O[16][4];
#pragma unroll
    for (int f = 0; f < 16; f++)
#pragma unroll
        for (int c = 0; c < 4; c++) O[f][c] = 0.f;

    mbar_wait(sb + 0, 0);   // Q ready

    const int qr = q0 + lm;
    const uint32_t qblk = sb + ASQ + ((uint32_t)(qr >> 6) << 15);
    const int qrl = qr & 63;

    for (int it = 0; it < 32; it++) {
        const int slot = it & 1;
        const int rnd  = it >> 1;
        mbar_wait(sb + 8 + slot * 8, rnd & 1);
        const uint32_t kvb = sb + ASKV + slot * ASTG;

        // ---- S = Q K^T (3-term split, log2 domain) ----
        float s[8][4];
#pragma unroll
        for (int j = 0; j < 8; j++)
#pragma unroll
            for (int c = 0; c < 4; c++) s[j][c] = 0.f;

#pragma unroll
        for (int kd = 0; kd < 8; kd++) {
            uint32_t aH[4], aL[4];
            ldsm4(aH[0], aH[1], aH[2], aH[3], qblk + ab_off(qrl, kd * 2 + lq));
            ldsm4(aL[0], aL[1], aL[2], aL[3], qblk + ab_off(qrl, kd * 2 + lq + 16));
#pragma unroll
            for (int kg = 0; kg < 4; kg++) {
                const int kr = kg * 16 + lq * 8 + l7;
                uint32_t t0, t1, t2, t3;
                uint32_t bh0[2], bh1[2], bl0[2], bl1[2];
                ldsm4(t0, t1, t2, t3, kvb + ab_off(kr, kd * 2 + l8));
                bh0[0] = t0; bh0[1] = t1; bh1[0] = t2; bh1[1] = t3;
                ldsm4(t0, t1, t2, t3, kvb + ab_off(kr, kd * 2 + l8 + 16));
                bl0[0] = t0; bl0[1] = t1; bl1[0] = t2; bl1[1] = t3;
                mma_bf16(s[2 * kg],     aH, bh0);
                mma_bf16(s[2 * kg],     aH, bl0);
                mma_bf16(s[2 * kg],     aL, bh0);
                mma_bf16(s[2 * kg + 1], aH, bh1);
                mma_bf16(s[2 * kg + 1], aH, bl1);
                mma_bf16(s[2 * kg + 1], aL, bh1);
            }
        }

        // ---- online softmax (registers) ----
        float mt0 = -1e30f, mt1 = -1e30f;
#pragma unroll
        for (int j = 0; j < 8; j++) {
#pragma unroll
            for (int c = 0; c < 4; c++) s[j][c] *= SOFTSC;
            mt0 = fmaxf(mt0, fmaxf(s[j][0], s[j][1]));
            mt1 = fmaxf(mt1, fmaxf(s[j][2], s[j][3]));
        }
        mt0 = fmaxf(mt0, __shfl_xor_sync(0xffffffffu, mt0, 1));
        mt0 = fmaxf(mt0, __shfl_xor_sync(0xffffffffu, mt0, 2));
        mt1 = fmaxf(mt1, __shfl_xor_sync(0xffffffffu, mt1, 1));
        mt1 = fmaxf(mt1, __shfl_xor_sync(0xffffffffu, mt1, 2));
        const float mn0 = fmaxf(m0, mt0), mn1 = fmaxf(m1, mt1);
        const float corr0 = ex2f(m0 - mn0), corr1 = ex2f(m1 - mn1);
        m0 = mn0; m1 = mn1;
        float ps0 = 0.f, ps1 = 0.f;
#pragma unroll
        for (int j = 0; j < 8; j++) {
            s[j][0] = ex2f(s[j][0] - mn0);
            s[j][1] = ex2f(s[j][1] - mn0);
            s[j][2] = ex2f(s[j][2] - mn1);
            s[j][3] = ex2f(s[j][3] - mn1);
            ps0 += s[j][0] + s[j][1];
            ps1 += s[j][2] + s[j][3];
        }
        l0 = l0 * corr0 + ps0;
        l1 = l1 * corr1 + ps1;
#pragma unroll
        for (int f = 0; f < 16; f++) {
            O[f][0] *= corr0; O[f][1] *= corr0;
            O[f][2] *= corr1; O[f][3] *= corr1;
        }

        // ---- O += P V ----
#pragma unroll
        for (int kk = 0; kk < 4; kk++) {
            const int j0 = 2 * kk, j1 = 2 * kk + 1;
            uint32_t pH[4], pL[4];
            {
                uint32_t hi;
                bf162 hv;
                float la, lb;
                hi = packbf(s[j0][0], s[j0][1]); hv = *(bf162*)&hi;
                la = s[j0][0] - __bfloat162float(hv.x);
                lb = s[j0][1] - __bfloat162float(hv.y);
                pH[0] = hi; pL[0] = packbf(la, lb);
                hi = packbf(s[j0][2], s[j0][3]); hv = *(bf162*)&hi;
                la = s[j0][2] - __bfloat162float(hv.x);
                lb = s[j0][3] - __bfloat162float(hv.y);
                pH[1] = hi; pL[1] = packbf(la, lb);
                hi = packbf(s[j1][0], s[j1][1]); hv = *(bf162*)&hi;
                la = s[j1][0] - __bfloat162float(hv.x);
                lb = s[j1][1] - __bfloat162float(hv.y);
                pH[2] = hi; pL[2] = packbf(la, lb);
                hi = packbf(s[j1][2], s[j1][3]); hv = *(bf162*)&hi;
                la = s[j1][2] - __bfloat162float(hv.x);
                lb = s[j1][3] - __bfloat162float(hv.y);
                pH[3] = hi; pL[3] = packbf(la, lb);
            }
#pragma unroll
            for (int g = 0; g < 8; g++) {
                const int vr = kk * 16 + l8 * 8 + l7;
                uint32_t t0, t1, t2, t3;
                uint32_t bh0[2], bh1[2], bl0[2], bl1[2];
                ldsm4t(t0, t1, t2, t3, kvb + 32768 + ab_off(vr, g * 2 + lq));
                bh0[0] = t0; bh0[1] = t1; bh1[0] = t2; bh1[1] = t3;
                ldsm4t(t0, t1, t2, t3, kvb + 32768 + ab_off(vr, g * 2 + lq + 16));
                bl0[0] = t0; bl0[1] = t1; bl1[0] = t2; bl1[1] = t3;
                mma_bf16(O[2 * g],     pH, bh0);
                mma_bf16(O[2 * g],     pH, bl0);
                mma_bf16(O[2 * g],     pL, bh0);
                mma_bf16(O[2 * g + 1], pH, bh1);
                mma_bf16(O[2 * g + 1], pH, bl1);
                mma_bf16(O[2 * g + 1], pL, bh1);
            }
        }
        // K/V fragments consumed by MMAs above -> release stage
        if (lane == 0) mbar_arrive(sb + 24 + slot * 8);
        if (tid == 0 && it + 2 < 32) {
            mbar_wait(sb + 24 + slot * 8, rnd & 1);
            const uint32_t mb = sb + 8 + slot * 8;
            const uint32_t dst = sb + ASKV + slot * ASTG;
            mbar_expect(mb, 65536);
            bulk_g2s(dst,         blk(1, it + 2), 32768, mb);
            bulk_g2s(dst + 32768, blk(2, it + 2), 32768, mb);
        }
    }

    // ---- finalize: normalize, split, store to TB layout ----
    l0 += __shfl_xor_sync(0xffffffffu, l0, 1);
    l0 += __shfl_xor_sync(0xffffffffu, l0, 2);
    l1 += __shfl_xor_sync(0xffffffffu, l1, 1);
    l1 += __shfl_xor_sync(0xffffffffu, l1, 2);
    const float inv0 = 1.f / l0, inv1 = 1.f / l1;
    const int r0g = b * SEQ + qb + q0 + (lane >> 2);
    const int r1g = r0g + 8;
    const int col0 = h * HEAD_DIM + 2 * (lane & 3);
    char* ga = (char*)aout;
#pragma unroll
    for (int f = 0; f < 16; f++) {
        const int col = col0 + f * 8;
        const int c = col >> 5, u = (col & 31) >> 3, bo = (col & 7) * 2;
#pragma unroll
        for (int half = 0; half < 2; half++) {
            const int row = half ? r1g : r0g;
            const float inv = half ? inv1 : inv0;
            const float vx = O[f][half * 2 + 0] * inv;
            const float vy = O[f][half * 2 + 1] * inv;
            bf16 h0, h1, lo0, lo1;
            split2(vx, h0, lo0); split2(vy, h1, lo1);
            bf162 ph; ph.x = h0; ph.y = h1;
            bf162 pl; pl.x = lo0; pl.y = lo1;
            const int mblk = row >> 7, rl = row & 127;
            char* base = ga + (((size_t)(mblk * 64 + c)) << 14);
            *(bf162*)(base + tb_off(rl, u) + bo)     = ph;
            *(bf162*)(base + tb_off(rl, u + 4) + bo) = pl;
        }
    }
}

// =========================== launch sequence ===============================
extern "C" void kernel_launch(void* const* d_in, const int* in_sizes, int n_in,
                              void* d_out, int out_size) {
    const float* hs      = (const float*)d_in[0];
    const float* ln1_g   = (const float*)d_in[1];
    const float* ln1_b   = (const float*)d_in[2];
    const float* w_qkv   = (const float*)d_in[3];
    const float* b_qkv   = (const float*)d_in[4];
    const float* attn_v  = (const float*)d_in[5];
    const float* attn_g  = (const float*)d_in[6];
    const float* attn_b  = (const float*)d_in[7];
    /* d_in[8] = emotion_bias: softmax-invariant, unused */
    const float* ln2_g   = (const float*)d_in[9];
    const float* ln2_b   = (const float*)d_in[10];
    const float* w_fc    = (const float*)d_in[11];
    const float* b_fc    = (const float*)d_in[12];
    const float* mlp_v   = (const float*)d_in[13];
    const float* mlp_g   = (const float*)d_in[14];
    const float* mlp_b   = (const float*)d_in[15];
    float* out = (float*)d_out;

    float *hid, *sA, *sM;
    bf16 *xt, *ft, *at, *qt, *wq, *wp, *wf, *wm;
    cudaGetSymbolAddress((void**)&hid, g_hid);
    cudaGetSymbolAddress((void**)&sA,  g_sA);
    cudaGetSymbolAddress((void**)&sM,  g_sM);
    cudaGetSymbolAddress((void**)&xt,  g_x);
    cudaGetSymbolAddress((void**)&ft,  g_f);
    cudaGetSymbolAddress((void**)&at,  g_a);
    cudaGetSymbolAddress((void**)&qt,  g_qt);
    cudaGetSymbolAddress((void**)&wq,  g_wq);
    cudaGetSymbolAddress((void**)&wp,  g_wp);
    cudaGetSymbolAddress((void**)&wf,  g_wf);
    cudaGetSymbolAddress((void**)&wm,  g_wm);

    cudaFuncSetAttribute(attn_mma,
                         cudaFuncAttributeMaxDynamicSharedMemorySize, ATT_SMEM);
    cudaFuncSetAttribute(tgemm<false, false, false, false, true>,
                         cudaFuncAttributeMaxDynamicSharedMemorySize, GEMM_SMEM);
    cudaFuncSetAttribute(tgemm<false, true, true, false, false>,
                         cudaFuncAttributeMaxDynamicSharedMemorySize, GEMM_SMEM);
    cudaFuncSetAttribute(tgemm<true, false, false, true, false>,
                         cudaFuncAttributeMaxDynamicSharedMemorySize, GEMM_SMEM);

    // 0: LN1 -> TB
    ln_kernel<<<ROWS, 256>>>(hs, ln1_g, ln1_b, xt);
    // 1: convw w_qkv -> TB
    convw_kernel<<<dim3(1, QKV_W), 256>>>(w_qkv, nullptr, wq, QKV_W, N_EMBD);
    // 2: colnorm attn proj
    colnorm_kernel<<<N_EMBD / 32, 256>>>(attn_v, attn_g, sA, N_EMBD, N_EMBD);
    // 3: QKV GEMM -> AB layout   (ncu capture target)
    tgemm<false, false, false, false, true>
        <<<dim3(QKV_W / 64, ROWS / 128), 128, GEMM_SMEM>>>(
        xt, wq, b_qkv, nullptr, nullptr, qt, ROWS, QKV_W, N_EMBD);
    // 4: attention -> TB
    attn_mma<<<dim3(SEQ / 128, N_HEAD, BATCH), 256, ATT_SMEM>>>(qt, at);
    // 5: convw attn proj (wn-folded) -> TB
    convw_kernel<<<dim3(1, N_EMBD), 256>>>(attn_v, sA, wp, N_EMBD, N_EMBD);
    // 6: attn proj + residual(hs) -> hid fp32
    tgemm<false, true, true, false, false>
        <<<dim3(N_EMBD / 64, ROWS / 128), 128, GEMM_SMEM>>>(
        at, wp, attn_b, hs, hid, nullptr, ROWS, N_EMBD, N_EMBD);
    // 7: LN2 -> TB
    ln_kernel<<<ROWS, 256>>>(hid, ln2_g, ln2_b, xt);
    // 8: convw w_fc -> TB
    convw_kernel<<<dim3(1, N_INNER), 256>>>(w_fc, nullptr, wf, N_INNER, N_EMBD);
    // 9: FC + GELU -> TB
    tgemm<true, false, false, true, false>
        <<<dim3(N_INNER / 64, ROWS / 128), 128, GEMM_SMEM>>>(
        xt, wf, b_fc, nullptr, nullptr, ft, ROWS, N_INNER, N_EMBD);
    // 10: colnorm mlp proj
    colnorm_kernel<<<N_INNER / 32, 256>>>(mlp_v, mlp_g, sM, N_EMBD, N_INNER);
    // 11: convw mlp proj (wn-folded) -> TB (K = N_INNER)
    convw_kernel<<<dim3(N_INNER / 2048, N_EMBD), 256>>>(mlp_v, sM, wm, N_EMBD, N_INNER);
    // 12: MLP proj + residual(hid) -> out fp32
    tgemm<false, true, true, false, false>
        <<<dim3(N_EMBD / 64, ROWS / 128), 128, GEMM_SMEM>>>(
        ft, wm, mlp_b, hid, out, nullptr, ROWS, N_EMBD, N_INNER);
}

// round 14
// speedup vs baseline: 6.2752x; 1.5264x over previous
#include <cuda_runtime.h>
#include <cuda_bf16.h>
#include <math.h>
#include <stdint.h>

// ---------------- problem constants ----------------
#define N_EMBD   2048
#define N_HEAD   16
#define HEAD_DIM 128
#define N_INNER  8192
#define SEQ      2048
#define BATCH    2
#define ROWS     (BATCH*SEQ)     /* 4096 */
#define QKV_W    (3*N_EMBD)      /* 6144 */

typedef __nv_bfloat16 bf16;
typedef __nv_bfloat162 bf162;

// ---------------- scratch (device globals; no allocs allowed) --------------
// TB  (bf16): [rowblk128][kchunk32] 16KB blocks; row=128B=[hi 64B|lo 64B],
//   16B unit u at r*128 + ((u^(r&7))<<4)  (u0..3 hi, 4..7 lo)
// TB8 (int8): [rowblk128][kchunk64] 16KB blocks; row=128B=[hi 64B|lo 64B],
//   same swizzle (u0..3 = hi k0..63, u4..7 = lo)
// AB  (bf16 attention): [type][b][h][seqblk64] 32KB blocks; row=512B,
//   unit u at r*512 + ((u^(r&7))<<4)  (u0..15 hi, 16..31 lo)
__device__ __align__(256) int8_t g_x8 [(size_t)ROWS * N_EMBD * 2];
__device__ __align__(256) int8_t g_a8 [(size_t)ROWS * N_EMBD * 2];
__device__ __align__(256) int8_t g_f8 [(size_t)ROWS * N_INNER * 2];
__device__ __align__(256) int8_t g_wq8[(size_t)QKV_W * N_EMBD * 2];
__device__ __align__(256) int8_t g_wp8[(size_t)N_EMBD * N_EMBD * 2];
__device__ __align__(256) int8_t g_wf8[(size_t)N_INNER * N_EMBD * 2];
__device__ __align__(256) int8_t g_wm8[(size_t)N_EMBD * N_INNER * 2];
__device__ __align__(256) bf16   g_a  [(size_t)ROWS * N_EMBD * 2];   // bf16 TB
__device__ __align__(256) bf16   g_f  [(size_t)ROWS * N_INNER * 2];  // bf16 TB
__device__ __align__(256) bf16   g_qt [(size_t)3 * BATCH * N_HEAD * 32 * 16384];
__device__ float g_hid[(size_t)ROWS * N_EMBD];
__device__ float g_sA [N_EMBD];
__device__ float g_sM [N_INNER];
__device__ float g_sx [ROWS];
__device__ float g_sa [ROWS];
__device__ float g_sf [ROWS];
__device__ float g_swq[QKV_W];
__device__ float g_swp[N_EMBD];
__device__ float g_swf[N_INNER];
__device__ float g_swm[N_EMBD];
__device__ float g_rma[ROWS];
__device__ float g_rmf[ROWS];

// ========================= helpers =========================================
__device__ __forceinline__ uint32_t smem_u32(const void* p) {
    uint32_t a;
    asm("{ .reg .u64 t; cvta.to.shared.u64 t, %1; cvt.u32.u64 %0, t; }"
        : "=r"(a) : "l"(p));
    return a;
}
__device__ __forceinline__ uint32_t tb_off(int r, int u) {
    return (uint32_t)(r * 128 + ((u ^ (r & 7)) << 4));
}
__device__ __forceinline__ uint32_t ab_off(int r, int u) {
    return (uint32_t)(r * 512 + ((u ^ (r & 7)) << 4));
}
__device__ __forceinline__ void mbar_init(uint32_t m, uint32_t cnt) {
    asm volatile("mbarrier.init.shared.b64 [%0], %1;" :: "r"(m), "r"(cnt) : "memory");
}
__device__ __forceinline__ void mbar_expect(uint32_t m, uint32_t bytes) {
    asm volatile("mbarrier.arrive.expect_tx.shared.b64 _, [%0], %1;"
                 :: "r"(m), "r"(bytes) : "memory");
}
__device__ __forceinline__ void mbar_arrive(uint32_t m) {
    asm volatile("mbarrier.arrive.shared.b64 _, [%0];" :: "r"(m) : "memory");
}
__device__ __forceinline__ void mbar_wait(uint32_t m, uint32_t parity) {
    asm volatile(
        "{\n\t.reg .pred P;\n\t"
        "W_%=:\n\t"
        "mbarrier.try_wait.parity.shared.b64 P, [%0], %1;\n\t"
        "@!P bra W_%=;\n\t}"
        :: "r"(m), "r"(parity) : "memory");
}
__device__ __forceinline__ void bulk_g2s(uint32_t dst, const void* src,
                                         uint32_t bytes, uint32_t mbar) {
    asm volatile(
        "cp.async.bulk.shared::cluster.global.mbarrier::complete_tx::bytes "
        "[%0], [%1], %2, [%3];"
        :: "r"(dst), "l"(src), "r"(bytes), "r"(mbar) : "memory");
}
__device__ __forceinline__ void ldsm4(uint32_t& r0, uint32_t& r1,
                                      uint32_t& r2, uint32_t& r3, uint32_t addr) {
    asm volatile("ldmatrix.sync.aligned.m8n8.x4.shared.b16 {%0,%1,%2,%3}, [%4];"
                 : "=r"(r0), "=r"(r1), "=r"(r2), "=r"(r3) : "r"(addr));
}
__device__ __forceinline__ void ldsm4t(uint32_t& r0, uint32_t& r1,
                                       uint32_t& r2, uint32_t& r3, uint32_t addr) {
    asm volatile("ldmatrix.sync.aligned.m8n8.x4.trans.shared.b16 {%0,%1,%2,%3}, [%4];"
                 : "=r"(r0), "=r"(r1), "=r"(r2), "=r"(r3) : "r"(addr));
}
__device__ __forceinline__ void mma_bf16(float* c, const uint32_t* a,
                                         const uint32_t* b) {
    asm volatile(
        "mma.sync.aligned.m16n8k16.row.col.f32.bf16.bf16.f32 "
        "{%0,%1,%2,%3}, {%4,%5,%6,%7}, {%8,%9}, {%0,%1,%2,%3};"
        : "+f"(c[0]), "+f"(c[1]), "+f"(c[2]), "+f"(c[3])
        : "r"(a[0]), "r"(a[1]), "r"(a[2]), "r"(a[3]), "r"(b[0]), "r"(b[1]));
}
__device__ __forceinline__ void mma_s8(int* c, const uint32_t* a,
                                       const uint32_t* b) {
    asm volatile(
        "mma.sync.aligned.m16n8k32.row.col.s32.s8.s8.s32 "
        "{%0,%1,%2,%3}, {%4,%5,%6,%7}, {%8,%9}, {%0,%1,%2,%3};"
        : "+r"(c[0]), "+r"(c[1]), "+r"(c[2]), "+r"(c[3])
        : "r"(a[0]), "r"(a[1]), "r"(a[2]), "r"(a[3]), "r"(b[0]), "r"(b[1]));
}
__device__ __forceinline__ float ex2f(float x) {
    float y;
    asm("ex2.approx.f32 %0, %1;" : "=f"(y) : "f"(x));
    return y;
}
__device__ __forceinline__ void split2(float x, bf16& h, bf16& l) {
    h = __float2bfloat16(x);
    l = __float2bfloat16(x - __bfloat162float(h));
}
__device__ __forceinline__ uint32_t packbf(float a, float b) {
    bf162 t = __floats2bfloat162_rn(a, b);
    return *(uint32_t*)&t;
}
__device__ __forceinline__ uint32_t packs8(int a, int b, int c, int d) {
    return (uint32_t)(a & 255) | ((uint32_t)(b & 255) << 8) |
           ((uint32_t)(c & 255) << 16) | ((uint32_t)(d & 255) << 24);
}
__device__ __forceinline__ void quant2(float x, float inv, int& qh, int& ql) {
    const float xh = x * inv;                 // |xh| <= 127
    qh = __float2int_rn(xh);
    ql = __float2int_rn((xh - (float)qh) * 254.f);
}
// block-wide max over 256 threads
__device__ __forceinline__ float blockmax256(float v, float* red, int t) {
#pragma unroll
    for (int o = 16; o > 0; o >>= 1) v = fmaxf(v, __shfl_xor_sync(0xffffffffu, v, o));
    if ((t & 31) == 0) red[t >> 5] = v;
    __syncthreads();
    float m = red[0];
#pragma unroll
    for (int i = 1; i < 8; i++) m = fmaxf(m, red[i]);
    return m;
}

// ======================= zero helper (replaces cudaMemsetAsync) ============
__global__ __launch_bounds__(256) void zero_kernel(float* a, float* b) {
    const int i = blockIdx.x * 256 + threadIdx.x;
    if (i < ROWS) { a[i] = 0.f; b[i] = 0.f; }
}

// ======================= LayerNorm -> int8 TB8 + scale =====================
__global__ __launch_bounds__(256) void ln8_kernel(const float* __restrict__ x,
                                                  const float* __restrict__ g,
                                                  const float* __restrict__ bp,
                                                  int8_t* __restrict__ yt,
                                                  float* __restrict__ sArr) {
    __shared__ float red[8];
    __shared__ float s_mean, s_rstd;
    const int row = blockIdx.x, t = threadIdx.x;
    const float* xr = x + (size_t)row * N_EMBD + t * 8;
    float v[8];
    *(float4*)&v[0] = *(const float4*)&xr[0];
    *(float4*)&v[4] = *(const float4*)&xr[4];
    float s = v[0] + v[1] + v[2] + v[3] + v[4] + v[5] + v[6] + v[7];
#pragma unroll
    for (int o = 16; o > 0; o >>= 1) s += __shfl_xor_sync(0xffffffffu, s, o);
    if ((t & 31) == 0) red[t >> 5] = s;
    __syncthreads();
    if (t == 0) {
        float tt = 0.f;
#pragma unroll
        for (int i = 0; i < 8; i++) tt += red[i];
        s_mean = tt * (1.f / N_EMBD);
    }
    __syncthreads();
    const float mu = s_mean;
    float vs = 0.f;
#pragma unroll
    for (int k = 0; k < 8; k++) { float d = v[k] - mu; vs += d * d; }
#pragma unroll
    for (int o = 16; o > 0; o >>= 1) vs += __shfl_xor_sync(0xffffffffu, vs, o);
    if ((t & 31) == 0) red[t >> 5] = vs;
    __syncthreads();
    if (t == 0) {
        float tt = 0.f;
#pragma unroll
        for (int i = 0; i < 8; i++) tt += red[i];
        s_rstd = rsqrtf(tt * (1.f / N_EMBD) + 1e-5f);
    }
    __syncthreads();
    const float rstd = s_rstd;
    float gg[8], bb[8];
    *(float4*)&gg[0] = *(const float4*)&g[t * 8];
    *(float4*)&gg[4] = *(const float4*)&g[t * 8 + 4];
    *(float4*)&bb[0] = *(const float4*)&bp[t * 8];
    *(float4*)&bb[4] = *(const float4*)&bp[t * 8 + 4];
    float val[8];
    float mx = 0.f;
#pragma unroll
    for (int k = 0; k < 8; k++) {
        val[k] = (v[k] - mu) * rstd * gg[k] + bb[k];
        mx = fmaxf(mx, fabsf(val[k]));
    }
    __syncthreads();   // red[] reuse
    const float gmax = fmaxf(blockmax256(mx, red, t), 1e-20f);
    const float inv = 127.f / gmax;
    if (t == 0) sArr[row] = gmax * (1.f / 127.f);
    int qh[8], ql[8];
#pragma unroll
    for (int k = 0; k < 8; k++) quant2(val[k], inv, qh[k], ql[k]);
    uint2 H, L;
    H.x = packs8(qh[0], qh[1], qh[2], qh[3]);
    H.y = packs8(qh[4], qh[5], qh[6], qh[7]);
    L.x = packs8(ql[0], ql[1], ql[2], ql[3]);
    L.y = packs8(ql[4], ql[5], ql[6], ql[7]);
    const int mblk = row >> 7, rl = row & 127;
    const int c = t >> 3, u = (t >> 1) & 3, intra = (t & 1) * 8;
    char* base = (char*)yt + (((size_t)(mblk * 32 + c)) << 14);
    *(uint2*)(base + tb_off(rl, u) + intra)     = H;
    *(uint2*)(base + tb_off(rl, u + 4) + intra) = L;
}

// ========== weight-norm column scales ======================================
__global__ __launch_bounds__(256) void colnorm_kernel(const float* __restrict__ v,
                                                      const float* __restrict__ g,
                                                      float* __restrict__ scale,
                                                      int rows, int cols) {
    __shared__ float red[8][32];
    const int lane = threadIdx.x & 31;
    const int r0   = threadIdx.x >> 5;
    const int j    = blockIdx.x * 32 + lane;
    float acc = 0.f;
    for (int r = r0; r < rows; r += 8) {
        float t = v[(size_t)r * cols + j];
        acc += t * t;
    }
    red[r0][lane] = acc;
    __syncthreads();
    if (r0 == 0) {
        float s = red[0][lane];
#pragma unroll
        for (int q = 1; q < 8; q++) s += red[q][lane];
        scale[j] = g[j] / sqrtf(s);
    }
}

// ========== weight conversion: fp32 (* s[k]) -> int8 TB8 + scale ===========
__global__ __launch_bounds__(256) void convw8_kernel(const float* __restrict__ w,
                                                     const float* __restrict__ s,
                                                     int8_t* __restrict__ out,
                                                     float* __restrict__ sArr,
                                                     int K) {
    __shared__ float red[8];
    const int n = blockIdx.x, t = threadIdx.x;
    const int groups = K >> 11;          // 1 or 4
    float val[32];
    float mx = 0.f;
    for (int gq = 0; gq < groups; gq++) {
        const int k = gq * 2048 + t * 8;
        float vv[8];
        *(float4*)&vv[0] = *(const float4*)&w[(size_t)n * K + k];
        *(float4*)&vv[4] = *(const float4*)&w[(size_t)n * K + k + 4];
        if (s) {
#pragma unroll
            for (int q = 0; q < 8; q++) vv[q] *= s[k + q];
        }
#pragma unroll
        for (int q = 0; q < 8; q++) {
            val[gq * 8 + q] = vv[q];
            mx = fmaxf(mx, fabsf(vv[q]));
        }
    }
    const float gmax = fmaxf(blockmax256(mx, red, t), 1e-20f);
    const float inv = 127.f / gmax;
    if (t == 0) sArr[n] = gmax * (1.f / 127.f);
    const int nblk = n >> 7, rl = n & 127, nc = K >> 6;
    for (int gq = 0; gq < groups; gq++) {
        const int k = gq * 2048 + t * 8;
        int qh[8], ql[8];
#pragma unroll
        for (int q = 0; q < 8; q++) quant2(val[gq * 8 + q], inv, qh[q], ql[q]);
        uint2 H, L;
        H.x = packs8(qh[0], qh[1], qh[2], qh[3]);
        H.y = packs8(qh[4], qh[5], qh[6], qh[7]);
        L.x = packs8(ql[0], ql[1], ql[2], ql[3]);
        L.y = packs8(ql[4], ql[5], ql[6], ql[7]);
        const int c = k >> 6, u = (k >> 4) & 3, intra = k & 15;
        char* base = (char*)out + (((size_t)(nblk * nc + c)) << 14);
        *(uint2*)(base + tb_off(rl, u) + intra)     = H;
        *(uint2*)(base + tb_off(rl, u + 4) + intra) = L;
    }
}

// ========== convert: bf16 TB -> int8 TB8 using atomic rowmax ===============
__global__ __launch_bounds__(256) void convert8_kernel(const bf16* __restrict__ src,
                                                       int8_t* __restrict__ dst,
                                                       const float* __restrict__ rm,
                                                       float* __restrict__ sArr,
                                                       int K) {
    const int row = blockIdx.x, t = threadIdx.x;
    const int groups = K >> 11;
    const float gmax = fmaxf(rm[row], 1e-20f);
    const float inv = 127.f / gmax;
    if (t == 0) sArr[row] = gmax * (1.f / 127.f);
    const int mblk = row >> 7, rl = row & 127;
    const int nc16 = K >> 5, nc8 = K >> 6;
    for (int gq = 0; gq < groups; gq++) {
        const int k = gq * 2048 + t * 8;
        const char* sblk = (const char*)src + (((size_t)(mblk * nc16 + (k >> 5))) << 14);
        const int u16 = (k >> 3) & 3;
        uint4 Hh = *(const uint4*)(sblk + tb_off(rl, u16));
        uint4 Ll = *(const uint4*)(sblk + tb_off(rl, u16 + 4));
        const uint32_t* hw = (const uint32_t*)&Hh;
        const uint32_t* lw = (const uint32_t*)&Ll;
        int qh[8], ql[8];
#pragma unroll
        for (int q = 0; q < 4; q++) {
            bf162 hb = *(const bf162*)&hw[q];
            bf162 lb = *(const bf162*)&lw[q];
            const float v0 = __bfloat162float(hb.x) + __bfloat162float(lb.x);
            const float v1 = __bfloat162float(hb.y) + __bfloat162float(lb.y);
            quant2(v0, inv, qh[2 * q], ql[2 * q]);
            quant2(v1, inv, qh[2 * q + 1], ql[2 * q + 1]);
        }
        uint2 H, L;
        H.x = packs8(qh[0], qh[1], qh[2], qh[3]);
        H.y = packs8(qh[4], qh[5], qh[6], qh[7]);
        L.x = packs8(ql[0], ql[1], ql[2], ql[3]);
        L.y = packs8(ql[4], ql[5], ql[6], ql[7]);
        char* base = (char*)dst + (((size_t)(mblk * nc8 + (k >> 6))) << 14);
        const int u = (k >> 4) & 3, intra = k & 15;
        *(uint2*)(base + tb_off(rl, u) + intra)     = H;
        *(uint2*)(base + tb_off(rl, u + 4) + intra) = L;
    }
}

// ================= split-int8 IMMA GEMM, 128x64 tile, 2 CTAs/SM ============
// 256 thr = 8 warps (2m x 4n), warp tile 64x16. 3-stage bulk pipeline.
// Stage: A 16KB (TB8 block, k64) + B 8KB (half TB8 block) = 24KB.
// D = sA[m]*sB[n]*(accHH + accX/254) + epilogue.
#define GSOFF 1024
#define GSTG  24576
#define GEMM_SMEM (GSOFF + 3 * GSTG)

template<bool DOGELU, bool RES, bool WF32, bool WTB, bool WQKV>
__global__ __launch_bounds__(256, 2) void tgemm8(const int8_t* __restrict__ A,
                                                 const int8_t* __restrict__ B,
                                                 const float* __restrict__ sA,
                                                 const float* __restrict__ sB,
                                                 const float* __restrict__ bias,
                                                 const float* __restrict__ res,
                                                 float* __restrict__ C,
                                                 bf16* __restrict__ T,
                                                 float* __restrict__ rmax,
                                                 int M, int N, int K) {
    extern __shared__ char sm[];
    const uint32_t sb = smem_u32(sm);
    const int tid  = threadIdx.x;
    const int lane = tid & 31;
    const int wid  = tid >> 5;
    const int warp_m = wid >> 2;    // 0..1 -> 64-row half
    const int warp_n = wid & 3;     // 0..3 -> 16-col slice
    const int m0 = blockIdx.y * 128;
    const int n0 = blockIdx.x * 64;
    const int nc = K >> 6;
    const int lm = lane & 15, lq = lane >> 4, l8 = (lane >> 3) & 1, l7 = lane & 7;
    const char* Ab = (const char*)A;
    const char* Bb = (const char*)B;
    const size_t bblk = (size_t)(blockIdx.x >> 1) * nc;
    const uint32_t bhalf = (uint32_t)(blockIdx.x & 1) * 8192;

    if (tid == 0) {
#pragma unroll
        for (int s = 0; s < 3; s++) {
            mbar_init(sb + s * 8, 1);
            mbar_init(sb + 32 + s * 8, 8);
        }
    }
    __syncthreads();
    if (tid == 0) {
#pragma unroll
        for (int s = 0; s < 3; s++) {
            const uint32_t mb = sb + s * 8;
            const uint32_t st = sb + GSOFF + s * GSTG;
            mbar_expect(mb, 24576);
            bulk_g2s(st,         Ab + (((size_t)blockIdx.y * nc + s) << 14), 16384, mb);
            bulk_g2s(st + 16384, Bb + ((bblk + s) << 14) + bhalf, 8192, mb);
        }
    }

    int aH[4][2][4], aX[4][2][4];
#pragma unroll
    for (int i = 0; i < 4; i++)
#pragma unroll
        for (int j = 0; j < 2; j++)
#pragma unroll
            for (int t = 0; t < 4; t++) { aH[i][j][t] = 0; aX[i][j][t] = 0; }

    for (int c = 0; c < nc; c++) {
        const int slot = c % 3;
        const int rnd  = c / 3;
        mbar_wait(sb + slot * 8, rnd & 1);
        const uint32_t st = sb + GSOFF + slot * GSTG;
#pragma unroll
        for (int s = 0; s < 2; s++) {
            uint32_t bh[2][2], bl[2][2];
            {
                const int r = warp_n * 16 + lq * 8 + l7;
                uint32_t t0, t1, t2, t3;
                ldsm4(t0, t1, t2, t3, st + 16384 + tb_off(r, s * 2 + l8));
                bh[0][0] = t0; bh[0][1] = t1; bh[1][0] = t2; bh[1][1] = t3;
                ldsm4(t0, t1, t2, t3, st + 16384 + tb_off(r, s * 2 + l8 + 4));
                bl[0][0] = t0; bl[0][1] = t1; bl[1][0] = t2; bl[1][1] = t3;
            }
#pragma unroll
            for (int i = 0; i < 4; i++) {
                const int rl = warp_m * 64 + lm + i * 16;
                uint32_t ah[4], al[4];
                ldsm4(ah[0], ah[1], ah[2], ah[3], st + tb_off(rl, s * 2 + lq));
                ldsm4(al[0], al[1], al[2], al[3], st + tb_off(rl, s * 2 + lq + 4));
#pragma unroll
                for (int j = 0; j < 2; j++) {
                    mma_s8(aH[i][j], ah, bh[j]);
                    mma_s8(aX[i][j], ah, bl[j]);
                    mma_s8(aX[i][j], al, bh[j]);
                }
            }
        }
        if (lane == 0) mbar_arrive(sb + 32 + slot * 8);
        if (tid == 0 && c + 3 < nc) {
            mbar_wait(sb + 32 + slot * 8, rnd & 1);
            const uint32_t mb = sb + slot * 8;
            mbar_expect(mb, 24576);
            bulk_g2s(st,         Ab + (((size_t)blockIdx.y * nc + c + 3) << 14), 16384, mb);
            bulk_g2s(st + 16384, Bb + ((bblk + c + 3) << 14) + bhalf, 8192, mb);
        }
    }

    // ---------------- epilogue ----------------
    const float i254 = 1.f / 254.f;
    const int r_base = m0 + warp_m * 64 + (lane >> 2);
    const int c_base = n0 + warp_n * 16 + 2 * (lane & 3);
    float sAv[8];
#pragma unroll
    for (int i = 0; i < 4; i++) {
        sAv[2 * i]     = sA[r_base + i * 16];
        sAv[2 * i + 1] = sA[r_base + i * 16 + 8];
    }
    float rmx[8];
#pragma unroll
    for (int i = 0; i < 8; i++) rmx[i] = 0.f;
#pragma unroll
    for (int j = 0; j < 2; j++) {
        const int col = c_base + j * 8;
        const float2 bi = *(const float2*)&bias[col];
        const float2 sb2 = *(const float2*)&sB[col];
#pragma unroll
        for (int i = 0; i < 4; i++) {
#pragma unroll
            for (int half = 0; half < 2; half++) {
                const int row = r_base + i * 16 + half * 8;
                const float sa = sAv[2 * i + half];
                float vx = ((float)aH[i][j][half * 2 + 0] +
                            (float)aX[i][j][half * 2 + 0] * i254) * (sa * sb2.x) + bi.x;
                float vy = ((float)aH[i][j][half * 2 + 1] +
                            (float)aX[i][j][half * 2 + 1] * i254) * (sa * sb2.y) + bi.y;
                if (DOGELU) {
                    vx = 0.5f * vx * (1.f + erff(vx * 0.70710678118654752f));
                    vy = 0.5f * vy * (1.f + erff(vy * 0.70710678118654752f));
                }
                if (RES) {
                    const float2 rv = *(const float2*)&res[(size_t)row * N + col];
                    vx += rv.x; vy += rv.y;
                }
                if (WF32) {
                    float2 o; o.x = vx; o.y = vy;
                    *(float2*)&C[(size_t)row * N + col] = o;
                }
                if (WTB) {
                    rmx[2 * i + half] = fmaxf(rmx[2 * i + half],
                                              fmaxf(fabsf(vx), fabsf(vy)));
                    bf16 h0, h1, l0, l1;
                    split2(vx, h0, l0); split2(vy, h1, l1);
                    bf162 ph; ph.x = h0; ph.y = h1;
                    bf162 pl; pl.x = l0; pl.y = l1;
                    const int mblk = row >> 7, rl = row & 127;
                    const int cc = col >> 5, u = (col & 31) >> 3, bo = (col & 7) * 2;
                    char* base = (char*)T + (((size_t)(mblk * (N >> 5) + cc)) << 14);
                    *(bf162*)(base + tb_off(rl, u) + bo)     = ph;
                    *(bf162*)(base + tb_off(rl, u + 4) + bo) = pl;
                }
                if (WQKV) {
                    bf16 h0, h1, l0, l1;
                    split2(vx, h0, l0); split2(vy, h1, l1);
                    bf162 ph; ph.x = h0; ph.y = h1;
                    bf162 pl; pl.x = l0; pl.y = l1;
                    const int type = col >> 11, hh = (col >> 7) & 15;
                    const int bb2 = row >> 11, seq = row & 2047;
                    const int sblk = seq >> 6, rl = seq & 63;
                    const int d = col & 127, u = d >> 3, bo = (d & 7) * 2;
                    char* base = (char*)T +
                        (((size_t)((((type * 2 + bb2) * 16 + hh) * 32) + sblk)) << 15);
                    *(bf162*)(base + ab_off(rl, u) + bo)      = ph;
                    *(bf162*)(base + ab_off(rl, u + 16) + bo) = pl;
                }
            }
        }
    }
    if (WTB) {
#pragma unroll
        for (int i = 0; i < 8; i++) {
            float m = rmx[i];
            m = fmaxf(m, __shfl_xor_sync(0xffffffffu, m, 1));
            m = fmaxf(m, __shfl_xor_sync(0xffffffffu, m, 2));
            if ((lane & 3) == 0) {
                const int row = r_base + (i >> 1) * 16 + (i & 1) * 8;
                atomicMax((int*)&rmax[row], __float_as_int(m));
            }
        }
    }
}

// ============== HMMA split-bf16 flash attention (unchanged compute) ========
// CTA: 128 queries x one head, 8 warps. Q/K/V bf16 AB layout.
// Output: bf16 TB (g_a) + fp32 atomic rowmax for int8 conversion.
#define ASQ   1024
#define ASKV  (1024 + 65536)
#define ASTG  65536
#define ATT_SMEM (1024 + 65536 + 2 * 65536)
#define SOFTSC 0.1275174048f /* (1/sqrt(128)) * log2(e) */

__global__ __launch_bounds__(256) void attn_mma(const bf16* __restrict__ qt,
                                                bf16* __restrict__ aout,
                                                float* __restrict__ rmax) {
    extern __shared__ char sm[];
    const uint32_t sb = smem_u32(sm);
    const int tid  = threadIdx.x;
    const int lane = tid & 31;
    const int wid  = tid >> 5;
    const int qb   = blockIdx.x * 128;
    const int h    = blockIdx.y;
    const int b    = blockIdx.z;
    const int q0   = wid * 16;
    const int lm = lane & 15, lq = lane >> 4, l8 = (lane >> 3) & 1, l7 = lane & 7;
    const char* qbase = (const char*)qt;

    auto blk = [&](int type, int sblk) -> const char* {
        return qbase + (((size_t)(((type * 2 + b) * 16 + h) * 32 + sblk)) << 15);
    };

    if (tid == 0) {
        mbar_init(sb + 0, 1);
        mbar_init(sb + 8, 1);
        mbar_init(sb + 16, 1);
        mbar_init(sb + 24, 8);
        mbar_init(sb + 32, 8);
    }
    __syncthreads();
    if (tid == 0) {
        mbar_expect(sb + 0, 65536);
        bulk_g2s(sb + ASQ,          blk(0, (qb >> 6) + 0), 32768, sb + 0);
        bulk_g2s(sb + ASQ + 32768,  blk(0, (qb >> 6) + 1), 32768, sb + 0);
        mbar_expect(sb + 8, 65536);
        bulk_g2s(sb + ASKV,          blk(1, 0), 32768, sb + 8);
        bulk_g2s(sb + ASKV + 32768,  blk(2, 0), 32768, sb + 8);
        mbar_expect(sb + 16, 65536);
        bulk_g2s(sb + ASKV + ASTG,          blk(1, 1), 32768, sb + 16);
        bulk_g2s(sb + ASKV + ASTG + 32768,  blk(2, 1), 32768, sb + 16);
    }

    float m0 = -1e30f, m1 = -1e30f, l0 = 0.f, l1 = 0.f;
    float O[16][4];
#pragma unroll
    for (int f = 0; f < 16; f++)
#pragma unroll
        for (int c = 0; c < 4; c++) O[f][c] = 0.f;

    mbar_wait(sb + 0, 0);

    const int qr = q0 + lm;
    const uint32_t qblk = sb + ASQ + ((uint32_t)(qr >> 6) << 15);
    const int qrl = qr & 63;

    for (int it = 0; it < 32; it++) {
        const int slot = it & 1;
        const int rnd  = it >> 1;
        mbar_wait(sb + 8 + slot * 8, rnd & 1);
        const uint32_t kvb = sb + ASKV + slot * ASTG;

        float s[8][4];
#pragma unroll
        for (int j = 0; j < 8; j++)
#pragma unroll
            for (int c = 0; c < 4; c++) s[j][c] = 0.f;

#pragma unroll
        for (int kd = 0; kd < 8; kd++) {
            uint32_t aH[4], aL[4];
            ldsm4(aH[0], aH[1], aH[2], aH[3], qblk + ab_off(qrl, kd * 2 + lq));
            ldsm4(aL[0], aL[1], aL[2], aL[3], qblk + ab_off(qrl, kd * 2 + lq + 16));
#pragma unroll
            for (int kg = 0; kg < 4; kg++) {
                const int kr = kg * 16 + lq * 8 + l7;
                uint32_t t0, t1, t2, t3;
                uint32_t bh0[2], bh1[2], bl0[2], bl1[2];
                ldsm4(t0, t1, t2, t3, kvb + ab_off(kr, kd * 2 + l8));
                bh0[0] = t0; bh0[1] = t1; bh1[0] = t2; bh1[1] = t3;
                ldsm4(t0, t1, t2, t3, kvb + ab_off(kr, kd * 2 + l8 + 16));
                bl0[0] = t0; bl0[1] = t1; bl1[0] = t2; bl1[1] = t3;
                mma_bf16(s[2 * kg],     aH, bh0);
                mma_bf16(s[2 * kg],     aH, bl0);
                mma_bf16(s[2 * kg],     aL, bh0);
                mma_bf16(s[2 * kg + 1], aH, bh1);
                mma_bf16(s[2 * kg + 1], aH, bl1);
                mma_bf16(s[2 * kg + 1], aL, bh1);
            }
        }

        float mt0 = -1e30f, mt1 = -1e30f;
#pragma unroll
        for (int j = 0; j < 8; j++) {
#pragma unroll
            for (int c = 0; c < 4; c++) s[j][c] *= SOFTSC;
            mt0 = fmaxf(mt0, fmaxf(s[j][0], s[j][1]));
            mt1 = fmaxf(mt1, fmaxf(s[j][2], s[j][3]));
        }
        mt0 = fmaxf(mt0, __shfl_xor_sync(0xffffffffu, mt0, 1));
        mt0 = fmaxf(mt0, __shfl_xor_sync(0xffffffffu, mt0, 2));
        mt1 = fmaxf(mt1, __shfl_xor_sync(0xffffffffu, mt1, 1));
        mt1 = fmaxf(mt1, __shfl_xor_sync(0xffffffffu, mt1, 2));
        const float mn0 = fmaxf(m0, mt0), mn1 = fmaxf(m1, mt1);
        const float corr0 = ex2f(m0 - mn0), corr1 = ex2f(m1 - mn1);
        m0 = mn0; m1 = mn1;
        float ps0 = 0.f, ps1 = 0.f;
#pragma unroll
        for (int j = 0; j < 8; j++) {
            s[j][0] = ex2f(s[j][0] - mn0);
            s[j][1] = ex2f(s[j][1] - mn0);
            s[j][2] = ex2f(s[j][2] - mn1);
            s[j][3] = ex2f(s[j][3] - mn1);
            ps0 += s[j][0] + s[j][1];
            ps1 += s[j][2] + s[j][3];
        }
        l0 = l0 * corr0 + ps0;
        l1 = l1 * corr1 + ps1;
#pragma unroll
        for (int f = 0; f < 16; f++) {
            O[f][0] *= corr0; O[f][1] *= corr0;
            O[f][2] *= corr1; O[f][3] *= corr1;
        }

#pragma unroll
        for (int kk = 0; kk < 4; kk++) {
            const int j0 = 2 * kk, j1 = 2 * kk + 1;
            uint32_t pH[4], pL[4];
            {
                uint32_t hi;
                bf162 hv;
                float la, lb;
                hi = packbf(s[j0][0], s[j0][1]); hv = *(bf162*)&hi;
                la = s[j0][0] - __bfloat162float(hv.x);
                lb = s[j0][1] - __bfloat162float(hv.y);
                pH[0] = hi; pL[0] = packbf(la, lb);
                hi = packbf(s[j0][2], s[j0][3]); hv = *(bf162*)&hi;
                la = s[j0][2] - __bfloat162float(hv.x);
                lb = s[j0][3] - __bfloat162float(hv.y);
                pH[1] = hi; pL[1] = packbf(la, lb);
                hi = packbf(s[j1][0], s[j1][1]); hv = *(bf162*)&hi;
                la = s[j1][0] - __bfloat162float(hv.x);
                lb = s[j1][1] - __bfloat162float(hv.y);
                pH[2] = hi; pL[2] = packbf(la, lb);
                hi = packbf(s[j1][2], s[j1][3]); hv = *(bf162*)&hi;
                la = s[j1][2] - __bfloat162float(hv.x);
                lb = s[j1][3] - __bfloat162float(hv.y);
                pH[3] = hi; pL[3] = packbf(la, lb);
            }
#pragma unroll
            for (int g = 0; g < 8; g++) {
                const int vr = kk * 16 + l8 * 8 + l7;
                uint32_t t0, t1, t2, t3;
                uint32_t bh0[2], bh1[2], bl0[2], bl1[2];
                ldsm4t(t0, t1, t2, t3, kvb + 32768 + ab_off(vr, g * 2 + lq));
                bh0[0] = t0; bh0[1] = t1; bh1[0] = t2; bh1[1] = t3;
                ldsm4t(t0, t1, t2, t3, kvb + 32768 + ab_off(vr, g * 2 + lq + 16));
                bl0[0] = t0; bl0[1] = t1; bl1[0] = t2; bl1[1] = t3;
                mma_bf16(O[2 * g],     pH, bh0);
                mma_bf16(O[2 * g],     pH, bl0);
                mma_bf16(O[2 * g],     pL, bh0);
                mma_bf16(O[2 * g + 1], pH, bh1);
                mma_bf16(O[2 * g + 1], pH, bl1);
                mma_bf16(O[2 * g + 1], pL, bh1);
            }
        }
        if (lane == 0) mbar_arrive(sb + 24 + slot * 8);
        if (tid == 0 && it + 2 < 32) {
            mbar_wait(sb + 24 + slot * 8, rnd & 1);
            const uint32_t mb = sb + 8 + slot * 8;
            const uint32_t dst = sb + ASKV + slot * ASTG;
            mbar_expect(mb, 65536);
            bulk_g2s(dst,         blk(1, it + 2), 32768, mb);
            bulk_g2s(dst + 32768, blk(2, it + 2), 32768, mb);
        }
    }

    // ---- finalize: normalize, split, store bf16 TB + rowmax atomics ----
    l0 += __shfl_xor_sync(0xffffffffu, l0, 1);
    l0 += __shfl_xor_sync(0xffffffffu, l0, 2);
    l1 += __shfl_xor_sync(0xffffffffu, l1, 1);
    l1 += __shfl_xor_sync(0xffffffffu, l1, 2);
    const float inv0 = 1.f / l0, inv1 = 1.f / l1;
    const int r0g = b * SEQ + qb + q0 + (lane >> 2);
    const int r1g = r0g + 8;
    const int col0 = h * HEAD_DIM + 2 * (lane & 3);
    char* ga = (char*)aout;
    float mx0 = 0.f, mx1 = 0.f;
#pragma unroll
    for (int f = 0; f < 16; f++) {
        const int col = col0 + f * 8;
        const int c = col >> 5, u = (col & 31) >> 3, bo = (col & 7) * 2;
#pragma unroll
        for (int half = 0; half < 2; half++) {
            const int row = half ? r1g : r0g;
            const float inv = half ? inv1 : inv0;
            const float vx = O[f][half * 2 + 0] * inv;
            const float vy = O[f][half * 2 + 1] * inv;
            const float am = fmaxf(fabsf(vx), fabsf(vy));
            if (half) mx1 = fmaxf(mx1, am); else mx0 = fmaxf(mx0, am);
            bf16 h0, h1, lo0, lo1;
            split2(vx, h0, lo0); split2(vy, h1, lo1);
            bf162 ph; ph.x = h0; ph.y = h1;
            bf162 pl; pl.x = lo0; pl.y = lo1;
            const int mblk = row >> 7, rl = row & 127;
            char* base = ga + (((size_t)(mblk * 64 + c)) << 14);
            *(bf162*)(base + tb_off(rl, u) + bo)     = ph;
            *(bf162*)(base + tb_off(rl, u + 4) + bo) = pl;
        }
    }
    mx0 = fmaxf(mx0, __shfl_xor_sync(0xffffffffu, mx0, 1));
    mx0 = fmaxf(mx0, __shfl_xor_sync(0xffffffffu, mx0, 2));
    mx1 = fmaxf(mx1, __shfl_xor_sync(0xffffffffu, mx1, 1));
    mx1 = fmaxf(mx1, __shfl_xor_sync(0xffffffffu, mx1, 2));
    if ((lane & 3) == 0) {
        atomicMax((int*)&rmax[r0g], __float_as_int(mx0));
        atomicMax((int*)&rmax[r1g], __float_as_int(mx1));
    }
}

// =========================== launch sequence ===============================
extern "C" void kernel_launch(void* const* d_in, const int* in_sizes, int n_in,
                              void* d_out, int out_size) {
    const float* hs      = (const float*)d_in[0];
    const float* ln1_g   = (const float*)d_in[1];
    const float* ln1_b   = (const float*)d_in[2];
    const float* w_qkv   = (const float*)d_in[3];
    const float* b_qkv   = (const float*)d_in[4];
    const float* attn_v  = (const float*)d_in[5];
    const float* attn_g  = (const float*)d_in[6];
    const float* attn_b  = (const float*)d_in[7];
    /* d_in[8] = emotion_bias: softmax-invariant, unused */
    const float* ln2_g   = (const float*)d_in[9];
    const float* ln2_b   = (const float*)d_in[10];
    const float* w_fc    = (const float*)d_in[11];
    const float* b_fc    = (const float*)d_in[12];
    const float* mlp_v   = (const float*)d_in[13];
    const float* mlp_g   = (const float*)d_in[14];
    const float* mlp_b   = (const float*)d_in[15];
    float* out = (float*)d_out;

    float *hid, *sA, *sM, *sx, *sa, *sf, *swq, *swp, *swf, *swm, *rma, *rmf;
    int8_t *x8, *a8, *f8, *wq8, *wp8, *wf8, *wm8;
    bf16 *at, *ft, *qt;
    cudaGetSymbolAddress((void**)&hid, g_hid);
    cudaGetSymbolAddress((void**)&sA,  g_sA);
    cudaGetSymbolAddress((void**)&sM,  g_sM);
    cudaGetSymbolAddress((void**)&sx,  g_sx);
    cudaGetSymbolAddress((void**)&sa,  g_sa);
    cudaGetSymbolAddress((void**)&sf,  g_sf);
    cudaGetSymbolAddress((void**)&swq, g_swq);
    cudaGetSymbolAddress((void**)&swp, g_swp);
    cudaGetSymbolAddress((void**)&swf, g_swf);
    cudaGetSymbolAddress((void**)&swm, g_swm);
    cudaGetSymbolAddress((void**)&rma, g_rma);
    cudaGetSymbolAddress((void**)&rmf, g_rmf);
    cudaGetSymbolAddress((void**)&x8,  g_x8);
    cudaGetSymbolAddress((void**)&a8,  g_a8);
    cudaGetSymbolAddress((void**)&f8,  g_f8);
    cudaGetSymbolAddress((void**)&wq8, g_wq8);
    cudaGetSymbolAddress((void**)&wp8, g_wp8);
    cudaGetSymbolAddress((void**)&wf8, g_wf8);
    cudaGetSymbolAddress((void**)&wm8, g_wm8);
    cudaGetSymbolAddress((void**)&at,  g_a);
    cudaGetSymbolAddress((void**)&ft,  g_f);
    cudaGetSymbolAddress((void**)&qt,  g_qt);

    cudaFuncSetAttribute(attn_mma,
                         cudaFuncAttributeMaxDynamicSharedMemorySize, ATT_SMEM);
    cudaFuncSetAttribute(tgemm8<false, false, false, false, true>,
                         cudaFuncAttributeMaxDynamicSharedMemorySize, GEMM_SMEM);
    cudaFuncSetAttribute(tgemm8<false, true, true, false, false>,
                         cudaFuncAttributeMaxDynamicSharedMemorySize, GEMM_SMEM);
    cudaFuncSetAttribute(tgemm8<true, false, false, true, false>,
                         cudaFuncAttributeMaxDynamicSharedMemorySize, GEMM_SMEM);

    // zero rowmax accumulators (kernel instead of cudaMemsetAsync — fewer
    // capture-API surfaces)
    zero_kernel<<<(ROWS + 255) / 256, 256>>>(rma, rmf);

    // k1: LN1 -> int8 TB8 + scale
    ln8_kernel<<<ROWS, 256>>>(hs, ln1_g, ln1_b, x8, sx);
    // k2: convw w_qkv -> int8 TB8
    convw8_kernel<<<QKV_W, 256>>>(w_qkv, nullptr, wq8, swq, N_EMBD);
    // k3: colnorm attn proj
    colnorm_kernel<<<N_EMBD / 32, 256>>>(attn_v, attn_g, sA, N_EMBD, N_EMBD);
    // k4: QKV GEMM (int8) -> bf16 AB
    tgemm8<false, false, false, false, true>
        <<<dim3(QKV_W / 64, ROWS / 128), 256, GEMM_SMEM>>>(
        x8, wq8, sx, swq, b_qkv, nullptr, nullptr, qt, nullptr,
        ROWS, QKV_W, N_EMBD);
    // k5: attention -> bf16 TB + rowmax
    attn_mma<<<dim3(SEQ / 128, N_HEAD, BATCH), 256, ATT_SMEM>>>(qt, at, rma);
    // k6: convw attn proj (wn-folded) -> int8
    convw8_kernel<<<N_EMBD, 256>>>(attn_v, sA, wp8, swp, N_EMBD);
    // k7: convert attention output -> int8
    convert8_kernel<<<ROWS, 256>>>(at, a8, rma, sa, N_EMBD);
    // k8: attn proj + residual(hs) -> hid fp32
    tgemm8<false, true, true, false, false>
        <<<dim3(N_EMBD / 64, ROWS / 128), 256, GEMM_SMEM>>>(
        a8, wp8, sa, swp, attn_b, hs, hid, nullptr, nullptr,
        ROWS, N_EMBD, N_EMBD);
    // k9: LN2 -> int8
    ln8_kernel<<<ROWS, 256>>>(hid, ln2_g, ln2_b, x8, sx);
    // k10: convw w_fc -> int8
    convw8_kernel<<<N_INNER, 256>>>(w_fc, nullptr, wf8, swf, N_EMBD);
    // k11: FC + GELU -> bf16 TB + rowmax
    tgemm8<true, false, false, true, false>
        <<<dim3(N_INNER / 64, ROWS / 128), 256, GEMM_SMEM>>>(
        x8, wf8, sx, swf, b_fc, nullptr, nullptr, ft, rmf,
        ROWS, N_INNER, N_EMBD);
    // k12: convert gelu output -> int8
    convert8_kernel<<<ROWS, 256>>>(ft, f8, rmf, sf, N_INNER);
    // k13: colnorm mlp proj
    colnorm_kernel<<<N_INNER / 32, 256>>>(mlp_v, mlp_g, sM, N_EMBD, N_INNER);
    // k14: convw mlp proj (wn-folded, K=8192) -> int8
    convw8_kernel<<<N_EMBD, 256>>>(mlp_v, sM, wm8, swm, N_INNER);
    // k15: MLP proj + residual(hid) -> out fp32
    tgemm8<false, true, true, false, false>
        <<<dim3(N_EMBD / 64, ROWS / 128), 256, GEMM_SMEM>>>(
        f8, wm8, sf, swm, mlp_b, hid, out, nullptr, nullptr,
        ROWS, N_EMBD, N_INNER);
}

// round 15
// speedup vs baseline: 6.3880x; 1.0180x over previous
#include <cuda_runtime.h>
#include <cuda_bf16.h>
#include <math.h>
#include <stdint.h>

// ---------------- problem constants ----------------
#define N_EMBD   2048
#define N_HEAD   16
#define HEAD_DIM 128
#define N_INNER  8192
#define SEQ      2048
#define BATCH    2
#define ROWS     (BATCH*SEQ)     /* 4096 */
#define QKV_W    (3*N_EMBD)      /* 6144 */

typedef __nv_bfloat16 bf16;
typedef __nv_bfloat162 bf162;

// ---------------- scratch (device globals; no allocs allowed) --------------
// TB8 (int8): [rowblk128][kchunk64] 16KB blocks; row=128B=[hi 64B|lo 64B],
//   16B unit u at r*128 + ((u^(r&7))<<4)  (u0..3 = hi k0..63, u4..7 = lo)
// TB  (bf16): [rowblk128][kchunk32] 16KB blocks; same swizzle, u0..3 hi/u4..7 lo
// AB  (bf16 attention): [type][b][h][seqblk64] 32KB blocks; row=512B,
//   unit u at r*512 + ((u^(r&7))<<4)  (u0..15 hi, 16..31 lo)
__device__ __align__(256) int8_t g_x8 [(size_t)ROWS * N_EMBD * 2];
__device__ __align__(256) int8_t g_a8 [(size_t)ROWS * N_EMBD * 2];
__device__ __align__(256) int8_t g_f8 [(size_t)ROWS * N_INNER * 2];
__device__ __align__(256) int8_t g_wq8[(size_t)QKV_W * N_EMBD * 2];
__device__ __align__(256) int8_t g_wp8[(size_t)N_EMBD * N_EMBD * 2];
__device__ __align__(256) int8_t g_wf8[(size_t)N_INNER * N_EMBD * 2];
__device__ __align__(256) int8_t g_wm8[(size_t)N_EMBD * N_INNER * 2];
__device__ __align__(256) bf16   g_a  [(size_t)ROWS * N_EMBD * 2];   // bf16 TB
__device__ __align__(256) bf16   g_f  [(size_t)ROWS * N_INNER * 2];  // bf16 TB
__device__ __align__(256) bf16   g_qt [(size_t)3 * BATCH * N_HEAD * 32 * 16384];
__device__ float g_hid[(size_t)ROWS * N_EMBD];
__device__ float g_sA [N_EMBD];
__device__ float g_sM [N_INNER];
__device__ float g_sx [ROWS];
__device__ float g_sa [ROWS];
__device__ float g_sf [ROWS];
__device__ float g_swq[QKV_W];
__device__ float g_swp[N_EMBD];
__device__ float g_swf[N_INNER];
__device__ float g_swm[N_EMBD];
__device__ float g_rma[ROWS];
__device__ float g_rmf[ROWS];

// ========================= helpers =========================================
__device__ __forceinline__ uint32_t smem_u32(const void* p) {
    uint32_t a;
    asm("{ .reg .u64 t; cvta.to.shared.u64 t, %1; cvt.u32.u64 %0, t; }"
        : "=r"(a) : "l"(p));
    return a;
}
__device__ __forceinline__ uint32_t tb_off(int r, int u) {
    return (uint32_t)(r * 128 + ((u ^ (r & 7)) << 4));
}
__device__ __forceinline__ uint32_t ab_off(int r, int u) {
    return (uint32_t)(r * 512 + ((u ^ (r & 7)) << 4));
}
__device__ __forceinline__ void mbar_init(uint32_t m, uint32_t cnt) {
    asm volatile("mbarrier.init.shared.b64 [%0], %1;" :: "r"(m), "r"(cnt) : "memory");
}
__device__ __forceinline__ void mbar_expect(uint32_t m, uint32_t bytes) {
    asm volatile("mbarrier.arrive.expect_tx.shared.b64 _, [%0], %1;"
                 :: "r"(m), "r"(bytes) : "memory");
}
__device__ __forceinline__ void mbar_arrive(uint32_t m) {
    asm volatile("mbarrier.arrive.shared.b64 _, [%0];" :: "r"(m) : "memory");
}
__device__ __forceinline__ void mbar_wait(uint32_t m, uint32_t parity) {
    asm volatile(
        "{\n\t.reg .pred P;\n\t"
        "W_%=:\n\t"
        "mbarrier.try_wait.parity.shared.b64 P, [%0], %1;\n\t"
        "@!P bra W_%=;\n\t}"
        :: "r"(m), "r"(parity) : "memory");
}
__device__ __forceinline__ void bulk_g2s(uint32_t dst, const void* src,
                                         uint32_t bytes, uint32_t mbar) {
    asm volatile(
        "cp.async.bulk.shared::cluster.global.mbarrier::complete_tx::bytes "
        "[%0], [%1], %2, [%3];"
        :: "r"(dst), "l"(src), "r"(bytes), "r"(mbar) : "memory");
}
__device__ __forceinline__ void ldsm4(uint32_t& r0, uint32_t& r1,
                                      uint32_t& r2, uint32_t& r3, uint32_t addr) {
    asm volatile("ldmatrix.sync.aligned.m8n8.x4.shared.b16 {%0,%1,%2,%3}, [%4];"
                 : "=r"(r0), "=r"(r1), "=r"(r2), "=r"(r3) : "r"(addr));
}
__device__ __forceinline__ void ldsm4t(uint32_t& r0, uint32_t& r1,
                                       uint32_t& r2, uint32_t& r3, uint32_t addr) {
    asm volatile("ldmatrix.sync.aligned.m8n8.x4.trans.shared.b16 {%0,%1,%2,%3}, [%4];"
                 : "=r"(r0), "=r"(r1), "=r"(r2), "=r"(r3) : "r"(addr));
}
__device__ __forceinline__ void mma_bf16(float* c, const uint32_t* a,
                                         const uint32_t* b) {
    asm volatile(
        "mma.sync.aligned.m16n8k16.row.col.f32.bf16.bf16.f32 "
        "{%0,%1,%2,%3}, {%4,%5,%6,%7}, {%8,%9}, {%0,%1,%2,%3};"
        : "+f"(c[0]), "+f"(c[1]), "+f"(c[2]), "+f"(c[3])
        : "r"(a[0]), "r"(a[1]), "r"(a[2]), "r"(a[3]), "r"(b[0]), "r"(b[1]));
}
__device__ __forceinline__ void mma_s8(int* c, const uint32_t* a,
                                       const uint32_t* b) {
    asm volatile(
        "mma.sync.aligned.m16n8k32.row.col.s32.s8.s8.s32 "
        "{%0,%1,%2,%3}, {%4,%5,%6,%7}, {%8,%9}, {%0,%1,%2,%3};"
        : "+r"(c[0]), "+r"(c[1]), "+r"(c[2]), "+r"(c[3])
        : "r"(a[0]), "r"(a[1]), "r"(a[2]), "r"(a[3]), "r"(b[0]), "r"(b[1]));
}
__device__ __forceinline__ float ex2f(float x) {
    float y;
    asm("ex2.approx.f32 %0, %1;" : "=f"(y) : "f"(x));
    return y;
}
__device__ __forceinline__ void split2(float x, bf16& h, bf16& l) {
    h = __float2bfloat16(x);
    l = __float2bfloat16(x - __bfloat162float(h));
}
__device__ __forceinline__ uint32_t packbf(float a, float b) {
    bf162 t = __floats2bfloat162_rn(a, b);
    return *(uint32_t*)&t;
}
__device__ __forceinline__ uint32_t packs8(int a, int b, int c, int d) {
    return (uint32_t)(a & 255) | ((uint32_t)(b & 255) << 8) |
           ((uint32_t)(c & 255) << 16) | ((uint32_t)(d & 255) << 24);
}
__device__ __forceinline__ void quant2(float x, float inv, int& qh, int& ql) {
    const float xh = x * inv;                 // |xh| <= 127
    qh = __float2int_rn(xh);
    ql = __float2int_rn((xh - (float)qh) * 254.f);
}
__device__ __forceinline__ float blockmax256(float v, float* red, int t) {
#pragma unroll
    for (int o = 16; o > 0; o >>= 1) v = fmaxf(v, __shfl_xor_sync(0xffffffffu, v, o));
    if ((t & 31) == 0) red[t >> 5] = v;
    __syncthreads();
    float m = red[0];
#pragma unroll
    for (int i = 1; i < 8; i++) m = fmaxf(m, red[i]);
    return m;
}

// ======================= zero helper =======================================
__global__ __launch_bounds__(256) void zero_kernel(float* a, float* b) {
    const int i = blockIdx.x * 256 + threadIdx.x;
    if (i < ROWS) { a[i] = 0.f; b[i] = 0.f; }
}

// ======================= LayerNorm -> int8 TB8 + scale =====================
__global__ __launch_bounds__(256) void ln8_kernel(const float* __restrict__ x,
                                                  const float* __restrict__ g,
                                                  const float* __restrict__ bp,
                                                  int8_t* __restrict__ yt,
                                                  float* __restrict__ sArr) {
    __shared__ float red[8];
    __shared__ float s_mean, s_rstd;
    const int row = blockIdx.x, t = threadIdx.x;
    const float* xr = x + (size_t)row * N_EMBD + t * 8;
    float v[8];
    *(float4*)&v[0] = *(const float4*)&xr[0];
    *(float4*)&v[4] = *(const float4*)&xr[4];
    float s = v[0] + v[1] + v[2] + v[3] + v[4] + v[5] + v[6] + v[7];
#pragma unroll
    for (int o = 16; o > 0; o >>= 1) s += __shfl_xor_sync(0xffffffffu, s, o);
    if ((t & 31) == 0) red[t >> 5] = s;
    __syncthreads();
    if (t == 0) {
        float tt = 0.f;
#pragma unroll
        for (int i = 0; i < 8; i++) tt += red[i];
        s_mean = tt * (1.f / N_EMBD);
    }
    __syncthreads();
    const float mu = s_mean;
    float vs = 0.f;
#pragma unroll
    for (int k = 0; k < 8; k++) { float d = v[k] - mu; vs += d * d; }
#pragma unroll
    for (int o = 16; o > 0; o >>= 1) vs += __shfl_xor_sync(0xffffffffu, vs, o);
    if ((t & 31) == 0) red[t >> 5] = vs;
    __syncthreads();
    if (t == 0) {
        float tt = 0.f;
#pragma unroll
        for (int i = 0; i < 8; i++) tt += red[i];
        s_rstd = rsqrtf(tt * (1.f / N_EMBD) + 1e-5f);
    }
    __syncthreads();
    const float rstd = s_rstd;
    float gg[8], bb[8];
    *(float4*)&gg[0] = *(const float4*)&g[t * 8];
    *(float4*)&gg[4] = *(const float4*)&g[t * 8 + 4];
    *(float4*)&bb[0] = *(const float4*)&bp[t * 8];
    *(float4*)&bb[4] = *(const float4*)&bp[t * 8 + 4];
    float val[8];
    float mx = 0.f;
#pragma unroll
    for (int k = 0; k < 8; k++) {
        val[k] = (v[k] - mu) * rstd * gg[k] + bb[k];
        mx = fmaxf(mx, fabsf(val[k]));
    }
    __syncthreads();   // red[] reuse
    const float gmax = fmaxf(blockmax256(mx, red, t), 1e-20f);
    const float inv = 127.f / gmax;
    if (t == 0) sArr[row] = gmax * (1.f / 127.f);
    int qh[8], ql[8];
#pragma unroll
    for (int k = 0; k < 8; k++) quant2(val[k], inv, qh[k], ql[k]);
    uint2 H, L;
    H.x = packs8(qh[0], qh[1], qh[2], qh[3]);
    H.y = packs8(qh[4], qh[5], qh[6], qh[7]);
    L.x = packs8(ql[0], ql[1], ql[2], ql[3]);
    L.y = packs8(ql[4], ql[5], ql[6], ql[7]);
    const int mblk = row >> 7, rl = row & 127;
    const int c = t >> 3, u = (t >> 1) & 3, intra = (t & 1) * 8;
    char* base = (char*)yt + (((size_t)(mblk * 32 + c)) << 14);
    *(uint2*)(base + tb_off(rl, u) + intra)     = H;
    *(uint2*)(base + tb_off(rl, u + 4) + intra) = L;
}

// ========== weight-norm column scales ======================================
__global__ __launch_bounds__(256) void colnorm_kernel(const float* __restrict__ v,
                                                      const float* __restrict__ g,
                                                      float* __restrict__ scale,
                                                      int rows, int cols) {
    __shared__ float red[8][32];
    const int lane = threadIdx.x & 31;
    const int r0   = threadIdx.x >> 5;
    const int j    = blockIdx.x * 32 + lane;
    float acc = 0.f;
    for (int r = r0; r < rows; r += 8) {
        float t = v[(size_t)r * cols + j];
        acc += t * t;
    }
    red[r0][lane] = acc;
    __syncthreads();
    if (r0 == 0) {
        float s = red[0][lane];
#pragma unroll
        for (int q = 1; q < 8; q++) s += red[q][lane];
        scale[j] = g[j] / sqrtf(s);
    }
}

// ========== weight conversion: fp32 (* s[k]) -> int8 TB8 + scale ===========
__global__ __launch_bounds__(256) void convw8_kernel(const float* __restrict__ w,
                                                     const float* __restrict__ s,
                                                     int8_t* __restrict__ out,
                                                     float* __restrict__ sArr,
                                                     int K) {
    __shared__ float red[8];
    const int n = blockIdx.x, t = threadIdx.x;
    const int groups = K >> 11;          // 1 or 4
    float val[32];
    float mx = 0.f;
    for (int gq = 0; gq < groups; gq++) {
        const int k = gq * 2048 + t * 8;
        float vv[8];
        *(float4*)&vv[0] = *(const float4*)&w[(size_t)n * K + k];
        *(float4*)&vv[4] = *(const float4*)&w[(size_t)n * K + k + 4];
        if (s) {
#pragma unroll
            for (int q = 0; q < 8; q++) vv[q] *= s[k + q];
        }
#pragma unroll
        for (int q = 0; q < 8; q++) {
            val[gq * 8 + q] = vv[q];
            mx = fmaxf(mx, fabsf(vv[q]));
        }
    }
    const float gmax = fmaxf(blockmax256(mx, red, t), 1e-20f);
    const float inv = 127.f / gmax;
    if (t == 0) sArr[n] = gmax * (1.f / 127.f);
    const int nblk = n >> 7, rl = n & 127, nc = K >> 6;
    for (int gq = 0; gq < groups; gq++) {
        const int k = gq * 2048 + t * 8;
        int qh[8], ql[8];
#pragma unroll
        for (int q = 0; q < 8; q++) quant2(val[gq * 8 + q], inv, qh[q], ql[q]);
        uint2 H, L;
        H.x = packs8(qh[0], qh[1], qh[2], qh[3]);
        H.y = packs8(qh[4], qh[5], qh[6], qh[7]);
        L.x = packs8(ql[0], ql[1], ql[2], ql[3]);
        L.y = packs8(ql[4], ql[5], ql[6], ql[7]);
        const int c = k >> 6, u = (k >> 4) & 3, intra = k & 15;
        char* base = (char*)out + (((size_t)(nblk * nc + c)) << 14);
        *(uint2*)(base + tb_off(rl, u) + intra)     = H;
        *(uint2*)(base + tb_off(rl, u + 4) + intra) = L;
    }
}

// ========== convert: bf16 TB -> int8 TB8 using atomic rowmax ===============
__global__ __launch_bounds__(256) void convert8_kernel(const bf16* __restrict__ src,
                                                       int8_t* __restrict__ dst,
                                                       const float* __restrict__ rm,
                                                       float* __restrict__ sArr,
                                                       int K) {
    const int row = blockIdx.x, t = threadIdx.x;
    const int groups = K >> 11;
    const float gmax = fmaxf(rm[row], 1e-20f);
    const float inv = 127.f / gmax;
    if (t == 0) sArr[row] = gmax * (1.f / 127.f);
    const int mblk = row >> 7, rl = row & 127;
    const int nc16 = K >> 5, nc8 = K >> 6;
    for (int gq = 0; gq < groups; gq++) {
        const int k = gq * 2048 + t * 8;
        const char* sblk = (const char*)src + (((size_t)(mblk * nc16 + (k >> 5))) << 14);
        const int u16 = (k >> 3) & 3;
        uint4 Hh = *(const uint4*)(sblk + tb_off(rl, u16));
        uint4 Ll = *(const uint4*)(sblk + tb_off(rl, u16 + 4));
        const uint32_t* hw = (const uint32_t*)&Hh;
        const uint32_t* lw = (const uint32_t*)&Ll;
        int qh[8], ql[8];
#pragma unroll
        for (int q = 0; q < 4; q++) {
            bf162 hb = *(const bf162*)&hw[q];
            bf162 lb = *(const bf162*)&lw[q];
            const float v0 = __bfloat162float(hb.x) + __bfloat162float(lb.x);
            const float v1 = __bfloat162float(hb.y) + __bfloat162float(lb.y);
            quant2(v0, inv, qh[2 * q], ql[2 * q]);
            quant2(v1, inv, qh[2 * q + 1], ql[2 * q + 1]);
        }
        uint2 H, L;
        H.x = packs8(qh[0], qh[1], qh[2], qh[3]);
        H.y = packs8(qh[4], qh[5], qh[6], qh[7]);
        L.x = packs8(ql[0], ql[1], ql[2], ql[3]);
        L.y = packs8(ql[4], ql[5], ql[6], ql[7]);
        char* base = (char*)dst + (((size_t)(mblk * nc8 + (k >> 6))) << 14);
        const int u = (k >> 4) & 3, intra = k & 15;
        *(uint2*)(base + tb_off(rl, u) + intra)     = H;
        *(uint2*)(base + tb_off(rl, u + 4) + intra) = L;
    }
}

// ================= split-int8 IMMA GEMM, 128x64 tile, 2 CTAs/SM ============
// 256 thr = 8 warps (4m x 2n), warp tile 32x32. 4-stage bulk pipeline.
// Per chunk per warp: 16 ldsm / 48 IMMA (was 20/48 with 2m x 4n).
// Stage: A 16KB (TB8 block, k64) + B 8KB (half TB8 block) = 24KB.
// D = sA[m]*sB[n]*(accHH + accX/254) + epilogue.
#define GSOFF 1024
#define GSTG  24576
#define GSTAGES 4
#define GEMM_SMEM (GSOFF + GSTAGES * GSTG)

template<bool DOGELU, bool RES, bool WF32, bool WTB, bool WQKV>
__global__ __launch_bounds__(256, 2) void tgemm8(const int8_t* __restrict__ A,
                                                 const int8_t* __restrict__ B,
                                                 const float* __restrict__ sA,
                                                 const float* __restrict__ sB,
                                                 const float* __restrict__ bias,
                                                 const float* __restrict__ res,
                                                 float* __restrict__ C,
                                                 bf16* __restrict__ T,
                                                 float* __restrict__ rmax,
                                                 int M, int N, int K) {
    extern __shared__ char sm[];
    const uint32_t sb = smem_u32(sm);
    const int tid  = threadIdx.x;
    const int lane = tid & 31;
    const int wid  = tid >> 5;
    const int warp_m = wid >> 1;    // 0..3 -> 32-row slice
    const int warp_n = wid & 1;     // 0..1 -> 32-col half
    const int m0 = blockIdx.y * 128;
    const int n0 = blockIdx.x * 64;
    const int nc = K >> 6;
    const int lm = lane & 15, lq = lane >> 4, l8 = (lane >> 3) & 1, l7 = lane & 7;
    const char* Ab = (const char*)A;
    const char* Bb = (const char*)B;
    const size_t bblk = (size_t)(blockIdx.x >> 1) * nc;
    const uint32_t bhalf = (uint32_t)(blockIdx.x & 1) * 8192;

    // full[s] = sb + s*8 (s<4); empty[s] = sb + 32 + s*8
    if (tid == 0) {
#pragma unroll
        for (int s = 0; s < GSTAGES; s++) {
            mbar_init(sb + s * 8, 1);
            mbar_init(sb + 32 + s * 8, 8);
        }
    }
    __syncthreads();
    if (tid == 0) {
#pragma unroll
        for (int s = 0; s < GSTAGES; s++) {
            const uint32_t mb = sb + s * 8;
            const uint32_t st = sb + GSOFF + s * GSTG;
            mbar_expect(mb, 24576);
            bulk_g2s(st,         Ab + (((size_t)blockIdx.y * nc + s) << 14), 16384, mb);
            bulk_g2s(st + 16384, Bb + ((bblk + s) << 14) + bhalf, 8192, mb);
        }
    }

    int aH[2][4][4], aX[2][4][4];
#pragma unroll
    for (int i = 0; i < 2; i++)
#pragma unroll
        for (int j = 0; j < 4; j++)
#pragma unroll
            for (int t = 0; t < 4; t++) { aH[i][j][t] = 0; aX[i][j][t] = 0; }

    for (int c = 0; c < nc; c++) {
        const int slot = c & 3;
        const int rnd  = c >> 2;
        mbar_wait(sb + slot * 8, rnd & 1);
        const uint32_t st = sb + GSOFF + slot * GSTG;
#pragma unroll
        for (int s = 0; s < 2; s++) {
            // B fragments: 4 n8 groups (32 cols), hi+lo
            uint32_t bh[4][2], bl[4][2];
#pragma unroll
            for (int j2 = 0; j2 < 2; j2++) {
                const int r = warp_n * 32 + j2 * 16 + lq * 8 + l7;
                uint32_t t0, t1, t2, t3;
                ldsm4(t0, t1, t2, t3, st + 16384 + tb_off(r, s * 2 + l8));
                bh[2 * j2][0] = t0; bh[2 * j2][1] = t1;
                bh[2 * j2 + 1][0] = t2; bh[2 * j2 + 1][1] = t3;
                ldsm4(t0, t1, t2, t3, st + 16384 + tb_off(r, s * 2 + l8 + 4));
                bl[2 * j2][0] = t0; bl[2 * j2][1] = t1;
                bl[2 * j2 + 1][0] = t2; bl[2 * j2 + 1][1] = t3;
            }
            // A fragments: 2 m16 blocks (32 rows), hi+lo; reuse across 4 j
#pragma unroll
            for (int i = 0; i < 2; i++) {
                const int rl = warp_m * 32 + lm + i * 16;
                uint32_t ah[4], al[4];
                ldsm4(ah[0], ah[1], ah[2], ah[3], st + tb_off(rl, s * 2 + lq));
                ldsm4(al[0], al[1], al[2], al[3], st + tb_off(rl, s * 2 + lq + 4));
#pragma unroll
                for (int j = 0; j < 4; j++) {
                    mma_s8(aH[i][j], ah, bh[j]);
                    mma_s8(aX[i][j], ah, bl[j]);
                    mma_s8(aX[i][j], al, bh[j]);
                }
            }
        }
        if (lane == 0) mbar_arrive(sb + 32 + slot * 8);
        if (tid == 0 && c + GSTAGES < nc) {
            mbar_wait(sb + 32 + slot * 8, rnd & 1);
            const uint32_t mb = sb + slot * 8;
            mbar_expect(mb, 24576);
            bulk_g2s(st,         Ab + (((size_t)blockIdx.y * nc + c + GSTAGES) << 14), 16384, mb);
            bulk_g2s(st + 16384, Bb + ((bblk + c + GSTAGES) << 14) + bhalf, 8192, mb);
        }
    }

    // ---------------- epilogue ----------------
    const float i254 = 1.f / 254.f;
    const int r_base = m0 + warp_m * 32 + (lane >> 2);
    const int c_base = n0 + warp_n * 32 + 2 * (lane & 3);
    float sAv[4];
#pragma unroll
    for (int i = 0; i < 2; i++) {
        sAv[2 * i]     = sA[r_base + i * 16];
        sAv[2 * i + 1] = sA[r_base + i * 16 + 8];
    }
    float rmx[4];
#pragma unroll
    for (int i = 0; i < 4; i++) rmx[i] = 0.f;
#pragma unroll
    for (int j = 0; j < 4; j++) {
        const int col = c_base + j * 8;
        const float2 bi = *(const float2*)&bias[col];
        const float2 sb2 = *(const float2*)&sB[col];
#pragma unroll
        for (int i = 0; i < 2; i++) {
#pragma unroll
            for (int half = 0; half < 2; half++) {
                const int row = r_base + i * 16 + half * 8;
                const float sa = sAv[2 * i + half];
                float vx = ((float)aH[i][j][half * 2 + 0] +
                            (float)aX[i][j][half * 2 + 0] * i254) * (sa * sb2.x) + bi.x;
                float vy = ((float)aH[i][j][half * 2 + 1] +
                            (float)aX[i][j][half * 2 + 1] * i254) * (sa * sb2.y) + bi.y;
                if (DOGELU) {
                    vx = 0.5f * vx * (1.f + erff(vx * 0.70710678118654752f));
                    vy = 0.5f * vy * (1.f + erff(vy * 0.70710678118654752f));
                }
                if (RES) {
                    const float2 rv = *(const float2*)&res[(size_t)row * N + col];
                    vx += rv.x; vy += rv.y;
                }
                if (WF32) {
                    float2 o; o.x = vx; o.y = vy;
                    *(float2*)&C[(size_t)row * N + col] = o;
                }
                if (WTB) {
                    rmx[2 * i + half] = fmaxf(rmx[2 * i + half],
                                              fmaxf(fabsf(vx), fabsf(vy)));
                    bf16 h0, h1, l0, l1;
                    split2(vx, h0, l0); split2(vy, h1, l1);
                    bf162 ph; ph.x = h0; ph.y = h1;
                    bf162 pl; pl.x = l0; pl.y = l1;
                    const int mblk = row >> 7, rl = row & 127;
                    const int cc = col >> 5, u = (col & 31) >> 3, bo = (col & 7) * 2;
                    char* base = (char*)T + (((size_t)(mblk * (N >> 5) + cc)) << 14);
                    *(bf162*)(base + tb_off(rl, u) + bo)     = ph;
                    *(bf162*)(base + tb_off(rl, u + 4) + bo) = pl;
                }
                if (WQKV) {
                    bf16 h0, h1, l0, l1;
                    split2(vx, h0, l0); split2(vy, h1, l1);
                    bf162 ph; ph.x = h0; ph.y = h1;
                    bf162 pl; pl.x = l0; pl.y = l1;
                    const int type = col >> 11, hh = (col >> 7) & 15;
                    const int bb2 = row >> 11, seq = row & 2047;
                    const int sblk = seq >> 6, rl = seq & 63;
                    const int d = col & 127, u = d >> 3, bo = (d & 7) * 2;
                    char* base = (char*)T +
                        (((size_t)((((type * 2 + bb2) * 16 + hh) * 32) + sblk)) << 15);
                    *(bf162*)(base + ab_off(rl, u) + bo)      = ph;
                    *(bf162*)(base + ab_off(rl, u + 16) + bo) = pl;
                }
            }
        }
    }
    if (WTB) {
#pragma unroll
        for (int i = 0; i < 4; i++) {
            float m = rmx[i];
            m = fmaxf(m, __shfl_xor_sync(0xffffffffu, m, 1));
            m = fmaxf(m, __shfl_xor_sync(0xffffffffu, m, 2));
            if ((lane & 3) == 0) {
                const int row = r_base + (i >> 1) * 16 + (i & 1) * 8;
                atomicMax((int*)&rmax[row], __float_as_int(m));
            }
        }
    }
}

// ============== HMMA split-bf16 flash attention (unchanged) ================
#define ASQ   1024
#define ASKV  (1024 + 65536)
#define ASTG  65536
#define ATT_SMEM (1024 + 65536 + 2 * 65536)
#define SOFTSC 0.1275174048f /* (1/sqrt(128)) * log2(e) */

__global__ __launch_bounds__(256) void attn_mma(const bf16* __restrict__ qt,
                                                bf16* __restrict__ aout,
                                                float* __restrict__ rmax) {
    extern __shared__ char sm[];
    const uint32_t sb = smem_u32(sm);
    const int tid  = threadIdx.x;
    const int lane = tid & 31;
    const int wid  = tid >> 5;
    const int qb   = blockIdx.x * 128;
    const int h    = blockIdx.y;
    const int b    = blockIdx.z;
    const int q0   = wid * 16;
    const int lm = lane & 15, lq = lane >> 4, l8 = (lane >> 3) & 1, l7 = lane & 7;
    const char* qbase = (const char*)qt;

    auto blk = [&](int type, int sblk) -> const char* {
        return qbase + (((size_t)(((type * 2 + b) * 16 + h) * 32 + sblk)) << 15);
    };

    if (tid == 0) {
        mbar_init(sb + 0, 1);
        mbar_init(sb + 8, 1);
        mbar_init(sb + 16, 1);
        mbar_init(sb + 24, 8);
        mbar_init(sb + 32, 8);
    }
    __syncthreads();
    if (tid == 0) {
        mbar_expect(sb + 0, 65536);
        bulk_g2s(sb + ASQ,          blk(0, (qb >> 6) + 0), 32768, sb + 0);
        bulk_g2s(sb + ASQ + 32768,  blk(0, (qb >> 6) + 1), 32768, sb + 0);
        mbar_expect(sb + 8, 65536);
        bulk_g2s(sb + ASKV,          blk(1, 0), 32768, sb + 8);
        bulk_g2s(sb + ASKV + 32768,  blk(2, 0), 32768, sb + 8);
        mbar_expect(sb + 16, 65536);
        bulk_g2s(sb + ASKV + ASTG,          blk(1, 1), 32768, sb + 16);
        bulk_g2s(sb + ASKV + ASTG + 32768,  blk(2, 1), 32768, sb + 16);
    }

    float m0 = -1e30f, m1 = -1e30f, l0 = 0.f, l1 = 0.f;
    float O[16][4];
#pragma unroll
    for (int f = 0; f < 16; f++)
#pragma unroll
        for (int c = 0; c < 4; c++) O[f][c] = 0.f;

    mbar_wait(sb + 0, 0);

    const int qr = q0 + lm;
    const uint32_t qblk = sb + ASQ + ((uint32_t)(qr >> 6) << 15);
    const int qrl = qr & 63;

    for (int it = 0; it < 32; it++) {
        const int slot = it & 1;
        const int rnd  = it >> 1;
        mbar_wait(sb + 8 + slot * 8, rnd & 1);
        const uint32_t kvb = sb + ASKV + slot * ASTG;

        float s[8][4];
#pragma unroll
        for (int j = 0; j < 8; j++)
#pragma unroll
            for (int c = 0; c < 4; c++) s[j][c] = 0.f;

#pragma unroll
        for (int kd = 0; kd < 8; kd++) {
            uint32_t aH[4], aL[4];
            ldsm4(aH[0], aH[1], aH[2], aH[3], qblk + ab_off(qrl, kd * 2 + lq));
            ldsm4(aL[0], aL[1], aL[2], aL[3], qblk + ab_off(qrl, kd * 2 + lq + 16));
#pragma unroll
            for (int kg = 0; kg < 4; kg++) {
                const int kr = kg * 16 + lq * 8 + l7;
                uint32_t t0, t1, t2, t3;
                uint32_t bh0[2], bh1[2], bl0[2], bl1[2];
                ldsm4(t0, t1, t2, t3, kvb + ab_off(kr, kd * 2 + l8));
                bh0[0] = t0; bh0[1] = t1; bh1[0] = t2; bh1[1] = t3;
                ldsm4(t0, t1, t2, t3, kvb + ab_off(kr, kd * 2 + l8 + 16));
                bl0[0] = t0; bl0[1] = t1; bl1[0] = t2; bl1[1] = t3;
                mma_bf16(s[2 * kg],     aH, bh0);
                mma_bf16(s[2 * kg],     aH, bl0);
                mma_bf16(s[2 * kg],     aL, bh0);
                mma_bf16(s[2 * kg + 1], aH, bh1);
                mma_bf16(s[2 * kg + 1], aH, bl1);
                mma_bf16(s[2 * kg + 1], aL, bh1);
            }
        }

        float mt0 = -1e30f, mt1 = -1e30f;
#pragma unroll
        for (int j = 0; j < 8; j++) {
#pragma unroll
            for (int c = 0; c < 4; c++) s[j][c] *= SOFTSC;
            mt0 = fmaxf(mt0, fmaxf(s[j][0], s[j][1]));
            mt1 = fmaxf(mt1, fmaxf(s[j][2], s[j][3]));
        }
        mt0 = fmaxf(mt0, __shfl_xor_sync(0xffffffffu, mt0, 1));
        mt0 = fmaxf(mt0, __shfl_xor_sync(0xffffffffu, mt0, 2));
        mt1 = fmaxf(mt1, __shfl_xor_sync(0xffffffffu, mt1, 1));
        mt1 = fmaxf(mt1, __shfl_xor_sync(0xffffffffu, mt1, 2));
        const float mn0 = fmaxf(m0, mt0), mn1 = fmaxf(m1, mt1);
        const float corr0 = ex2f(m0 - mn0), corr1 = ex2f(m1 - mn1);
        m0 = mn0; m1 = mn1;
        float ps0 = 0.f, ps1 = 0.f;
#pragma unroll
        for (int j = 0; j < 8; j++) {
            s[j][0] = ex2f(s[j][0] - mn0);
            s[j][1] = ex2f(s[j][1] - mn0);
            s[j][2] = ex2f(s[j][2] - mn1);
            s[j][3] = ex2f(s[j][3] - mn1);
            ps0 += s[j][0] + s[j][1];
            ps1 += s[j][2] + s[j][3];
        }
        l0 = l0 * corr0 + ps0;
        l1 = l1 * corr1 + ps1;
#pragma unroll
        for (int f = 0; f < 16; f++) {
            O[f][0] *= corr0; O[f][1] *= corr0;
            O[f][2] *= corr1; O[f][3] *= corr1;
        }

#pragma unroll
        for (int kk = 0; kk < 4; kk++) {
            const int j0 = 2 * kk, j1 = 2 * kk + 1;
            uint32_t pH[4], pL[4];
            {
                uint32_t hi;
                bf162 hv;
                float la, lb;
                hi = packbf(s[j0][0], s[j0][1]); hv = *(bf162*)&hi;
                la = s[j0][0] - __bfloat162float(hv.x);
                lb = s[j0][1] - __bfloat162float(hv.y);
                pH[0] = hi; pL[0] = packbf(la, lb);
                hi = packbf(s[j0][2], s[j0][3]); hv = *(bf162*)&hi;
                la = s[j0][2] - __bfloat162float(hv.x);
                lb = s[j0][3] - __bfloat162float(hv.y);
                pH[1] = hi; pL[1] = packbf(la, lb);
                hi = packbf(s[j1][0], s[j1][1]); hv = *(bf162*)&hi;
                la = s[j1][0] - __bfloat162float(hv.x);
                lb = s[j1][1] - __bfloat162float(hv.y);
                pH[2] = hi; pL[2] = packbf(la, lb);
                hi = packbf(s[j1][2], s[j1][3]); hv = *(bf162*)&hi;
                la = s[j1][2] - __bfloat162float(hv.x);
                lb = s[j1][3] - __bfloat162float(hv.y);
                pH[3] = hi; pL[3] = packbf(la, lb);
            }
#pragma unroll
            for (int g = 0; g < 8; g++) {
                const int vr = kk * 16 + l8 * 8 + l7;
                uint32_t t0, t1, t2, t3;
                uint32_t bh0[2], bh1[2], bl0[2], bl1[2];
                ldsm4t(t0, t1, t2, t3, kvb + 32768 + ab_off(vr, g * 2 + lq));
                bh0[0] = t0; bh0[1] = t1; bh1[0] = t2; bh1[1] = t3;
                ldsm4t(t0, t1, t2, t3, kvb + 32768 + ab_off(vr, g * 2 + lq + 16));
                bl0[0] = t0; bl0[1] = t1; bl1[0] = t2; bl1[1] = t3;
                mma_bf16(O[2 * g],     pH, bh0);
                mma_bf16(O[2 * g],     pH, bl0);
                mma_bf16(O[2 * g],     pL, bh0);
                mma_bf16(O[2 * g + 1], pH, bh1);
                mma_bf16(O[2 * g + 1], pH, bl1);
                mma_bf16(O[2 * g + 1], pL, bh1);
            }
        }
        if (lane == 0) mbar_arrive(sb + 24 + slot * 8);
        if (tid == 0 && it + 2 < 32) {
            mbar_wait(sb + 24 + slot * 8, rnd & 1);
            const uint32_t mb = sb + 8 + slot * 8;
            const uint32_t dst = sb + ASKV + slot * ASTG;
            mbar_expect(mb, 65536);
            bulk_g2s(dst,         blk(1, it + 2), 32768, mb);
            bulk_g2s(dst + 32768, blk(2, it + 2), 32768, mb);
        }
    }

    l0 += __shfl_xor_sync(0xffffffffu, l0, 1);
    l0 += __shfl_xor_sync(0xffffffffu, l0, 2);
    l1 += __shfl_xor_sync(0xffffffffu, l1, 1);
    l1 += __shfl_xor_sync(0xffffffffu, l1, 2);
    const float inv0 = 1.f / l0, inv1 = 1.f / l1;
    const int r0g = b * SEQ + qb + q0 + (lane >> 2);
    const int r1g = r0g + 8;
    const int col0 = h * HEAD_DIM + 2 * (lane & 3);
    char* ga = (char*)aout;
    float mx0 = 0.f, mx1 = 0.f;
#pragma unroll
    for (int f = 0; f < 16; f++) {
        const int col = col0 + f * 8;
        const int c = col >> 5, u = (col & 31) >> 3, bo = (col & 7) * 2;
#pragma unroll
        for (int half = 0; half < 2; half++) {
            const int row = half ? r1g : r0g;
            const float inv = half ? inv1 : inv0;
            const float vx = O[f][half * 2 + 0] * inv;
            const float vy = O[f][half * 2 + 1] * inv;
            const float am = fmaxf(fabsf(vx), fabsf(vy));
            if (half) mx1 = fmaxf(mx1, am); else mx0 = fmaxf(mx0, am);
            bf16 h0, h1, lo0, lo1;
            split2(vx, h0, lo0); split2(vy, h1, lo1);
            bf162 ph; ph.x = h0; ph.y = h1;
            bf162 pl; pl.x = lo0; pl.y = lo1;
            const int mblk = row >> 7, rl = row & 127;
            char* base = ga + (((size_t)(mblk * 64 + c)) << 14);
            *(bf162*)(base + tb_off(rl, u) + bo)     = ph;
            *(bf162*)(base + tb_off(rl, u + 4) + bo) = pl;
        }
    }
    mx0 = fmaxf(mx0, __shfl_xor_sync(0xffffffffu, mx0, 1));
    mx0 = fmaxf(mx0, __shfl_xor_sync(0xffffffffu, mx0, 2));
    mx1 = fmaxf(mx1, __shfl_xor_sync(0xffffffffu, mx1, 1));
    mx1 = fmaxf(mx1, __shfl_xor_sync(0xffffffffu, mx1, 2));
    if ((lane & 3) == 0) {
        atomicMax((int*)&rmax[r0g], __float_as_int(mx0));
        atomicMax((int*)&rmax[r1g], __float_as_int(mx1));
    }
}

// =========================== launch sequence ===============================
extern "C" void kernel_launch(void* const* d_in, const int* in_sizes, int n_in,
                              void* d_out, int out_size) {
    const float* hs      = (const float*)d_in[0];
    const float* ln1_g   = (const float*)d_in[1];
    const float* ln1_b   = (const float*)d_in[2];
    const float* w_qkv   = (const float*)d_in[3];
    const float* b_qkv   = (const float*)d_in[4];
    const float* attn_v  = (const float*)d_in[5];
    const float* attn_g  = (const float*)d_in[6];
    const float* attn_b  = (const float*)d_in[7];
    /* d_in[8] = emotion_bias: softmax-invariant, unused */
    const float* ln2_g   = (const float*)d_in[9];
    const float* ln2_b   = (const float*)d_in[10];
    const float* w_fc    = (const float*)d_in[11];
    const float* b_fc    = (const float*)d_in[12];
    const float* mlp_v   = (const float*)d_in[13];
    const float* mlp_g   = (const float*)d_in[14];
    const float* mlp_b   = (const float*)d_in[15];
    float* out = (float*)d_out;

    float *hid, *sA, *sM, *sx, *sa, *sf, *swq, *swp, *swf, *swm, *rma, *rmf;
    int8_t *x8, *a8, *f8, *wq8, *wp8, *wf8, *wm8;
    bf16 *at, *ft, *qt;
    cudaGetSymbolAddress((void**)&hid, g_hid);
    cudaGetSymbolAddress((void**)&sA,  g_sA);
    cudaGetSymbolAddress((void**)&sM,  g_sM);
    cudaGetSymbolAddress((void**)&sx,  g_sx);
    cudaGetSymbolAddress((void**)&sa,  g_sa);
    cudaGetSymbolAddress((void**)&sf,  g_sf);
    cudaGetSymbolAddress((void**)&swq, g_swq);
    cudaGetSymbolAddress((void**)&swp, g_swp);
    cudaGetSymbolAddress((void**)&swf, g_swf);
    cudaGetSymbolAddress((void**)&swm, g_swm);
    cudaGetSymbolAddress((void**)&rma, g_rma);
    cudaGetSymbolAddress((void**)&rmf, g_rmf);
    cudaGetSymbolAddress((void**)&x8,  g_x8);
    cudaGetSymbolAddress((void**)&a8,  g_a8);
    cudaGetSymbolAddress((void**)&f8,  g_f8);
    cudaGetSymbolAddress((void**)&wq8, g_wq8);
    cudaGetSymbolAddress((void**)&wp8, g_wp8);
    cudaGetSymbolAddress((void**)&wf8, g_wf8);
    cudaGetSymbolAddress((void**)&wm8, g_wm8);
    cudaGetSymbolAddress((void**)&at,  g_a);
    cudaGetSymbolAddress((void**)&ft,  g_f);
    cudaGetSymbolAddress((void**)&qt,  g_qt);

    cudaFuncSetAttribute(attn_mma,
                         cudaFuncAttributeMaxDynamicSharedMemorySize, ATT_SMEM);
    cudaFuncSetAttribute(tgemm8<false, false, false, false, true>,
                         cudaFuncAttributeMaxDynamicSharedMemorySize, GEMM_SMEM);
    cudaFuncSetAttribute(tgemm8<false, true, true, false, false>,
                         cudaFuncAttributeMaxDynamicSharedMemorySize, GEMM_SMEM);
    cudaFuncSetAttribute(tgemm8<true, false, false, true, false>,
                         cudaFuncAttributeMaxDynamicSharedMemorySize, GEMM_SMEM);

    // k0: zero rowmax accumulators
    zero_kernel<<<(ROWS + 255) / 256, 256>>>(rma, rmf);
    // k1: LN1 -> int8 TB8 + scale
    ln8_kernel<<<ROWS, 256>>>(hs, ln1_g, ln1_b, x8, sx);
    // k2: convw w_qkv -> int8 TB8
    convw8_kernel<<<QKV_W, 256>>>(w_qkv, nullptr, wq8, swq, N_EMBD);
    // k3: QKV GEMM (int8) -> bf16 AB    (ncu capture target: harness slot 5)
    tgemm8<false, false, false, false, true>
        <<<dim3(QKV_W / 64, ROWS / 128), 256, GEMM_SMEM>>>(
        x8, wq8, sx, swq, b_qkv, nullptr, nullptr, qt, nullptr,
        ROWS, QKV_W, N_EMBD);
    // k4: colnorm attn proj
    colnorm_kernel<<<N_EMBD / 32, 256>>>(attn_v, attn_g, sA, N_EMBD, N_EMBD);
    // k5: attention -> bf16 TB + rowmax
    attn_mma<<<dim3(SEQ / 128, N_HEAD, BATCH), 256, ATT_SMEM>>>(qt, at, rma);
    // k6: convw attn proj (wn-folded) -> int8
    convw8_kernel<<<N_EMBD, 256>>>(attn_v, sA, wp8, swp, N_EMBD);
    // k7: convert attention output -> int8
    convert8_kernel<<<ROWS, 256>>>(at, a8, rma, sa, N_EMBD);
    // k8: attn proj + residual(hs) -> hid fp32
    tgemm8<false, true, true, false, false>
        <<<dim3(N_EMBD / 64, ROWS / 128), 256, GEMM_SMEM>>>(
        a8, wp8, sa, swp, attn_b, hs, hid, nullptr, nullptr,
        ROWS, N_EMBD, N_EMBD);
    // k9: LN2 -> int8
    ln8_kernel<<<ROWS, 256>>>(hid, ln2_g, ln2_b, x8, sx);
    // k10: convw w_fc -> int8
    convw8_kernel<<<N_INNER, 256>>>(w_fc, nullptr, wf8, swf, N_EMBD);
    // k11: FC + GELU -> bf16 TB + rowmax
    tgemm8<true, false, false, true, false>
        <<<dim3(N_INNER / 64, ROWS / 128), 256, GEMM_SMEM>>>(
        x8, wf8, sx, swf, b_fc, nullptr, nullptr, ft, rmf,
        ROWS, N_INNER, N_EMBD);
    // k12: convert gelu output -> int8
    convert8_kernel<<<ROWS, 256>>>(ft, f8, rmf, sf, N_INNER);
    // k13: colnorm mlp proj
    colnorm_kernel<<<N_INNER / 32, 256>>>(mlp_v, mlp_g, sM, N_EMBD, N_INNER);
    // k14: convw mlp proj (wn-folded, K=8192) -> int8
    convw8_kernel<<<N_EMBD, 256>>>(mlp_v, sM, wm8, swm, N_INNER);
    // k15: MLP proj + residual(hid) -> out fp32
    tgemm8<false, true, true, false, false>
        <<<dim3(N_EMBD / 64, ROWS / 128), 256, GEMM_SMEM>>>(
        f8, wm8, sf, swm, mlp_b, hid, out, nullptr, nullptr,
        ROWS, N_EMBD, N_INNER);
}